// round 3
// baseline (speedup 1.0000x reference)
#include <cuda_runtime.h>
#include <cstdint>

#define NN 50000
#define NE 800000
#define NR 16
#define DD 128

// Scratch (device globals; no dynamic allocation allowed).
__device__ float g_hall[(size_t)NR * NN * DD];   // 409.6 MB: per-relation transformed features
__device__ float g_sgate[(size_t)NR * NN];       // 3.2 MB: sigmoid(h . gate_w[r]) table
__device__ float g_h1[(size_t)NN * DD];          // 25.6 MB: layer-0 output (pre-relu)

__device__ __forceinline__ uint32_t f2tf32(float f) {
    uint32_t u;
    asm("cvt.rna.tf32.f32 %0, %1;" : "=r"(u) : "f"(f));
    return u;
}

// ---------------------------------------------------------------------------
// Gate table: g_sgate[r][n] = sigmoid( x[n] . gate_w[r] ).  One warp per node.
// ---------------------------------------------------------------------------
__global__ void gate_kernel(const float* __restrict__ x,
                            const float* __restrict__ gw,
                            int relu) {
    int node = (blockIdx.x * blockDim.x + threadIdx.x) >> 5;
    int lane = threadIdx.x & 31;
    if (node >= NN) return;
    float4 xv = __ldg(((const float4*)x) + (size_t)node * 32 + lane);
    if (relu) {
        xv.x = fmaxf(xv.x, 0.f); xv.y = fmaxf(xv.y, 0.f);
        xv.z = fmaxf(xv.z, 0.f); xv.w = fmaxf(xv.w, 0.f);
    }
#pragma unroll
    for (int r = 0; r < NR; r++) {
        float4 gv = __ldg(((const float4*)gw) + r * 32 + lane);
        float d = xv.x * gv.x + xv.y * gv.y + xv.z * gv.z + xv.w * gv.w;
#pragma unroll
        for (int o = 16; o; o >>= 1) d += __shfl_xor_sync(0xffffffffu, d, o);
        if (lane == 0) g_sgate[(size_t)r * NN + node] = 1.f / (1.f + __expf(-d));
    }
}

// ---------------------------------------------------------------------------
// Batched GEMM (tf32 tensor cores):
//   r in [0,16): g_hall[r] = X @ W[r]
//   r == 16    : y        = X @ loop_w + bias     (initializes the output)
// Block tile 128x128, full K=128 in smem. 256 threads = 8 warps, warp tile 32x64.
// ---------------------------------------------------------------------------
#define STR 132
#define GEMM_SMEM (2 * 128 * STR * 4)

__global__ void __launch_bounds__(256, 1)
gemm_kernel(const float* __restrict__ X,
            const float* __restrict__ Wr,
            const float* __restrict__ loopw,
            const float* __restrict__ bias,
            float* __restrict__ y, int relu) {
    extern __shared__ float sm[];
    float* sX = sm;              // [128][STR]  (m x k), tf32 bits
    float* sW = sm + 128 * STR;  // [128][STR]  (k x n), tf32 bits

    const int r    = blockIdx.x;          // relation (fastest -> X tile L2 reuse)
    const int row0 = blockIdx.y * 128;
    const float* Wp = (r < NR) ? (Wr + (size_t)r * DD * DD) : loopw;
    const int tid = threadIdx.x;

    // Global -> smem (vectorized, tf32-rounded, relu on X if requested)
#pragma unroll
    for (int i = 0; i < 16; i++) {
        int idx = tid + i * 256;            // float4 index within the 128x128 tile
        int row = idx >> 5, c4 = idx & 31;
        float4 v = make_float4(0.f, 0.f, 0.f, 0.f);
        if (row0 + row < NN) v = __ldg((const float4*)X + (size_t)(row0 + row) * 32 + c4);
        if (relu) {
            v.x = fmaxf(v.x, 0.f); v.y = fmaxf(v.y, 0.f);
            v.z = fmaxf(v.z, 0.f); v.w = fmaxf(v.w, 0.f);
        }
        uint32_t* dX = (uint32_t*)(sX + row * STR + c4 * 4);
        dX[0] = f2tf32(v.x); dX[1] = f2tf32(v.y); dX[2] = f2tf32(v.z); dX[3] = f2tf32(v.w);

        float4 w = __ldg((const float4*)Wp + idx);
        uint32_t* dW = (uint32_t*)(sW + row * STR + c4 * 4);
        dW[0] = f2tf32(w.x); dW[1] = f2tf32(w.y); dW[2] = f2tf32(w.z); dW[3] = f2tf32(w.w);
    }
    __syncthreads();

    const uint32_t* uX = (const uint32_t*)sX;
    const uint32_t* uW = (const uint32_t*)sW;
    const int warp = tid >> 5, lane = tid & 31;
    const int g = lane >> 2, t = lane & 3;
    const int mbase = (warp >> 1) * 32;   // 4 warps along M
    const int nbase = (warp & 1) * 64;    // 2 warps along N

    float acc[2][8][4];
#pragma unroll
    for (int mt = 0; mt < 2; mt++)
#pragma unroll
        for (int nt = 0; nt < 8; nt++)
#pragma unroll
            for (int q = 0; q < 4; q++) acc[mt][nt][q] = 0.f;

#pragma unroll
    for (int kk = 0; kk < 16; kk++) {
        const int k0 = kk * 8;
        uint32_t a[2][4];
#pragma unroll
        for (int mt = 0; mt < 2; mt++) {
            int base = (mbase + mt * 16 + g) * STR + k0 + t;
            a[mt][0] = uX[base];
            a[mt][1] = uX[base + 8 * STR];
            a[mt][2] = uX[base + 4];
            a[mt][3] = uX[base + 8 * STR + 4];
        }
#pragma unroll
        for (int nt = 0; nt < 8; nt++) {
            int col = nbase + nt * 8 + g;
            uint32_t b0 = uW[(k0 + t) * STR + col];
            uint32_t b1 = uW[(k0 + t + 4) * STR + col];
#pragma unroll
            for (int mt = 0; mt < 2; mt++) {
                asm volatile(
                    "mma.sync.aligned.m16n8k8.row.col.f32.tf32.tf32.f32 "
                    "{%0,%1,%2,%3}, {%4,%5,%6,%7}, {%8,%9}, {%0,%1,%2,%3};\n"
                    : "+f"(acc[mt][nt][0]), "+f"(acc[mt][nt][1]),
                      "+f"(acc[mt][nt][2]), "+f"(acc[mt][nt][3])
                    : "r"(a[mt][0]), "r"(a[mt][1]), "r"(a[mt][2]), "r"(a[mt][3]),
                      "r"(b0), "r"(b1));
            }
        }
    }

    // Epilogue
    float* outp = (r < NR) ? (g_hall + (size_t)r * NN * DD) : y;
#pragma unroll
    for (int mt = 0; mt < 2; mt++) {
        int rA = row0 + mbase + mt * 16 + g;
#pragma unroll
        for (int nt = 0; nt < 8; nt++) {
            int col = nbase + nt * 8 + 2 * t;
            float ba = 0.f, bb = 0.f;
            if (r == NR) { ba = __ldg(bias + col); bb = __ldg(bias + col + 1); }
            if (rA < NN)
                *(float2*)(outp + (size_t)rA * DD + col) =
                    make_float2(acc[mt][nt][0] + ba, acc[mt][nt][1] + bb);
            if (rA + 8 < NN)
                *(float2*)(outp + (size_t)(rA + 8) * DD + col) =
                    make_float2(acc[mt][nt][2] + ba, acc[mt][nt][3] + bb);
        }
    }
}

// ---------------------------------------------------------------------------
// Edge scatter: y[dst] += norm * sigmoid_gate(rel,src) * g_hall[rel][src].
// One warp per edge; 32 lanes x float4 = the full 128-float row.
// Vector reduction (red.add.v4.f32) into L2-resident output.
// ---------------------------------------------------------------------------
__global__ void edge_kernel(const int* __restrict__ src,
                            const int* __restrict__ dst,
                            const int* __restrict__ rel,
                            const float* __restrict__ norm,
                            float* __restrict__ y) {
    int e = (int)((blockIdx.x * (size_t)blockDim.x + threadIdx.x) >> 5);
    int lane = threadIdx.x & 31;
    if (e >= NE) return;
    int s = __ldg(src + e);
    int d = __ldg(dst + e);
    int r = __ldg(rel + e);
    float w = __ldg(norm + e) * __ldg(&g_sgate[(size_t)r * NN + s]);
    float4 m = __ldg(((const float4*)(g_hall + ((size_t)r * NN + s) * DD)) + lane);
    float* yp = y + (size_t)d * DD + lane * 4;
    asm volatile("red.global.add.v4.f32 [%0], {%1,%2,%3,%4};"
                 :: "l"(yp), "f"(m.x * w), "f"(m.y * w), "f"(m.z * w), "f"(m.w * w)
                 : "memory");
}

// ---------------------------------------------------------------------------
extern "C" void kernel_launch(void* const* d_in, const int* in_sizes, int n_in,
                              void* d_out, int out_size) {
    const float* h    = (const float*)d_in[0];
    const float* norm = (const float*)d_in[1];
    const float* w0   = (const float*)d_in[2];
    const float* b0   = (const float*)d_in[3];
    const float* lw0  = (const float*)d_in[4];
    const float* gw0  = (const float*)d_in[5];
    const float* w1   = (const float*)d_in[6];
    const float* b1   = (const float*)d_in[7];
    const float* lw1  = (const float*)d_in[8];
    const float* gw1  = (const float*)d_in[9];
    const int*   src  = (const int*)d_in[10];
    const int*   dst  = (const int*)d_in[11];
    const int*   rel  = (const int*)d_in[12];
    float* out = (float*)d_out;

    cudaFuncSetAttribute(gemm_kernel,
                         cudaFuncAttributeMaxDynamicSharedMemorySize, GEMM_SMEM);

    float* h1 = nullptr;
    cudaGetSymbolAddress((void**)&h1, g_h1);

    dim3 ggrid(NR + 1, (NN + 127) / 128);   // relation fastest -> X tile L2 reuse
    const int gate_grid = (NN * 32 + 255) / 256;
    const int edge_grid = (int)(((size_t)NE * 32 + 255) / 256);

    // ---- Layer 0 (input = h, output = g_h1; relu applied by layer-1 readers)
    gate_kernel<<<gate_grid, 256>>>(h, gw0, 0);
    gemm_kernel<<<ggrid, 256, GEMM_SMEM>>>(h, w0, lw0, b0, h1, 0);
    edge_kernel<<<edge_grid, 256>>>(src, dst, rel, norm, h1);

    // ---- Layer 1 (input = relu(g_h1), output = d_out; no activation)
    gate_kernel<<<gate_grid, 256>>>(h1, gw1, 1);
    gemm_kernel<<<ggrid, 256, GEMM_SMEM>>>(h1, w1, lw1, b1, out, 1);
    edge_kernel<<<edge_grid, 256>>>(src, dst, rel, norm, out);
}

// round 4
// speedup vs baseline: 1.2967x; 1.2967x over previous
#include <cuda_runtime.h>
#include <cstdint>

#define NN 50000
#define NE 800000
#define NR 16
#define DD 128

// Scratch (device globals; no dynamic allocation allowed).
__device__ float g_hall[(size_t)NR * NN * DD];   // 409.6 MB: per-relation transformed features
__device__ float g_sgate[(size_t)NR * NN];       // 3.2 MB: sigmoid gate table
__device__ float g_h1[(size_t)NN * DD];          // 25.6 MB: layer-0 output (pre-relu)
__device__ float g_xt[(size_t)NN * DD];          // 25.6 MB: relu'd + tf32-rounded X
__device__ float g_wt[(size_t)(NR + 1) * DD * DD]; // 1.1 MB: tf32-rounded W[0..15], loop_w

__device__ __forceinline__ uint32_t f2tf32(float f) {
    uint32_t u;
    asm("cvt.rna.tf32.f32 %0, %1;" : "=r"(u) : "f"(f));
    return u;
}
__device__ __forceinline__ uint32_t sptr(const void* p) {
    return (uint32_t)__cvta_generic_to_shared(p);
}

// ---------------------------------------------------------------------------
// X pre-pass: xt = tf32_rna( relu?(x) ).  Enables raw cp.async in the GEMM
// while keeping round-to-nearest tf32 numerics.
// ---------------------------------------------------------------------------
__global__ void xcvt_kernel(const float* __restrict__ x, float* __restrict__ xt,
                            int relu) {
    size_t i = (size_t)blockIdx.x * blockDim.x + threadIdx.x;  // float4 index
    float4 v = __ldg((const float4*)x + i);
    if (relu) {
        v.x = fmaxf(v.x, 0.f); v.y = fmaxf(v.y, 0.f);
        v.z = fmaxf(v.z, 0.f); v.w = fmaxf(v.w, 0.f);
    }
    uint4 o;
    o.x = f2tf32(v.x); o.y = f2tf32(v.y); o.z = f2tf32(v.z); o.w = f2tf32(v.w);
    ((uint4*)xt)[i] = o;
}

// W pre-pass: g_wt[0..15] = tf32(W[r]), g_wt[16] = tf32(loop_w).
__global__ void wcvt_kernel(const float* __restrict__ Wr,
                            const float* __restrict__ loopw) {
    size_t i = (size_t)blockIdx.x * blockDim.x + threadIdx.x;  // float4 index
    const size_t wlim = (size_t)NR * DD * DD / 4;
    float4 v = (i < wlim) ? __ldg((const float4*)Wr + i)
                          : __ldg((const float4*)loopw + (i - wlim));
    uint4 o;
    o.x = f2tf32(v.x); o.y = f2tf32(v.y); o.z = f2tf32(v.z); o.w = f2tf32(v.w);
    ((uint4*)g_wt)[i] = o;
}

// ---------------------------------------------------------------------------
// Gate table: g_sgate[r][n] = sigmoid( x[n] . gate_w[r] ).
// 128 threads = 8 nodes x 16 relations; x tile + gate weights in smem.
// ---------------------------------------------------------------------------
__global__ void gate_kernel(const float* __restrict__ x,
                            const float* __restrict__ gw) {
    __shared__ float sx[8][132];
    __shared__ float sg[16][132];
    const int tid = threadIdx.x;
    const int nb = blockIdx.x * 8;
#pragma unroll
    for (int i = 0; i < 4; i++) {           // gw: 16x128 = 512 float4
        int l = tid + i * 128;
        int r = l >> 5, c = l & 31;
        *(float4*)&sg[r][c * 4] = __ldg((const float4*)gw + r * 32 + c);
    }
#pragma unroll
    for (int i = 0; i < 2; i++) {           // x: 8x128 = 256 float4
        int l = tid + i * 128;
        int n = l >> 5, c = l & 31;
        float4 v = make_float4(0.f, 0.f, 0.f, 0.f);
        if (nb + n < NN) v = __ldg((const float4*)x + (size_t)(nb + n) * 32 + c);
        *(float4*)&sx[n][c * 4] = v;
    }
    __syncthreads();
    const int node = tid >> 4, rel = tid & 15;
    float d = 0.f;
#pragma unroll
    for (int k = 0; k < 32; k++) {
        float4 a = *(float4*)&sx[node][k * 4];
        float4 g = *(float4*)&sg[rel][k * 4];
        d += a.x * g.x + a.y * g.y + a.z * g.z + a.w * g.w;
    }
    if (nb + node < NN)
        g_sgate[(size_t)rel * NN + nb + node] = 1.f / (1.f + __expf(-d));
}

// ---------------------------------------------------------------------------
// Batched tf32 GEMM, cp.async 4-stage (K=32) double-buffered pipeline.
//   r in [0,16): g_hall[r] = Xt @ Wt[r]        (streaming stores)
//   r == 16    : y        = Xt @ Wt[16] + bias (initializes output)
// 128x128 block tile, 8 warps (4Mx2N), warp tile 32x64, 2 CTAs/SM.
// ---------------------------------------------------------------------------
#define XSTR 36                   // floats; bank = (4g+t): conflict-free A loads
#define WSTR 136                  // floats; bank = (8t+g): conflict-free B loads
#define XS (128 * XSTR)           // 4608 floats per stage
#define WS (32 * WSTR)            // 4352 floats per stage
#define GEMM_SMEM ((2 * XS + 2 * WS) * 4)   // 71680 B

__global__ void __launch_bounds__(256, 2)
gemm_kernel(const float* __restrict__ Xt,
            const float* __restrict__ bias,
            float* __restrict__ y) {
    extern __shared__ float sm[];
    float* sX = sm;
    float* sW = sm + 2 * XS;

    const int r    = blockIdx.x;           // relation fastest -> X tile L2 reuse
    const int row0 = blockIdx.y * 128;
    const int tid  = threadIdx.x;
    const float* Wp = g_wt + (size_t)r * DD * DD;

    float acc[2][8][4];
#pragma unroll
    for (int mt = 0; mt < 2; mt++)
#pragma unroll
        for (int nt = 0; nt < 8; nt++)
#pragma unroll
            for (int q = 0; q < 4; q++) acc[mt][nt][q] = 0.f;

    // cp.async issue for one K-stage (8 x 16B per thread)
    auto issue = [&](int s, int buf) {
#pragma unroll
        for (int i = 0; i < 4; i++) {
            int linear = tid + i * 256;                    // [0,1024)
            int xrow = linear >> 3, xc4 = linear & 7;
            const float4* src = (const float4*)Xt + (size_t)(row0 + xrow) * 32 + s * 8 + xc4;
            uint32_t dst = sptr(sX + buf * XS + xrow * XSTR + xc4 * 4);
            int pb = (row0 + xrow < NN) ? 16 : 0;
            asm volatile("cp.async.cg.shared.global [%0], [%1], 16, %2;\n"
                         :: "r"(dst), "l"(src), "r"(pb) : "memory");
        }
#pragma unroll
        for (int i = 0; i < 4; i++) {
            int linear = tid + i * 256;
            int wk = linear >> 5, wc4 = linear & 31;
            const float4* src = (const float4*)Wp + (size_t)(32 * s + wk) * 32 + wc4;
            uint32_t dst = sptr(sW + buf * WS + wk * WSTR + wc4 * 4);
            asm volatile("cp.async.cg.shared.global [%0], [%1], 16;\n"
                         :: "r"(dst), "l"(src) : "memory");
        }
    };

    issue(0, 0);
    asm volatile("cp.async.commit_group;\n" ::: "memory");

    const int warp = tid >> 5, lane = tid & 31;
    const int g = lane >> 2, t = lane & 3;
    const int mbase = (warp >> 1) * 32;
    const int nbase = (warp & 1) * 64;

#pragma unroll
    for (int s = 0; s < 4; s++) {
        if (s < 3) {
            issue(s + 1, (s + 1) & 1);
            asm volatile("cp.async.commit_group;\n" ::: "memory");
            asm volatile("cp.async.wait_group 1;\n" ::: "memory");
        } else {
            asm volatile("cp.async.wait_group 0;\n" ::: "memory");
        }
        __syncthreads();

        const uint32_t* uX = (const uint32_t*)(sX + (s & 1) * XS);
        const uint32_t* uW = (const uint32_t*)(sW + (s & 1) * WS);
#pragma unroll
        for (int kk = 0; kk < 4; kk++) {
            const int k0 = kk * 8;
            uint32_t a[2][4];
#pragma unroll
            for (int mt = 0; mt < 2; mt++) {
                int base = (mbase + mt * 16 + g) * XSTR + k0 + t;
                a[mt][0] = uX[base];
                a[mt][1] = uX[base + 8 * XSTR];
                a[mt][2] = uX[base + 4];
                a[mt][3] = uX[base + 8 * XSTR + 4];
            }
#pragma unroll
            for (int nt = 0; nt < 8; nt++) {
                int col = nbase + nt * 8 + g;
                uint32_t b0 = uW[(k0 + t) * WSTR + col];
                uint32_t b1 = uW[(k0 + t + 4) * WSTR + col];
#pragma unroll
                for (int mt = 0; mt < 2; mt++) {
                    asm volatile(
                        "mma.sync.aligned.m16n8k8.row.col.f32.tf32.tf32.f32 "
                        "{%0,%1,%2,%3}, {%4,%5,%6,%7}, {%8,%9}, {%0,%1,%2,%3};\n"
                        : "+f"(acc[mt][nt][0]), "+f"(acc[mt][nt][1]),
                          "+f"(acc[mt][nt][2]), "+f"(acc[mt][nt][3])
                        : "r"(a[mt][0]), "r"(a[mt][1]), "r"(a[mt][2]), "r"(a[mt][3]),
                          "r"(b0), "r"(b1));
                }
            }
        }
        __syncthreads();
    }

    // Epilogue
    float* outp = (r < NR) ? (g_hall + (size_t)r * NN * DD) : y;
#pragma unroll
    for (int mt = 0; mt < 2; mt++) {
        int rA = row0 + mbase + mt * 16 + g;
#pragma unroll
        for (int nt = 0; nt < 8; nt++) {
            int col = nbase + nt * 8 + 2 * t;
            if (r == NR) {
                float ba = __ldg(bias + col), bb = __ldg(bias + col + 1);
                if (rA < NN)
                    *(float2*)(outp + (size_t)rA * DD + col) =
                        make_float2(acc[mt][nt][0] + ba, acc[mt][nt][1] + bb);
                if (rA + 8 < NN)
                    *(float2*)(outp + (size_t)(rA + 8) * DD + col) =
                        make_float2(acc[mt][nt][2] + ba, acc[mt][nt][3] + bb);
            } else {
                // streaming stores: don't pollute L2 (g_hall >> L2 anyway)
                if (rA < NN)
                    __stcs((float2*)(outp + (size_t)rA * DD + col),
                           make_float2(acc[mt][nt][0], acc[mt][nt][1]));
                if (rA + 8 < NN)
                    __stcs((float2*)(outp + (size_t)(rA + 8) * DD + col),
                           make_float2(acc[mt][nt][2], acc[mt][nt][3]));
            }
        }
    }
}

// ---------------------------------------------------------------------------
// Edge scatter: y[dst] += norm * gate(rel,src) * g_hall[rel][src].
// One warp per edge; red.global.add.v4.f32 into L2-resident output.
// ---------------------------------------------------------------------------
__global__ void edge_kernel(const int* __restrict__ src,
                            const int* __restrict__ dst,
                            const int* __restrict__ rel,
                            const float* __restrict__ norm,
                            float* __restrict__ y) {
    int e = (int)((blockIdx.x * (size_t)blockDim.x + threadIdx.x) >> 5);
    int lane = threadIdx.x & 31;
    if (e >= NE) return;
    int s = __ldg(src + e);
    int d = __ldg(dst + e);
    int r = __ldg(rel + e);
    float w = __ldg(norm + e) * __ldg(&g_sgate[(size_t)r * NN + s]);
    float4 m = __ldg(((const float4*)(g_hall + ((size_t)r * NN + s) * DD)) + lane);
    float* yp = y + (size_t)d * DD + lane * 4;
    asm volatile("red.global.add.v4.f32 [%0], {%1,%2,%3,%4};"
                 :: "l"(yp), "f"(m.x * w), "f"(m.y * w), "f"(m.z * w), "f"(m.w * w)
                 : "memory");
}

// ---------------------------------------------------------------------------
extern "C" void kernel_launch(void* const* d_in, const int* in_sizes, int n_in,
                              void* d_out, int out_size) {
    const float* h    = (const float*)d_in[0];
    const float* norm = (const float*)d_in[1];
    const float* w0   = (const float*)d_in[2];
    const float* b0   = (const float*)d_in[3];
    const float* lw0  = (const float*)d_in[4];
    const float* gw0  = (const float*)d_in[5];
    const float* w1   = (const float*)d_in[6];
    const float* b1   = (const float*)d_in[7];
    const float* lw1  = (const float*)d_in[8];
    const float* gw1  = (const float*)d_in[9];
    const int*   src  = (const int*)d_in[10];
    const int*   dst  = (const int*)d_in[11];
    const int*   rel  = (const int*)d_in[12];
    float* out = (float*)d_out;

    cudaFuncSetAttribute(gemm_kernel,
                         cudaFuncAttributeMaxDynamicSharedMemorySize, GEMM_SMEM);

    float* h1 = nullptr;
    cudaGetSymbolAddress((void**)&h1, g_h1);
    float* xt = nullptr;
    cudaGetSymbolAddress((void**)&xt, g_xt);

    dim3 ggrid(NR + 1, (NN + 127) / 128);
    const int xcvt_grid = (NN * 32) / 256;                 // 6250 (exact)
    const int wcvt_grid = ((NR + 1) * DD * DD / 4 + 255) / 256;
    const int gate_grid = (NN + 7) / 8;
    const int edge_grid = (int)(((size_t)NE * 32 + 255) / 256);

    // ---- Layer 0
    xcvt_kernel<<<xcvt_grid, 256>>>(h, xt, 0);
    wcvt_kernel<<<wcvt_grid, 256>>>(w0, lw0);
    gate_kernel<<<gate_grid, 128>>>(xt, gw0);
    gemm_kernel<<<ggrid, 256, GEMM_SMEM>>>(xt, b0, h1);
    edge_kernel<<<edge_grid, 256>>>(src, dst, rel, norm, h1);

    // ---- Layer 1 (relu fused into xcvt)
    xcvt_kernel<<<xcvt_grid, 256>>>(h1, xt, 1);
    wcvt_kernel<<<wcvt_grid, 256>>>(w1, lw1);
    gate_kernel<<<gate_grid, 128>>>(xt, gw1);
    gemm_kernel<<<ggrid, 256, GEMM_SMEM>>>(xt, b1, out);
    edge_kernel<<<edge_grid, 256>>>(src, dst, rel, norm, out);
}

// round 5
// speedup vs baseline: 1.2984x; 1.0013x over previous
#include <cuda_runtime.h>
#include <cstdint>

#define NN 50000
#define NE 800000
#define NR 16
#define DD 128

// Scratch (device globals; no dynamic allocation allowed).
__device__ float g_hall[(size_t)NR * NN * DD];   // 409.6 MB: per-relation transformed features
__device__ float g_sgate[(size_t)NR * NN];       // 3.2 MB: sigmoid gate table
__device__ float g_h1[(size_t)NN * DD];          // 25.6 MB: layer-0 output (pre-relu)
__device__ float g_xt[(size_t)NN * DD];          // 25.6 MB: relu'd + tf32-rounded X
__device__ float g_wt[(size_t)(NR + 1) * DD * DD]; // 1.1 MB: tf32-rounded W[0..15], loop_w

__device__ __forceinline__ uint32_t f2tf32(float f) {
    uint32_t u;
    asm("cvt.rna.tf32.f32 %0, %1;" : "=r"(u) : "f"(f));
    return u;
}
__device__ __forceinline__ uint32_t sptr(const void* p) {
    return (uint32_t)__cvta_generic_to_shared(p);
}

// ---------------------------------------------------------------------------
// X pre-pass: xt = tf32_rna( relu?(x) ).  Enables raw cp.async in the GEMM
// while keeping round-to-nearest tf32 numerics.
// ---------------------------------------------------------------------------
__global__ void xcvt_kernel(const float* __restrict__ x, float* __restrict__ xt,
                            int relu) {
    size_t i = (size_t)blockIdx.x * blockDim.x + threadIdx.x;  // float4 index
    float4 v = __ldg((const float4*)x + i);
    if (relu) {
        v.x = fmaxf(v.x, 0.f); v.y = fmaxf(v.y, 0.f);
        v.z = fmaxf(v.z, 0.f); v.w = fmaxf(v.w, 0.f);
    }
    uint4 o;
    o.x = f2tf32(v.x); o.y = f2tf32(v.y); o.z = f2tf32(v.z); o.w = f2tf32(v.w);
    ((uint4*)xt)[i] = o;
}

// W pre-pass: g_wt[0..15] = tf32(W[r]), g_wt[16] = tf32(loop_w).
__global__ void wcvt_kernel(const float* __restrict__ Wr,
                            const float* __restrict__ loopw) {
    size_t i = (size_t)blockIdx.x * blockDim.x + threadIdx.x;  // float4 index
    const size_t wlim = (size_t)NR * DD * DD / 4;
    float4 v = (i < wlim) ? __ldg((const float4*)Wr + i)
                          : __ldg((const float4*)loopw + (i - wlim));
    uint4 o;
    o.x = f2tf32(v.x); o.y = f2tf32(v.y); o.z = f2tf32(v.z); o.w = f2tf32(v.w);
    ((uint4*)g_wt)[i] = o;
}

// ---------------------------------------------------------------------------
// Gate table: g_sgate[r][n] = sigmoid( x[n] . gate_w[r] ).
// 128 threads = 8 nodes x 16 relations; x tile + gate weights in smem.
// ---------------------------------------------------------------------------
__global__ void gate_kernel(const float* __restrict__ x,
                            const float* __restrict__ gw) {
    __shared__ float sx[8][132];
    __shared__ float sg[16][132];
    const int tid = threadIdx.x;
    const int nb = blockIdx.x * 8;
#pragma unroll
    for (int i = 0; i < 4; i++) {           // gw: 16x128 = 512 float4
        int l = tid + i * 128;
        int r = l >> 5, c = l & 31;
        *(float4*)&sg[r][c * 4] = __ldg((const float4*)gw + r * 32 + c);
    }
#pragma unroll
    for (int i = 0; i < 2; i++) {           // x: 8x128 = 256 float4
        int l = tid + i * 128;
        int n = l >> 5, c = l & 31;
        float4 v = make_float4(0.f, 0.f, 0.f, 0.f);
        if (nb + n < NN) v = __ldg((const float4*)x + (size_t)(nb + n) * 32 + c);
        *(float4*)&sx[n][c * 4] = v;
    }
    __syncthreads();
    const int node = tid >> 4, rel = tid & 15;
    float d = 0.f;
#pragma unroll
    for (int k = 0; k < 32; k++) {
        float4 a = *(float4*)&sx[node][k * 4];
        float4 g = *(float4*)&sg[rel][k * 4];
        d += a.x * g.x + a.y * g.y + a.z * g.z + a.w * g.w;
    }
    if (nb + node < NN)
        g_sgate[(size_t)rel * NN + nb + node] = 1.f / (1.f + __expf(-d));
}

// ---------------------------------------------------------------------------
// Batched tf32 GEMM, cp.async 4-stage (K=32) double-buffered pipeline.
//   r in [0,16): g_hall[r] = Xt @ Wt[r]        (streaming stores)
//   r == 16    : y        = Xt @ Wt[16] + bias (initializes output)
// 128x128 block tile, 8 warps (4Mx2N), warp tile 32x64, 2 CTAs/SM.
// ---------------------------------------------------------------------------
#define XSTR 36                   // floats; bank = (4g+t): conflict-free A loads
#define WSTR 136                  // floats; bank = (8t+g): conflict-free B loads
#define XS (128 * XSTR)           // 4608 floats per stage
#define WS (32 * WSTR)            // 4352 floats per stage
#define GEMM_SMEM ((2 * XS + 2 * WS) * 4)   // 71680 B

__global__ void __launch_bounds__(256, 2)
gemm_kernel(const float* __restrict__ Xt,
            const float* __restrict__ bias,
            float* __restrict__ y) {
    extern __shared__ float sm[];
    float* sX = sm;
    float* sW = sm + 2 * XS;

    const int r    = blockIdx.x;           // relation fastest -> X tile L2 reuse
    const int row0 = blockIdx.y * 128;
    const int tid  = threadIdx.x;
    const float* Wp = g_wt + (size_t)r * DD * DD;

    float acc[2][8][4];
#pragma unroll
    for (int mt = 0; mt < 2; mt++)
#pragma unroll
        for (int nt = 0; nt < 8; nt++)
#pragma unroll
            for (int q = 0; q < 4; q++) acc[mt][nt][q] = 0.f;

    // cp.async issue for one K-stage (8 x 16B per thread)
    auto issue = [&](int s, int buf) {
#pragma unroll
        for (int i = 0; i < 4; i++) {
            int linear = tid + i * 256;                    // [0,1024)
            int xrow = linear >> 3, xc4 = linear & 7;
            const float4* src = (const float4*)Xt + (size_t)(row0 + xrow) * 32 + s * 8 + xc4;
            uint32_t dst = sptr(sX + buf * XS + xrow * XSTR + xc4 * 4);
            int pb = (row0 + xrow < NN) ? 16 : 0;
            asm volatile("cp.async.cg.shared.global [%0], [%1], 16, %2;\n"
                         :: "r"(dst), "l"(src), "r"(pb) : "memory");
        }
#pragma unroll
        for (int i = 0; i < 4; i++) {
            int linear = tid + i * 256;
            int wk = linear >> 5, wc4 = linear & 31;
            const float4* src = (const float4*)Wp + (size_t)(32 * s + wk) * 32 + wc4;
            uint32_t dst = sptr(sW + buf * WS + wk * WSTR + wc4 * 4);
            asm volatile("cp.async.cg.shared.global [%0], [%1], 16;\n"
                         :: "r"(dst), "l"(src) : "memory");
        }
    };

    issue(0, 0);
    asm volatile("cp.async.commit_group;\n" ::: "memory");

    const int warp = tid >> 5, lane = tid & 31;
    const int g = lane >> 2, t = lane & 3;
    const int mbase = (warp >> 1) * 32;
    const int nbase = (warp & 1) * 64;

#pragma unroll
    for (int s = 0; s < 4; s++) {
        if (s < 3) {
            issue(s + 1, (s + 1) & 1);
            asm volatile("cp.async.commit_group;\n" ::: "memory");
            asm volatile("cp.async.wait_group 1;\n" ::: "memory");
        } else {
            asm volatile("cp.async.wait_group 0;\n" ::: "memory");
        }
        __syncthreads();

        const uint32_t* uX = (const uint32_t*)(sX + (s & 1) * XS);
        const uint32_t* uW = (const uint32_t*)(sW + (s & 1) * WS);
#pragma unroll
        for (int kk = 0; kk < 4; kk++) {
            const int k0 = kk * 8;
            uint32_t a[2][4];
#pragma unroll
            for (int mt = 0; mt < 2; mt++) {
                int base = (mbase + mt * 16 + g) * XSTR + k0 + t;
                a[mt][0] = uX[base];
                a[mt][1] = uX[base + 8 * XSTR];
                a[mt][2] = uX[base + 4];
                a[mt][3] = uX[base + 8 * XSTR + 4];
            }
#pragma unroll
            for (int nt = 0; nt < 8; nt++) {
                int col = nbase + nt * 8 + g;
                uint32_t b0 = uW[(k0 + t) * WSTR + col];
                uint32_t b1 = uW[(k0 + t + 4) * WSTR + col];
#pragma unroll
                for (int mt = 0; mt < 2; mt++) {
                    asm volatile(
                        "mma.sync.aligned.m16n8k8.row.col.f32.tf32.tf32.f32 "
                        "{%0,%1,%2,%3}, {%4,%5,%6,%7}, {%8,%9}, {%0,%1,%2,%3};\n"
                        : "+f"(acc[mt][nt][0]), "+f"(acc[mt][nt][1]),
                          "+f"(acc[mt][nt][2]), "+f"(acc[mt][nt][3])
                        : "r"(a[mt][0]), "r"(a[mt][1]), "r"(a[mt][2]), "r"(a[mt][3]),
                          "r"(b0), "r"(b1));
                }
            }
        }
        __syncthreads();
    }

    // Epilogue
    float* outp = (r < NR) ? (g_hall + (size_t)r * NN * DD) : y;
#pragma unroll
    for (int mt = 0; mt < 2; mt++) {
        int rA = row0 + mbase + mt * 16 + g;
#pragma unroll
        for (int nt = 0; nt < 8; nt++) {
            int col = nbase + nt * 8 + 2 * t;
            if (r == NR) {
                float ba = __ldg(bias + col), bb = __ldg(bias + col + 1);
                if (rA < NN)
                    *(float2*)(outp + (size_t)rA * DD + col) =
                        make_float2(acc[mt][nt][0] + ba, acc[mt][nt][1] + bb);
                if (rA + 8 < NN)
                    *(float2*)(outp + (size_t)(rA + 8) * DD + col) =
                        make_float2(acc[mt][nt][2] + ba, acc[mt][nt][3] + bb);
            } else {
                // streaming stores: don't pollute L2 (g_hall >> L2 anyway)
                if (rA < NN)
                    __stcs((float2*)(outp + (size_t)rA * DD + col),
                           make_float2(acc[mt][nt][0], acc[mt][nt][1]));
                if (rA + 8 < NN)
                    __stcs((float2*)(outp + (size_t)(rA + 8) * DD + col),
                           make_float2(acc[mt][nt][2], acc[mt][nt][3]));
            }
        }
    }
}

// ---------------------------------------------------------------------------
// Edge scatter: y[dst] += norm * gate(rel,src) * g_hall[rel][src].
// One warp per edge; red.global.add.v4.f32 into L2-resident output.
// ---------------------------------------------------------------------------
__global__ void edge_kernel(const int* __restrict__ src,
                            const int* __restrict__ dst,
                            const int* __restrict__ rel,
                            const float* __restrict__ norm,
                            float* __restrict__ y) {
    int e = (int)((blockIdx.x * (size_t)blockDim.x + threadIdx.x) >> 5);
    int lane = threadIdx.x & 31;
    if (e >= NE) return;
    int s = __ldg(src + e);
    int d = __ldg(dst + e);
    int r = __ldg(rel + e);
    float w = __ldg(norm + e) * __ldg(&g_sgate[(size_t)r * NN + s]);
    float4 m = __ldg(((const float4*)(g_hall + ((size_t)r * NN + s) * DD)) + lane);
    float* yp = y + (size_t)d * DD + lane * 4;
    asm volatile("red.global.add.v4.f32 [%0], {%1,%2,%3,%4};"
                 :: "l"(yp), "f"(m.x * w), "f"(m.y * w), "f"(m.z * w), "f"(m.w * w)
                 : "memory");
}

// ---------------------------------------------------------------------------
extern "C" void kernel_launch(void* const* d_in, const int* in_sizes, int n_in,
                              void* d_out, int out_size) {
    const float* h    = (const float*)d_in[0];
    const float* norm = (const float*)d_in[1];
    const float* w0   = (const float*)d_in[2];
    const float* b0   = (const float*)d_in[3];
    const float* lw0  = (const float*)d_in[4];
    const float* gw0  = (const float*)d_in[5];
    const float* w1   = (const float*)d_in[6];
    const float* b1   = (const float*)d_in[7];
    const float* lw1  = (const float*)d_in[8];
    const float* gw1  = (const float*)d_in[9];
    const int*   src  = (const int*)d_in[10];
    const int*   dst  = (const int*)d_in[11];
    const int*   rel  = (const int*)d_in[12];
    float* out = (float*)d_out;

    cudaFuncSetAttribute(gemm_kernel,
                         cudaFuncAttributeMaxDynamicSharedMemorySize, GEMM_SMEM);

    float* h1 = nullptr;
    cudaGetSymbolAddress((void**)&h1, g_h1);
    float* xt = nullptr;
    cudaGetSymbolAddress((void**)&xt, g_xt);

    dim3 ggrid(NR + 1, (NN + 127) / 128);
    const int xcvt_grid = (NN * 32) / 256;                 // 6250 (exact)
    const int wcvt_grid = ((NR + 1) * DD * DD / 4 + 255) / 256;
    const int gate_grid = (NN + 7) / 8;
    const int edge_grid = (int)(((size_t)NE * 32 + 255) / 256);

    // ---- Layer 0
    xcvt_kernel<<<xcvt_grid, 256>>>(h, xt, 0);
    wcvt_kernel<<<wcvt_grid, 256>>>(w0, lw0);
    gate_kernel<<<gate_grid, 128>>>(xt, gw0);
    gemm_kernel<<<ggrid, 256, GEMM_SMEM>>>(xt, b0, h1);
    edge_kernel<<<edge_grid, 256>>>(src, dst, rel, norm, h1);

    // ---- Layer 1 (relu fused into xcvt)
    xcvt_kernel<<<xcvt_grid, 256>>>(h1, xt, 1);
    wcvt_kernel<<<wcvt_grid, 256>>>(w1, lw1);
    gate_kernel<<<gate_grid, 128>>>(xt, gw1);
    gemm_kernel<<<ggrid, 256, GEMM_SMEM>>>(xt, b1, out);
    edge_kernel<<<edge_grid, 256>>>(src, dst, rel, norm, out);
}

// round 6
// speedup vs baseline: 1.4902x; 1.1477x over previous
#include <cuda_runtime.h>
#include <cstdint>

#define NN 50000
#define NE 800000
#define NR 16
#define DD 128

// Scratch (device globals; no dynamic allocation allowed).
__device__ float g_hall[(size_t)NR * NN * DD];   // 409.6 MB: per-relation transformed features
__device__ float g_sgate[(size_t)NR * NN];       // 3.2 MB: sigmoid gate table
__device__ float g_h1[(size_t)NN * DD];          // 25.6 MB: layer-0 output (pre-relu)
__device__ float g_xt[(size_t)NN * DD];          // 25.6 MB: relu'd + tf32-rounded X
__device__ float g_wt[(size_t)(NR + 1) * DD * DD]; // 1.1 MB: tf32-rounded W[0..15], loop_w

__device__ __forceinline__ uint32_t f2tf32(float f) {
    uint32_t u;
    asm("cvt.rna.tf32.f32 %0, %1;" : "=r"(u) : "f"(f));
    return u;
}
__device__ __forceinline__ uint32_t sptr(const void* p) {
    return (uint32_t)__cvta_generic_to_shared(p);
}

// ---------------------------------------------------------------------------
// X pre-pass: xt = tf32_rna( relu?(x) ).  Enables raw cp.async in the GEMM
// while keeping round-to-nearest tf32 numerics.
// ---------------------------------------------------------------------------
__global__ void xcvt_kernel(const float* __restrict__ x, float* __restrict__ xt,
                            int relu) {
    size_t i = (size_t)blockIdx.x * blockDim.x + threadIdx.x;  // float4 index
    float4 v = __ldg((const float4*)x + i);
    if (relu) {
        v.x = fmaxf(v.x, 0.f); v.y = fmaxf(v.y, 0.f);
        v.z = fmaxf(v.z, 0.f); v.w = fmaxf(v.w, 0.f);
    }
    uint4 o;
    o.x = f2tf32(v.x); o.y = f2tf32(v.y); o.z = f2tf32(v.z); o.w = f2tf32(v.w);
    ((uint4*)xt)[i] = o;
}

// W pre-pass: g_wt[0..15] = tf32(W[r]), g_wt[16] = tf32(loop_w).
__global__ void wcvt_kernel(const float* __restrict__ Wr,
                            const float* __restrict__ loopw) {
    size_t i = (size_t)blockIdx.x * blockDim.x + threadIdx.x;  // float4 index
    const size_t wlim = (size_t)NR * DD * DD / 4;
    float4 v = (i < wlim) ? __ldg((const float4*)Wr + i)
                          : __ldg((const float4*)loopw + (i - wlim));
    uint4 o;
    o.x = f2tf32(v.x); o.y = f2tf32(v.y); o.z = f2tf32(v.z); o.w = f2tf32(v.w);
    ((uint4*)g_wt)[i] = o;
}

// ---------------------------------------------------------------------------
// Gate table: g_sgate[r][n] = sigmoid( x[n] . gate_w[r] ).
// 128 threads = 8 nodes x 16 relations; x tile + gate weights in smem.
// ---------------------------------------------------------------------------
__global__ void gate_kernel(const float* __restrict__ x,
                            const float* __restrict__ gw) {
    __shared__ float sx[8][132];
    __shared__ float sg[16][132];
    const int tid = threadIdx.x;
    const int nb = blockIdx.x * 8;
#pragma unroll
    for (int i = 0; i < 4; i++) {           // gw: 16x128 = 512 float4
        int l = tid + i * 128;
        int r = l >> 5, c = l & 31;
        *(float4*)&sg[r][c * 4] = __ldg((const float4*)gw + r * 32 + c);
    }
#pragma unroll
    for (int i = 0; i < 2; i++) {           // x: 8x128 = 256 float4
        int l = tid + i * 128;
        int n = l >> 5, c = l & 31;
        float4 v = make_float4(0.f, 0.f, 0.f, 0.f);
        if (nb + n < NN) v = __ldg((const float4*)x + (size_t)(nb + n) * 32 + c);
        *(float4*)&sx[n][c * 4] = v;
    }
    __syncthreads();
    const int node = tid >> 4, rel = tid & 15;
    float d = 0.f;
#pragma unroll
    for (int k = 0; k < 32; k++) {
        float4 a = *(float4*)&sx[node][k * 4];
        float4 g = *(float4*)&sg[rel][k * 4];
        d += a.x * g.x + a.y * g.y + a.z * g.z + a.w * g.w;
    }
    if (nb + node < NN)
        g_sgate[(size_t)rel * NN + nb + node] = 1.f / (1.f + __expf(-d));
}

// ---------------------------------------------------------------------------
// Batched tf32 GEMM, cp.async 3-buffer pipeline over 4 K-stages (K=32 each).
//   r in [0,16): g_hall[r] = Xt @ Wt[r]        (streaming stores)
//   r == 16    : y        = Xt @ Wt[16] + bias (initializes output)
// 128x128 block tile, 8 warps (4Mx2N), warp tile 32x64, 2 CTAs/SM.
// ---------------------------------------------------------------------------
#define XSTR 36                   // floats; bank = (4g+t): conflict-free A loads
#define WSTR 136                  // floats; bank = (8t+g): conflict-free B loads
#define XS (128 * XSTR)           // 4608 floats per stage
#define WS (32 * WSTR)            // 4352 floats per stage
#define NSTG 3
#define GEMM_SMEM (NSTG * (XS + WS) * 4)    // 107,520 B -> 2 CTAs = 215 KB/SM

__global__ void __launch_bounds__(256, 2)
gemm_kernel(const float* __restrict__ Xt,
            const float* __restrict__ bias,
            float* __restrict__ y) {
    extern __shared__ float sm[];
    float* sX = sm;
    float* sW = sm + NSTG * XS;

    const int r    = blockIdx.x;           // relation fastest -> X tile L2 reuse
    const int row0 = blockIdx.y * 128;
    const int tid  = threadIdx.x;
    const float* Wp = g_wt + (size_t)r * DD * DD;

    float acc[2][8][4];
#pragma unroll
    for (int mt = 0; mt < 2; mt++)
#pragma unroll
        for (int nt = 0; nt < 8; nt++)
#pragma unroll
            for (int q = 0; q < 4; q++) acc[mt][nt][q] = 0.f;

    // cp.async issue for one K-stage (8 x 16B per thread)
    auto issue = [&](int s, int buf) {
#pragma unroll
        for (int i = 0; i < 4; i++) {
            int linear = tid + i * 256;                    // [0,1024)
            int xrow = linear >> 3, xc4 = linear & 7;
            const float4* src = (const float4*)Xt + (size_t)(row0 + xrow) * 32 + s * 8 + xc4;
            uint32_t dst = sptr(sX + buf * XS + xrow * XSTR + xc4 * 4);
            int pb = (row0 + xrow < NN) ? 16 : 0;
            asm volatile("cp.async.cg.shared.global [%0], [%1], 16, %2;\n"
                         :: "r"(dst), "l"(src), "r"(pb) : "memory");
        }
#pragma unroll
        for (int i = 0; i < 4; i++) {
            int linear = tid + i * 256;
            int wk = linear >> 5, wc4 = linear & 31;
            const float4* src = (const float4*)Wp + (size_t)(32 * s + wk) * 32 + wc4;
            uint32_t dst = sptr(sW + buf * WS + wk * WSTR + wc4 * 4);
            asm volatile("cp.async.cg.shared.global [%0], [%1], 16;\n"
                         :: "r"(dst), "l"(src) : "memory");
        }
    };

    issue(0, 0);
    asm volatile("cp.async.commit_group;\n" ::: "memory");
    issue(1, 1);
    asm volatile("cp.async.commit_group;\n" ::: "memory");

    const int warp = tid >> 5, lane = tid & 31;
    const int g = lane >> 2, t = lane & 3;
    const int mbase = (warp >> 1) * 32;
    const int nbase = (warp & 1) * 64;

#pragma unroll
    for (int s = 0; s < 4; s++) {
        // Wait for stage s (groups complete in order; <=1 newer may stay pending).
        if (s < 3) asm volatile("cp.async.wait_group 1;\n" ::: "memory");
        else       asm volatile("cp.async.wait_group 0;\n" ::: "memory");
        // Single barrier: data of stage s visible to all warps AND all warps
        // are done reading the buffer that stage s+2 will overwrite.
        __syncthreads();
        if (s + 2 < 4) {
            issue(s + 2, (s + 2) % 3);
            asm volatile("cp.async.commit_group;\n" ::: "memory");
        }

        const uint32_t* uX = (const uint32_t*)(sX + (s % 3) * XS);
        const uint32_t* uW = (const uint32_t*)(sW + (s % 3) * WS);
#pragma unroll
        for (int kk = 0; kk < 4; kk++) {
            const int k0 = kk * 8;
            uint32_t a[2][4];
#pragma unroll
            for (int mt = 0; mt < 2; mt++) {
                int base = (mbase + mt * 16 + g) * XSTR + k0 + t;
                a[mt][0] = uX[base];
                a[mt][1] = uX[base + 8 * XSTR];
                a[mt][2] = uX[base + 4];
                a[mt][3] = uX[base + 8 * XSTR + 4];
            }
#pragma unroll
            for (int nt = 0; nt < 8; nt++) {
                int col = nbase + nt * 8 + g;
                uint32_t b0 = uW[(k0 + t) * WSTR + col];
                uint32_t b1 = uW[(k0 + t + 4) * WSTR + col];
#pragma unroll
                for (int mt = 0; mt < 2; mt++) {
                    asm volatile(
                        "mma.sync.aligned.m16n8k8.row.col.f32.tf32.tf32.f32 "
                        "{%0,%1,%2,%3}, {%4,%5,%6,%7}, {%8,%9}, {%0,%1,%2,%3};\n"
                        : "+f"(acc[mt][nt][0]), "+f"(acc[mt][nt][1]),
                          "+f"(acc[mt][nt][2]), "+f"(acc[mt][nt][3])
                        : "r"(a[mt][0]), "r"(a[mt][1]), "r"(a[mt][2]), "r"(a[mt][3]),
                          "r"(b0), "r"(b1));
                }
            }
        }
    }

    // Epilogue
    float* outp = (r < NR) ? (g_hall + (size_t)r * NN * DD) : y;
#pragma unroll
    for (int mt = 0; mt < 2; mt++) {
        int rA = row0 + mbase + mt * 16 + g;
#pragma unroll
        for (int nt = 0; nt < 8; nt++) {
            int col = nbase + nt * 8 + 2 * t;
            if (r == NR) {
                float ba = __ldg(bias + col), bb = __ldg(bias + col + 1);
                if (rA < NN)
                    *(float2*)(outp + (size_t)rA * DD + col) =
                        make_float2(acc[mt][nt][0] + ba, acc[mt][nt][1] + bb);
                if (rA + 8 < NN)
                    *(float2*)(outp + (size_t)(rA + 8) * DD + col) =
                        make_float2(acc[mt][nt][2] + ba, acc[mt][nt][3] + bb);
            } else {
                // streaming stores: don't pollute L2 (g_hall >> L2 anyway)
                if (rA < NN)
                    __stcs((float2*)(outp + (size_t)rA * DD + col),
                           make_float2(acc[mt][nt][0], acc[mt][nt][1]));
                if (rA + 8 < NN)
                    __stcs((float2*)(outp + (size_t)(rA + 8) * DD + col),
                           make_float2(acc[mt][nt][2], acc[mt][nt][3]));
            }
        }
    }
}

// ---------------------------------------------------------------------------
// Edge scatter: y[dst] += norm * gate(rel,src) * g_hall[rel][src].
// 4 edges per warp (MLP=4 on the 512B row loads), red.global.add.v4.f32
// into the L2-resident output. NE % 4 == 0 and the grid is exact.
// ---------------------------------------------------------------------------
#define EPW 4
__global__ void __launch_bounds__(256)
edge_kernel(const int* __restrict__ src,
            const int* __restrict__ dst,
            const int* __restrict__ rel,
            const float* __restrict__ norm,
            float* __restrict__ y) {
    const int warp = (blockIdx.x * 256 + threadIdx.x) >> 5;
    const int lane = threadIdx.x & 31;
    const int e0 = warp * EPW;

    float4 m[EPW];
    float  w[EPW];
    int    d[EPW];
#pragma unroll
    for (int i = 0; i < EPW; i++) {
        int e = e0 + i;
        int s = __ldg(src + e);
        int r = __ldg(rel + e);
        d[i] = __ldg(dst + e);
        w[i] = __ldg(norm + e) * __ldg(&g_sgate[(size_t)r * NN + s]);
        m[i] = __ldcs(((const float4*)(g_hall + ((size_t)r * NN + s) * DD)) + lane);
    }
#pragma unroll
    for (int i = 0; i < EPW; i++) {
        float* yp = y + (size_t)d[i] * DD + lane * 4;
        asm volatile("red.global.add.v4.f32 [%0], {%1,%2,%3,%4};"
                     :: "l"(yp), "f"(m[i].x * w[i]), "f"(m[i].y * w[i]),
                        "f"(m[i].z * w[i]), "f"(m[i].w * w[i])
                     : "memory");
    }
}

// ---------------------------------------------------------------------------
extern "C" void kernel_launch(void* const* d_in, const int* in_sizes, int n_in,
                              void* d_out, int out_size) {
    const float* h    = (const float*)d_in[0];
    const float* norm = (const float*)d_in[1];
    const float* w0   = (const float*)d_in[2];
    const float* b0   = (const float*)d_in[3];
    const float* lw0  = (const float*)d_in[4];
    const float* gw0  = (const float*)d_in[5];
    const float* w1   = (const float*)d_in[6];
    const float* b1   = (const float*)d_in[7];
    const float* lw1  = (const float*)d_in[8];
    const float* gw1  = (const float*)d_in[9];
    const int*   src  = (const int*)d_in[10];
    const int*   dst  = (const int*)d_in[11];
    const int*   rel  = (const int*)d_in[12];
    float* out = (float*)d_out;

    cudaFuncSetAttribute(gemm_kernel,
                         cudaFuncAttributeMaxDynamicSharedMemorySize, GEMM_SMEM);

    float* h1 = nullptr;
    cudaGetSymbolAddress((void**)&h1, g_h1);
    float* xt = nullptr;
    cudaGetSymbolAddress((void**)&xt, g_xt);

    dim3 ggrid(NR + 1, (NN + 127) / 128);
    const int xcvt_grid = (NN * 32) / 256;                 // 6250 (exact)
    const int wcvt_grid = ((NR + 1) * DD * DD / 4 + 255) / 256;
    const int gate_grid = (NN + 7) / 8;
    const int edge_grid = NE / (8 * EPW);                  // 8 warps/block, exact

    // ---- Layer 0
    xcvt_kernel<<<xcvt_grid, 256>>>(h, xt, 0);
    wcvt_kernel<<<wcvt_grid, 256>>>(w0, lw0);
    gate_kernel<<<gate_grid, 128>>>(xt, gw0);
    gemm_kernel<<<ggrid, 256, GEMM_SMEM>>>(xt, b0, h1);
    edge_kernel<<<edge_grid, 256>>>(src, dst, rel, norm, h1);

    // ---- Layer 1 (relu fused into xcvt)
    xcvt_kernel<<<xcvt_grid, 256>>>(h1, xt, 1);
    wcvt_kernel<<<wcvt_grid, 256>>>(w1, lw1);
    gate_kernel<<<gate_grid, 128>>>(xt, gw1);
    gemm_kernel<<<ggrid, 256, GEMM_SMEM>>>(xt, b1, out);
    edge_kernel<<<edge_grid, 256>>>(src, dst, rel, norm, out);
}

// round 7
// speedup vs baseline: 1.4919x; 1.0011x over previous
#include <cuda_runtime.h>
#include <cstdint>

#define NN 50000
#define NE 800000
#define NR 16
#define DD 128

// Scratch (device globals; no dynamic allocation allowed).
__device__ float g_hall[(size_t)NR * NN * DD];   // 409.6 MB: per-relation transformed features
__device__ float g_sgate[(size_t)NR * NN];       // 3.2 MB: sigmoid gate table
__device__ float g_h1[(size_t)NN * DD];          // 25.6 MB: layer-0 output (pre-relu)
__device__ float g_xt[(size_t)NN * DD];          // 25.6 MB: relu'd + tf32-rounded X
__device__ float g_wt[(size_t)(NR + 1) * DD * DD]; // 1.1 MB: tf32-rounded W[0..15], loop_w

__device__ __forceinline__ uint32_t f2tf32(float f) {
    uint32_t u;
    asm("cvt.rna.tf32.f32 %0, %1;" : "=r"(u) : "f"(f));
    return u;
}
__device__ __forceinline__ uint32_t sptr(const void* p) {
    return (uint32_t)__cvta_generic_to_shared(p);
}

// ---------------------------------------------------------------------------
// X pre-pass: xt = tf32_rna( relu?(x) ).  Enables raw cp.async in the GEMM
// while keeping round-to-nearest tf32 numerics.
// ---------------------------------------------------------------------------
__global__ void xcvt_kernel(const float* __restrict__ x, float* __restrict__ xt,
                            int relu) {
    size_t i = (size_t)blockIdx.x * blockDim.x + threadIdx.x;  // float4 index
    float4 v = __ldg((const float4*)x + i);
    if (relu) {
        v.x = fmaxf(v.x, 0.f); v.y = fmaxf(v.y, 0.f);
        v.z = fmaxf(v.z, 0.f); v.w = fmaxf(v.w, 0.f);
    }
    uint4 o;
    o.x = f2tf32(v.x); o.y = f2tf32(v.y); o.z = f2tf32(v.z); o.w = f2tf32(v.w);
    ((uint4*)xt)[i] = o;
}

// W pre-pass: g_wt[0..15] = tf32(W[r]), g_wt[16] = tf32(loop_w).
__global__ void wcvt_kernel(const float* __restrict__ Wr,
                            const float* __restrict__ loopw) {
    size_t i = (size_t)blockIdx.x * blockDim.x + threadIdx.x;  // float4 index
    const size_t wlim = (size_t)NR * DD * DD / 4;
    float4 v = (i < wlim) ? __ldg((const float4*)Wr + i)
                          : __ldg((const float4*)loopw + (i - wlim));
    uint4 o;
    o.x = f2tf32(v.x); o.y = f2tf32(v.y); o.z = f2tf32(v.z); o.w = f2tf32(v.w);
    ((uint4*)g_wt)[i] = o;
}

// ---------------------------------------------------------------------------
// Gate table: g_sgate[r][n] = sigmoid( x[n] . gate_w[r] ).
// 128 threads = 8 nodes x 16 relations; x tile + gate weights in smem.
// ---------------------------------------------------------------------------
__global__ void gate_kernel(const float* __restrict__ x,
                            const float* __restrict__ gw) {
    __shared__ float sx[8][132];
    __shared__ float sg[16][132];
    const int tid = threadIdx.x;
    const int nb = blockIdx.x * 8;
#pragma unroll
    for (int i = 0; i < 4; i++) {           // gw: 16x128 = 512 float4
        int l = tid + i * 128;
        int r = l >> 5, c = l & 31;
        *(float4*)&sg[r][c * 4] = __ldg((const float4*)gw + r * 32 + c);
    }
#pragma unroll
    for (int i = 0; i < 2; i++) {           // x: 8x128 = 256 float4
        int l = tid + i * 128;
        int n = l >> 5, c = l & 31;
        float4 v = make_float4(0.f, 0.f, 0.f, 0.f);
        if (nb + n < NN) v = __ldg((const float4*)x + (size_t)(nb + n) * 32 + c);
        *(float4*)&sx[n][c * 4] = v;
    }
    __syncthreads();
    const int node = tid >> 4, rel = tid & 15;
    float d = 0.f;
#pragma unroll
    for (int k = 0; k < 32; k++) {
        float4 a = *(float4*)&sx[node][k * 4];
        float4 g = *(float4*)&sg[rel][k * 4];
        d += a.x * g.x + a.y * g.y + a.z * g.z + a.w * g.w;
    }
    if (nb + node < NN)
        g_sgate[(size_t)rel * NN + nb + node] = 1.f / (1.f + __expf(-d));
}

// ---------------------------------------------------------------------------
// Batched tf32 GEMM, cp.async 3-buffer pipeline over 4 K-stages (K=32 each).
//   r in [0,16): g_hall[r] = Xt @ Wt[r]        (streaming stores)
//   r == 16    : y        = Xt @ Wt[16] + bias (initializes output)
// 128x128 block tile, 8 warps (4Mx2N), warp tile 32x64, 2 CTAs/SM.
// ---------------------------------------------------------------------------
#define XSTR 36                   // floats; bank = (4g+t): conflict-free A loads
#define WSTR 136                  // floats; bank = (8t+g): conflict-free B loads
#define XS (128 * XSTR)           // 4608 floats per stage
#define WS (32 * WSTR)            // 4352 floats per stage
#define NSTG 3
#define GEMM_SMEM (NSTG * (XS + WS) * 4)    // 107,520 B -> 2 CTAs = 215 KB/SM

__global__ void __launch_bounds__(256, 2)
gemm_kernel(const float* __restrict__ Xt,
            const float* __restrict__ bias,
            float* __restrict__ y) {
    extern __shared__ float sm[];
    float* sX = sm;
    float* sW = sm + NSTG * XS;

    const int r    = blockIdx.x;           // relation fastest -> X tile L2 reuse
    const int row0 = blockIdx.y * 128;
    const int tid  = threadIdx.x;
    const float* Wp = g_wt + (size_t)r * DD * DD;

    float acc[2][8][4];
#pragma unroll
    for (int mt = 0; mt < 2; mt++)
#pragma unroll
        for (int nt = 0; nt < 8; nt++)
#pragma unroll
            for (int q = 0; q < 4; q++) acc[mt][nt][q] = 0.f;

    // cp.async issue for one K-stage (8 x 16B per thread)
    auto issue = [&](int s, int buf) {
#pragma unroll
        for (int i = 0; i < 4; i++) {
            int linear = tid + i * 256;                    // [0,1024)
            int xrow = linear >> 3, xc4 = linear & 7;
            const float4* src = (const float4*)Xt + (size_t)(row0 + xrow) * 32 + s * 8 + xc4;
            uint32_t dst = sptr(sX + buf * XS + xrow * XSTR + xc4 * 4);
            int pb = (row0 + xrow < NN) ? 16 : 0;
            asm volatile("cp.async.cg.shared.global [%0], [%1], 16, %2;\n"
                         :: "r"(dst), "l"(src), "r"(pb) : "memory");
        }
#pragma unroll
        for (int i = 0; i < 4; i++) {
            int linear = tid + i * 256;
            int wk = linear >> 5, wc4 = linear & 31;
            const float4* src = (const float4*)Wp + (size_t)(32 * s + wk) * 32 + wc4;
            uint32_t dst = sptr(sW + buf * WS + wk * WSTR + wc4 * 4);
            asm volatile("cp.async.cg.shared.global [%0], [%1], 16;\n"
                         :: "r"(dst), "l"(src) : "memory");
        }
    };

    issue(0, 0);
    asm volatile("cp.async.commit_group;\n" ::: "memory");
    issue(1, 1);
    asm volatile("cp.async.commit_group;\n" ::: "memory");

    const int warp = tid >> 5, lane = tid & 31;
    const int g = lane >> 2, t = lane & 3;
    const int mbase = (warp >> 1) * 32;
    const int nbase = (warp & 1) * 64;

#pragma unroll
    for (int s = 0; s < 4; s++) {
        // Wait for stage s (groups complete in order; <=1 newer may stay pending).
        if (s < 3) asm volatile("cp.async.wait_group 1;\n" ::: "memory");
        else       asm volatile("cp.async.wait_group 0;\n" ::: "memory");
        // Single barrier: data of stage s visible to all warps AND all warps
        // are done reading the buffer that stage s+2 will overwrite.
        __syncthreads();
        if (s + 2 < 4) {
            issue(s + 2, (s + 2) % 3);
            asm volatile("cp.async.commit_group;\n" ::: "memory");
        }

        const uint32_t* uX = (const uint32_t*)(sX + (s % 3) * XS);
        const uint32_t* uW = (const uint32_t*)(sW + (s % 3) * WS);
#pragma unroll
        for (int kk = 0; kk < 4; kk++) {
            const int k0 = kk * 8;
            uint32_t a[2][4];
#pragma unroll
            for (int mt = 0; mt < 2; mt++) {
                int base = (mbase + mt * 16 + g) * XSTR + k0 + t;
                a[mt][0] = uX[base];
                a[mt][1] = uX[base + 8 * XSTR];
                a[mt][2] = uX[base + 4];
                a[mt][3] = uX[base + 8 * XSTR + 4];
            }
#pragma unroll
            for (int nt = 0; nt < 8; nt++) {
                int col = nbase + nt * 8 + g;
                uint32_t b0 = uW[(k0 + t) * WSTR + col];
                uint32_t b1 = uW[(k0 + t + 4) * WSTR + col];
#pragma unroll
                for (int mt = 0; mt < 2; mt++) {
                    asm volatile(
                        "mma.sync.aligned.m16n8k8.row.col.f32.tf32.tf32.f32 "
                        "{%0,%1,%2,%3}, {%4,%5,%6,%7}, {%8,%9}, {%0,%1,%2,%3};\n"
                        : "+f"(acc[mt][nt][0]), "+f"(acc[mt][nt][1]),
                          "+f"(acc[mt][nt][2]), "+f"(acc[mt][nt][3])
                        : "r"(a[mt][0]), "r"(a[mt][1]), "r"(a[mt][2]), "r"(a[mt][3]),
                          "r"(b0), "r"(b1));
                }
            }
        }
    }

    // Epilogue
    float* outp = (r < NR) ? (g_hall + (size_t)r * NN * DD) : y;
#pragma unroll
    for (int mt = 0; mt < 2; mt++) {
        int rA = row0 + mbase + mt * 16 + g;
#pragma unroll
        for (int nt = 0; nt < 8; nt++) {
            int col = nbase + nt * 8 + 2 * t;
            if (r == NR) {
                float ba = __ldg(bias + col), bb = __ldg(bias + col + 1);
                if (rA < NN)
                    *(float2*)(outp + (size_t)rA * DD + col) =
                        make_float2(acc[mt][nt][0] + ba, acc[mt][nt][1] + bb);
                if (rA + 8 < NN)
                    *(float2*)(outp + (size_t)(rA + 8) * DD + col) =
                        make_float2(acc[mt][nt][2] + ba, acc[mt][nt][3] + bb);
            } else {
                // streaming stores: don't pollute L2 (g_hall >> L2 anyway)
                if (rA < NN)
                    __stcs((float2*)(outp + (size_t)rA * DD + col),
                           make_float2(acc[mt][nt][0], acc[mt][nt][1]));
                if (rA + 8 < NN)
                    __stcs((float2*)(outp + (size_t)(rA + 8) * DD + col),
                           make_float2(acc[mt][nt][2], acc[mt][nt][3]));
            }
        }
    }
}

// ---------------------------------------------------------------------------
// Edge scatter: y[dst] += norm * gate(rel,src) * g_hall[rel][src].
// 4 edges per warp (MLP=4 on the 512B row loads), red.global.add.v4.f32
// into the L2-resident output. NE % 4 == 0 and the grid is exact.
// ---------------------------------------------------------------------------
#define EPW 4
__global__ void __launch_bounds__(256)
edge_kernel(const int* __restrict__ src,
            const int* __restrict__ dst,
            const int* __restrict__ rel,
            const float* __restrict__ norm,
            float* __restrict__ y) {
    const int warp = (blockIdx.x * 256 + threadIdx.x) >> 5;
    const int lane = threadIdx.x & 31;
    const int e0 = warp * EPW;

    float4 m[EPW];
    float  w[EPW];
    int    d[EPW];
#pragma unroll
    for (int i = 0; i < EPW; i++) {
        int e = e0 + i;
        int s = __ldg(src + e);
        int r = __ldg(rel + e);
        d[i] = __ldg(dst + e);
        w[i] = __ldg(norm + e) * __ldg(&g_sgate[(size_t)r * NN + s]);
        m[i] = __ldcs(((const float4*)(g_hall + ((size_t)r * NN + s) * DD)) + lane);
    }
#pragma unroll
    for (int i = 0; i < EPW; i++) {
        float* yp = y + (size_t)d[i] * DD + lane * 4;
        asm volatile("red.global.add.v4.f32 [%0], {%1,%2,%3,%4};"
                     :: "l"(yp), "f"(m[i].x * w[i]), "f"(m[i].y * w[i]),
                        "f"(m[i].z * w[i]), "f"(m[i].w * w[i])
                     : "memory");
    }
}

// ---------------------------------------------------------------------------
extern "C" void kernel_launch(void* const* d_in, const int* in_sizes, int n_in,
                              void* d_out, int out_size) {
    const float* h    = (const float*)d_in[0];
    const float* norm = (const float*)d_in[1];
    const float* w0   = (const float*)d_in[2];
    const float* b0   = (const float*)d_in[3];
    const float* lw0  = (const float*)d_in[4];
    const float* gw0  = (const float*)d_in[5];
    const float* w1   = (const float*)d_in[6];
    const float* b1   = (const float*)d_in[7];
    const float* lw1  = (const float*)d_in[8];
    const float* gw1  = (const float*)d_in[9];
    const int*   src  = (const int*)d_in[10];
    const int*   dst  = (const int*)d_in[11];
    const int*   rel  = (const int*)d_in[12];
    float* out = (float*)d_out;

    cudaFuncSetAttribute(gemm_kernel,
                         cudaFuncAttributeMaxDynamicSharedMemorySize, GEMM_SMEM);

    float* h1 = nullptr;
    cudaGetSymbolAddress((void**)&h1, g_h1);
    float* xt = nullptr;
    cudaGetSymbolAddress((void**)&xt, g_xt);

    dim3 ggrid(NR + 1, (NN + 127) / 128);
    const int xcvt_grid = (NN * 32) / 256;                 // 6250 (exact)
    const int wcvt_grid = ((NR + 1) * DD * DD / 4 + 255) / 256;
    const int gate_grid = (NN + 7) / 8;
    const int edge_grid = NE / (8 * EPW);                  // 8 warps/block, exact

    // ---- Layer 0
    xcvt_kernel<<<xcvt_grid, 256>>>(h, xt, 0);
    wcvt_kernel<<<wcvt_grid, 256>>>(w0, lw0);
    gate_kernel<<<gate_grid, 128>>>(xt, gw0);
    gemm_kernel<<<ggrid, 256, GEMM_SMEM>>>(xt, b0, h1);
    edge_kernel<<<edge_grid, 256>>>(src, dst, rel, norm, h1);

    // ---- Layer 1 (relu fused into xcvt)
    xcvt_kernel<<<xcvt_grid, 256>>>(h1, xt, 1);
    wcvt_kernel<<<wcvt_grid, 256>>>(w1, lw1);
    gate_kernel<<<gate_grid, 128>>>(xt, gw1);
    gemm_kernel<<<ggrid, 256, GEMM_SMEM>>>(xt, b1, out);
    edge_kernel<<<edge_grid, 256>>>(src, dst, rel, norm, out);
}

// round 9
// speedup vs baseline: 1.6885x; 1.1318x over previous
#include <cuda_runtime.h>
#include <cstdint>

#define NN 50000
#define NE 800000
#define NR 16
#define DD 128
#define NP 50048                 // NN padded to 128 (391 blocks)
#define NBLK 391
#define NFLAG (NR * NN)          // 800000 (r,s) pairs
#define NPADMAX (NR * NP)        // 800768 max padded compact rows

// Scratch (device globals; no dynamic allocation allowed).
__device__ float g_hall[(size_t)NPADMAX * DD];     // 410 MB compacted transformed rows
__device__ float g_sgate[(size_t)NR * NN];         // 3.2 MB gate table
__device__ float g_h1[(size_t)NN * DD];            // 25.6 MB layer-0 output (pre-relu)
__device__ float g_xt[(size_t)NP * DD];            // 25.6 MB tf32-rounded X (zero-padded)
__device__ float g_wt[(size_t)(NR + 1) * DD * DD]; // 1.1 MB tf32-rounded W[0..15], loop_w
// Compaction scratch
__device__ int g_flag[NFLAG];
__device__ int g_scan[NFLAG];
__device__ int g_bsum[1024];
__device__ int g_glist[NPADMAX];
__device__ int g_cidx[NE];
__device__ int g_relstart[NR];
__device__ int g_padoff[NR + 1];
__device__ int g_pblk[NR + 1];
__device__ int g_nblk;

__device__ __forceinline__ uint32_t f2tf32(float f) {
    uint32_t u;
    asm("cvt.rna.tf32.f32 %0, %1;" : "=r"(u) : "f"(f));
    return u;
}
__device__ __forceinline__ uint32_t sptr(const void* p) {
    return (uint32_t)__cvta_generic_to_shared(p);
}

// ---------------------------------------------------------------------------
// Compaction prep (deterministic, once per call)
// ---------------------------------------------------------------------------
__global__ void zero_kernel() {
    int i = blockIdx.x * 256 + threadIdx.x;          // grid covers NPADMAX
    g_glist[i] = 0;
    if (i < NFLAG) g_flag[i] = 0;
}
__global__ void mark_kernel(const int* __restrict__ src, const int* __restrict__ rel) {
    int e = blockIdx.x * 256 + threadIdx.x;
    g_flag[__ldg(rel + e) * NN + __ldg(src + e)] = 1;
}
// Block-local exclusive scan (1024 elems/block of 256 threads) + block sums.
__global__ void scan1_kernel() {
    __shared__ int sd[256];
    const int tid = threadIdx.x;
    int base = blockIdx.x * 1024 + tid * 4;
    int f[4], s = 0;
#pragma unroll
    for (int j = 0; j < 4; j++) {
        f[j] = (base + j < NFLAG) ? g_flag[base + j] : 0;
        s += f[j];
    }
    sd[tid] = s;
    __syncthreads();
#pragma unroll
    for (int off = 1; off < 256; off <<= 1) {
        int v = (tid >= off) ? sd[tid - off] : 0;
        __syncthreads();
        sd[tid] += v;
        __syncthreads();
    }
    int run = sd[tid] - s;                           // block-local exclusive
#pragma unroll
    for (int j = 0; j < 4; j++) {
        if (base + j < NFLAG) g_scan[base + j] = run;
        run += f[j];
    }
    if (tid == 255) g_bsum[blockIdx.x] = sd[255];
}
__global__ void scan2_kernel(int nblocks) {          // one block, 1024 threads
    __shared__ int sd[1024];
    const int tid = threadIdx.x;
    int v0 = (tid < nblocks) ? g_bsum[tid] : 0;
    sd[tid] = v0;
    __syncthreads();
#pragma unroll
    for (int off = 1; off < 1024; off <<= 1) {
        int v = (tid >= off) ? sd[tid - off] : 0;
        __syncthreads();
        sd[tid] += v;
        __syncthreads();
    }
    if (tid < nblocks) g_bsum[tid] = sd[tid] - v0;   // exclusive
}
__global__ void scan3_kernel() {
    int i = blockIdx.x * 256 + threadIdx.x;          // grid covers NFLAG
    if (i < NFLAG) g_scan[i] += g_bsum[i >> 10];
}
__global__ void meta_kernel() {
    if (threadIdx.x != 0) return;
    int total = g_scan[NFLAG - 1] + g_flag[NFLAG - 1];
    int pad = 0;
    for (int r = 0; r < NR; r++) {
        int st = g_scan[r * NN];
        int nx = (r < NR - 1) ? g_scan[(r + 1) * NN] : total;
        g_relstart[r] = st;
        g_padoff[r] = pad;
        g_pblk[r] = pad >> 7;
        pad += ((nx - st + 127) & ~127);
    }
    g_padoff[NR] = pad;
    g_pblk[NR] = pad >> 7;
    g_nblk = pad >> 7;
}
__global__ void build_kernel() {
    int p = blockIdx.x * 256 + threadIdx.x;          // grid covers NFLAG
    if (p >= NFLAG || !g_flag[p]) return;
    int r = p / NN, s = p - r * NN;
    g_glist[g_padoff[r] + g_scan[p] - g_relstart[r]] = s;
}
__global__ void cidx_kernel(const int* __restrict__ src, const int* __restrict__ rel) {
    int e = blockIdx.x * 256 + threadIdx.x;
    int r = __ldg(rel + e), s = __ldg(src + e);
    g_cidx[e] = g_padoff[r] + g_scan[r * NN + s] - g_relstart[r];
}

// ---------------------------------------------------------------------------
// X pre-pass: xt = tf32_rna( relu?(x) ), zero-padded to NP rows.
// ---------------------------------------------------------------------------
__global__ void xcvt_kernel(const float* __restrict__ x, int relu) {
    int i = blockIdx.x * 256 + threadIdx.x;          // float4 index, grid covers NP*32
    int m = i >> 5, c = i & 31;
    float4 v = make_float4(0.f, 0.f, 0.f, 0.f);
    if (m < NN) v = __ldg((const float4*)x + (size_t)m * 32 + c);
    if (relu) {
        v.x = fmaxf(v.x, 0.f); v.y = fmaxf(v.y, 0.f);
        v.z = fmaxf(v.z, 0.f); v.w = fmaxf(v.w, 0.f);
    }
    uint4 o;
    o.x = f2tf32(v.x); o.y = f2tf32(v.y); o.z = f2tf32(v.z); o.w = f2tf32(v.w);
    ((uint4*)g_xt)[i] = o;
}

// W pre-pass: g_wt[0..15] = tf32(W[r]), g_wt[16] = tf32(loop_w).
__global__ void wcvt_kernel(const float* __restrict__ Wr,
                            const float* __restrict__ loopw) {
    size_t i = (size_t)blockIdx.x * 256 + threadIdx.x;  // float4 index
    const size_t wlim = (size_t)NR * DD * DD / 4;
    float4 v = (i < wlim) ? __ldg((const float4*)Wr + i)
                          : __ldg((const float4*)loopw + (i - wlim));
    uint4 o;
    o.x = f2tf32(v.x); o.y = f2tf32(v.y); o.z = f2tf32(v.z); o.w = f2tf32(v.w);
    ((uint4*)g_wt)[i] = o;
}

// ---------------------------------------------------------------------------
// Gate table: g_sgate[r][n] = sigmoid( x[n] . gate_w[r] ).
// ---------------------------------------------------------------------------
__global__ void gate_kernel(const float* __restrict__ x,
                            const float* __restrict__ gw) {
    __shared__ float sx[8][132];
    __shared__ float sg[16][132];
    const int tid = threadIdx.x;
    const int nb = blockIdx.x * 8;
#pragma unroll
    for (int i = 0; i < 4; i++) {
        int l = tid + i * 128;
        int r = l >> 5, c = l & 31;
        *(float4*)&sg[r][c * 4] = __ldg((const float4*)gw + r * 32 + c);
    }
#pragma unroll
    for (int i = 0; i < 2; i++) {
        int l = tid + i * 128;
        int n = l >> 5, c = l & 31;
        float4 v = make_float4(0.f, 0.f, 0.f, 0.f);
        if (nb + n < NN) v = __ldg((const float4*)x + (size_t)(nb + n) * 32 + c);
        *(float4*)&sx[n][c * 4] = v;
    }
    __syncthreads();
    const int node = tid >> 4, rel = tid & 15;
    float d = 0.f;
#pragma unroll
    for (int k = 0; k < 32; k++) {
        float4 a = *(float4*)&sx[node][k * 4];
        float4 g = *(float4*)&sg[rel][k * 4];
        d += a.x * g.x + a.y * g.y + a.z * g.z + a.w * g.w;
    }
    if (nb + node < NN)
        g_sgate[(size_t)rel * NN + nb + node] = 1.f / (1.f + __expf(-d));
}

// ---------------------------------------------------------------------------
// Batched tf32 GEMM on COMPACTED rows, cp.async 3-buffer pipeline (4 K-stages).
//   bid <  NBLK : y = X @ loop_w + bias  (linear rows)
//   bid >= NBLK : data block j=bid-NBLK (exit if j>=g_nblk); relation from
//                 g_pblk; A rows gathered via g_glist; out -> g_hall[j*128..].
// 128x128 block tile, 8 warps (4Mx2N), warp tile 32x64, 2 CTAs/SM.
// ---------------------------------------------------------------------------
#define XSTR 36
#define WSTR 136
#define XS (128 * XSTR)
#define WS (32 * WSTR)
#define NSTG 3
#define GEMM_SMEM (NSTG * (XS + WS) * 4)    // 107,520 B -> 2 CTAs = 215 KB/SM

__global__ void __launch_bounds__(256, 2)
gemm_kernel(const float* __restrict__ bias, float* __restrict__ y) {
    extern __shared__ float sm[];
    float* sX = sm;
    float* sW = sm + NSTG * XS;

    const int bid = blockIdx.x;
    const int tid = threadIdx.x;
    const bool is_loop = bid < NBLK;
    int r, rowbase;
    if (is_loop) {
        r = NR;
        rowbase = bid * 128;
    } else {
        int j = bid - NBLK;
        if (j >= g_nblk) return;
        r = NR - 1;
#pragma unroll
        for (int q = NR - 1; q > 0; q--)
            if (j < g_pblk[q]) r = q - 1;
        rowbase = j * 128;          // compact row base
    }
    const float* Wp = g_wt + (size_t)r * DD * DD;

    // Gathered A-row ids for this thread's 4 copy chunks (same across stages).
    int ga[4];
#pragma unroll
    for (int i = 0; i < 4; i++) {
        int xr = (tid >> 3) + i * 32;
        ga[i] = is_loop ? (rowbase + xr) : __ldg(&g_glist[rowbase + xr]);
    }
    const int xc4 = tid & 7;

    float acc[2][8][4];
#pragma unroll
    for (int mt = 0; mt < 2; mt++)
#pragma unroll
        for (int nt = 0; nt < 8; nt++)
#pragma unroll
            for (int q = 0; q < 4; q++) acc[mt][nt][q] = 0.f;

    auto issue = [&](int s, int buf) {
#pragma unroll
        for (int i = 0; i < 4; i++) {
            const char* src = (const char*)g_xt + (size_t)ga[i] * 512 + s * 128 + xc4 * 16;
            uint32_t dst = sptr(sX + buf * XS + ((tid >> 3) + i * 32) * XSTR + xc4 * 4);
            asm volatile("cp.async.cg.shared.global [%0], [%1], 16;"
                         :: "r"(dst), "l"(src) : "memory");
        }
#pragma unroll
        for (int i = 0; i < 4; i++) {
            int linear = tid + i * 256;
            int wk = linear >> 5, wc4 = linear & 31;
            const float4* src = (const float4*)Wp + (size_t)(32 * s + wk) * 32 + wc4;
            uint32_t dst = sptr(sW + buf * WS + wk * WSTR + wc4 * 4);
            asm volatile("cp.async.cg.shared.global [%0], [%1], 16;"
                         :: "r"(dst), "l"(src) : "memory");
        }
    };

    issue(0, 0);
    asm volatile("cp.async.commit_group;" ::: "memory");
    issue(1, 1);
    asm volatile("cp.async.commit_group;" ::: "memory");

    const int warp = tid >> 5, lane = tid & 31;
    const int g = lane >> 2, t = lane & 3;
    const int mbase = (warp >> 1) * 32;
    const int nbase = (warp & 1) * 64;

#pragma unroll
    for (int s = 0; s < 4; s++) {
        if (s < 3) asm volatile("cp.async.wait_group 1;" ::: "memory");
        else       asm volatile("cp.async.wait_group 0;" ::: "memory");
        __syncthreads();
        if (s + 2 < 4) {
            issue(s + 2, (s + 2) % 3);
            asm volatile("cp.async.commit_group;" ::: "memory");
        }

        const uint32_t* uX = (const uint32_t*)(sX + (s % 3) * XS);
        const uint32_t* uW = (const uint32_t*)(sW + (s % 3) * WS);
#pragma unroll
        for (int kk = 0; kk < 4; kk++) {
            const int k0 = kk * 8;
            uint32_t a[2][4];
#pragma unroll
            for (int mt = 0; mt < 2; mt++) {
                int base = (mbase + mt * 16 + g) * XSTR + k0 + t;
                a[mt][0] = uX[base];
                a[mt][1] = uX[base + 8 * XSTR];
                a[mt][2] = uX[base + 4];
                a[mt][3] = uX[base + 8 * XSTR + 4];
            }
#pragma unroll
            for (int nt = 0; nt < 8; nt++) {
                int col = nbase + nt * 8 + g;
                uint32_t b0 = uW[(k0 + t) * WSTR + col];
                uint32_t b1 = uW[(k0 + t + 4) * WSTR + col];
#pragma unroll
                for (int mt = 0; mt < 2; mt++) {
                    asm volatile(
                        "mma.sync.aligned.m16n8k8.row.col.f32.tf32.tf32.f32 "
                        "{%0,%1,%2,%3}, {%4,%5,%6,%7}, {%8,%9}, {%0,%1,%2,%3};\n"
                        : "+f"(acc[mt][nt][0]), "+f"(acc[mt][nt][1]),
                          "+f"(acc[mt][nt][2]), "+f"(acc[mt][nt][3])
                        : "r"(a[mt][0]), "r"(a[mt][1]), "r"(a[mt][2]), "r"(a[mt][3]),
                          "r"(b0), "r"(b1));
                }
            }
        }
    }

    // Epilogue
#pragma unroll
    for (int mt = 0; mt < 2; mt++) {
        int rA = rowbase + mbase + mt * 16 + g;      // loop: node row; data: compact row
#pragma unroll
        for (int nt = 0; nt < 8; nt++) {
            int col = nbase + nt * 8 + 2 * t;
            if (is_loop) {
                float ba = __ldg(bias + col), bb = __ldg(bias + col + 1);
                if (rA < NN)
                    *(float2*)(y + (size_t)rA * DD + col) =
                        make_float2(acc[mt][nt][0] + ba, acc[mt][nt][1] + bb);
                if (rA + 8 < NN)
                    *(float2*)(y + (size_t)(rA + 8) * DD + col) =
                        make_float2(acc[mt][nt][2] + ba, acc[mt][nt][3] + bb);
            } else {
                __stcs((float2*)(g_hall + (size_t)rA * DD + col),
                       make_float2(acc[mt][nt][0], acc[mt][nt][1]));
                __stcs((float2*)(g_hall + (size_t)(rA + 8) * DD + col),
                       make_float2(acc[mt][nt][2], acc[mt][nt][3]));
            }
        }
    }
}

// ---------------------------------------------------------------------------
// Edge scatter: y[dst] += norm * gate(rel,src) * g_hall[cidx[e]].
// 4 edges per warp, red.global.add.v4.f32 into L2-resident output.
// ---------------------------------------------------------------------------
#define EPW 4
__global__ void __launch_bounds__(256)
edge_kernel(const int* __restrict__ src,
            const int* __restrict__ dst,
            const int* __restrict__ rel,
            const float* __restrict__ norm,
            float* __restrict__ y) {
    const int warp = (blockIdx.x * 256 + threadIdx.x) >> 5;
    const int lane = threadIdx.x & 31;
    const int e0 = warp * EPW;

    float4 m[EPW];
    float  w[EPW];
    int    d[EPW];
#pragma unroll
    for (int i = 0; i < EPW; i++) {
        int e = e0 + i;
        int s = __ldg(src + e);
        int r = __ldg(rel + e);
        int c = __ldg(&g_cidx[e]);
        d[i] = __ldg(dst + e);
        w[i] = __ldg(norm + e) * __ldg(&g_sgate[(size_t)r * NN + s]);
        m[i] = __ldg(((const float4*)(g_hall + (size_t)c * DD)) + lane);
    }
#pragma unroll
    for (int i = 0; i < EPW; i++) {
        float* yp = y + (size_t)d[i] * DD + lane * 4;
        asm volatile("red.global.add.v4.f32 [%0], {%1,%2,%3,%4};"
                     :: "l"(yp), "f"(m[i].x * w[i]), "f"(m[i].y * w[i]),
                        "f"(m[i].z * w[i]), "f"(m[i].w * w[i])
                     : "memory");
    }
}

// ---------------------------------------------------------------------------
extern "C" void kernel_launch(void* const* d_in, const int* in_sizes, int n_in,
                              void* d_out, int out_size) {
    const float* h    = (const float*)d_in[0];
    const float* norm = (const float*)d_in[1];
    const float* w0   = (const float*)d_in[2];
    const float* b0   = (const float*)d_in[3];
    const float* lw0  = (const float*)d_in[4];
    const float* gw0  = (const float*)d_in[5];
    const float* w1   = (const float*)d_in[6];
    const float* b1   = (const float*)d_in[7];
    const float* lw1  = (const float*)d_in[8];
    const float* gw1  = (const float*)d_in[9];
    const int*   src  = (const int*)d_in[10];
    const int*   dst  = (const int*)d_in[11];
    const int*   rel  = (const int*)d_in[12];
    float* out = (float*)d_out;

    cudaFuncSetAttribute(gemm_kernel,
                         cudaFuncAttributeMaxDynamicSharedMemorySize, GEMM_SMEM);

    float* h1 = nullptr;
    cudaGetSymbolAddress((void**)&h1, g_h1);
    float* xt = nullptr;
    cudaGetSymbolAddress((void**)&xt, g_xt);

    const int NB1 = (NFLAG + 1023) / 1024;           // 782 scan blocks
    const int gemm_grid = NBLK + NPADMAX / 128;      // 391 + 6256 worst case
    const int xcvt_grid = NP * 32 / 256;
    const int wcvt_grid = ((NR + 1) * DD * DD / 4 + 255) / 256;
    const int gate_grid = (NN + 7) / 8;
    const int edge_grid = NE / (8 * EPW);

    // ---- Compaction prep (shared by both layers)
    zero_kernel<<<NPADMAX / 256, 256>>>();
    mark_kernel<<<NE / 256, 256>>>(src, rel);
    scan1_kernel<<<NB1, 256>>>();
    scan2_kernel<<<1, 1024>>>(NB1);
    scan3_kernel<<<(NFLAG + 255) / 256, 256>>>();
    meta_kernel<<<1, 32>>>();
    build_kernel<<<(NFLAG + 255) / 256, 256>>>();
    cidx_kernel<<<NE / 256, 256>>>(src, rel);

    // ---- Layer 0
    xcvt_kernel<<<xcvt_grid, 256>>>(h, 0);
    wcvt_kernel<<<wcvt_grid, 256>>>(w0, lw0);
    gate_kernel<<<gate_grid, 128>>>(xt, gw0);
    gemm_kernel<<<gemm_grid, 256, GEMM_SMEM>>>(b0, h1);
    edge_kernel<<<edge_grid, 256>>>(src, dst, rel, norm, h1);

    // ---- Layer 1 (relu fused into xcvt)
    xcvt_kernel<<<xcvt_grid, 256>>>(h1, 1);
    wcvt_kernel<<<wcvt_grid, 256>>>(w1, lw1);
    gate_kernel<<<gate_grid, 128>>>(xt, gw1);
    gemm_kernel<<<gemm_grid, 256, GEMM_SMEM>>>(b1, out);
    edge_kernel<<<edge_grid, 256>>>(src, dst, rel, norm, out);
}

// round 10
// speedup vs baseline: 1.7620x; 1.0435x over previous
#include <cuda_runtime.h>
#include <cstdint>

#define NN 50000
#define NE 800000
#define NR 16
#define DD 128
#define NP 50048                 // NN padded to 128 (391 blocks)
#define NBLK 391
#define NFLAG (NR * NN)          // 800000 (r,s) pairs
#define NPADMAX (NR * NP)        // 800768 max padded compact rows

// Scratch (device globals; no dynamic allocation allowed).
__device__ float g_sgate[(size_t)NR * NN];         // 3.2 MB gate table
__device__ float g_h1[(size_t)NN * DD];            // 25.6 MB layer-0 output (pre-relu)
__device__ float g_xt[(size_t)NP * DD];            // 25.6 MB tf32-rounded X (zero-padded)
__device__ float g_wt[(size_t)(NR + 1) * DD * DD]; // 1.1 MB tf32-rounded W[0..15], loop_w
// Compaction + CSR scratch
__device__ int g_flag[NFLAG];
__device__ int g_scan[NFLAG];
__device__ int g_bsum[1024];
__device__ int g_glist[NPADMAX];
__device__ int g_cidx[NE];
__device__ int g_ecnt[NPADMAX];
__device__ int g_efill[NPADMAX];
__device__ int g_erow[NPADMAX + 1];
__device__ int g_elist[NE];
__device__ int g_relstart[NR];
__device__ int g_padoff[NR + 1];
__device__ int g_pblk[NR + 1];
__device__ int g_nblk;

__device__ __forceinline__ uint32_t f2tf32(float f) {
    uint32_t u;
    asm("cvt.rna.tf32.f32 %0, %1;" : "=r"(u) : "f"(f));
    return u;
}
__device__ __forceinline__ uint32_t sptr(const void* p) {
    return (uint32_t)__cvta_generic_to_shared(p);
}

// ---------------------------------------------------------------------------
// Compaction + CSR prep (once per call)
// ---------------------------------------------------------------------------
__global__ void zero_kernel() {
    int i = blockIdx.x * 256 + threadIdx.x;          // grid covers NPADMAX exactly
    g_glist[i] = 0;
    g_ecnt[i] = 0;
    g_efill[i] = 0;
    if (i < NFLAG) g_flag[i] = 0;
}
__global__ void mark_kernel(const int* __restrict__ src, const int* __restrict__ rel) {
    int e = blockIdx.x * 256 + threadIdx.x;
    g_flag[__ldg(rel + e) * NN + __ldg(src + e)] = 1;
}
// Block-local exclusive scan (1024 elems/block of 256 threads) + block sums.
__global__ void scan1_kernel(const int* __restrict__ in, int* __restrict__ out, int n) {
    __shared__ int sd[256];
    const int tid = threadIdx.x;
    int base = blockIdx.x * 1024 + tid * 4;
    int f[4], s = 0;
#pragma unroll
    for (int j = 0; j < 4; j++) {
        f[j] = (base + j < n) ? in[base + j] : 0;
        s += f[j];
    }
    sd[tid] = s;
    __syncthreads();
#pragma unroll
    for (int off = 1; off < 256; off <<= 1) {
        int v = (tid >= off) ? sd[tid - off] : 0;
        __syncthreads();
        sd[tid] += v;
        __syncthreads();
    }
    int run = sd[tid] - s;                           // block-local exclusive
#pragma unroll
    for (int j = 0; j < 4; j++) {
        if (base + j < n) out[base + j] = run;
        run += f[j];
    }
    if (tid == 255) g_bsum[blockIdx.x] = sd[255];
}
__global__ void scan2_kernel(int nblocks) {          // one block, 1024 threads
    __shared__ int sd[1024];
    const int tid = threadIdx.x;
    int v0 = (tid < nblocks) ? g_bsum[tid] : 0;
    sd[tid] = v0;
    __syncthreads();
#pragma unroll
    for (int off = 1; off < 1024; off <<= 1) {
        int v = (tid >= off) ? sd[tid - off] : 0;
        __syncthreads();
        sd[tid] += v;
        __syncthreads();
    }
    if (tid < nblocks) g_bsum[tid] = sd[tid] - v0;   // exclusive
}
__global__ void scan3_kernel(int* __restrict__ out, int n, int tail) {
    int i = blockIdx.x * 256 + threadIdx.x;
    if (i < n) out[i] += g_bsum[i >> 10];
    if (i == 0 && tail >= 0) out[n] = tail;
}
__global__ void meta_kernel() {
    if (threadIdx.x != 0) return;
    int total = g_scan[NFLAG - 1] + g_flag[NFLAG - 1];
    int pad = 0;
    for (int r = 0; r < NR; r++) {
        int st = g_scan[r * NN];
        int nx = (r < NR - 1) ? g_scan[(r + 1) * NN] : total;
        g_relstart[r] = st;
        g_padoff[r] = pad;
        g_pblk[r] = pad >> 7;
        pad += ((nx - st + 127) & ~127);
    }
    g_padoff[NR] = pad;
    g_pblk[NR] = pad >> 7;
    g_nblk = pad >> 7;
}
__global__ void build_kernel() {
    int p = blockIdx.x * 256 + threadIdx.x;          // grid covers NFLAG
    if (p >= NFLAG || !g_flag[p]) return;
    int r = p / NN, s = p - r * NN;
    g_glist[g_padoff[r] + g_scan[p] - g_relstart[r]] = s;
}
__global__ void cidx_kernel(const int* __restrict__ src, const int* __restrict__ rel) {
    int e = blockIdx.x * 256 + threadIdx.x;
    int r = __ldg(rel + e), s = __ldg(src + e);
    int c = g_padoff[r] + g_scan[r * NN + s] - g_relstart[r];
    g_cidx[e] = c;
    atomicAdd(&g_ecnt[c], 1);
}
__global__ void scatter_kernel() {
    int e = blockIdx.x * 256 + threadIdx.x;          // grid covers NE
    int c = g_cidx[e];
    int pos = g_erow[c] + atomicAdd(&g_efill[c], 1);
    g_elist[pos] = e;
}

// ---------------------------------------------------------------------------
// X pre-pass: xt = tf32_rna( relu?(x) ), zero-padded to NP rows.
// ---------------------------------------------------------------------------
__global__ void xcvt_kernel(const float* __restrict__ x, int relu) {
    int i = blockIdx.x * 256 + threadIdx.x;          // float4 index, grid covers NP*32
    int m = i >> 5, c = i & 31;
    float4 v = make_float4(0.f, 0.f, 0.f, 0.f);
    if (m < NN) v = __ldg((const float4*)x + (size_t)m * 32 + c);
    if (relu) {
        v.x = fmaxf(v.x, 0.f); v.y = fmaxf(v.y, 0.f);
        v.z = fmaxf(v.z, 0.f); v.w = fmaxf(v.w, 0.f);
    }
    uint4 o;
    o.x = f2tf32(v.x); o.y = f2tf32(v.y); o.z = f2tf32(v.z); o.w = f2tf32(v.w);
    ((uint4*)g_xt)[i] = o;
}

// W pre-pass: g_wt[0..15] = tf32(W[r]), g_wt[16] = tf32(loop_w).
__global__ void wcvt_kernel(const float* __restrict__ Wr,
                            const float* __restrict__ loopw) {
    size_t i = (size_t)blockIdx.x * 256 + threadIdx.x;  // float4 index
    const size_t wlim = (size_t)NR * DD * DD / 4;
    float4 v = (i < wlim) ? __ldg((const float4*)Wr + i)
                          : __ldg((const float4*)loopw + (i - wlim));
    uint4 o;
    o.x = f2tf32(v.x); o.y = f2tf32(v.y); o.z = f2tf32(v.z); o.w = f2tf32(v.w);
    ((uint4*)g_wt)[i] = o;
}

// ---------------------------------------------------------------------------
// Gate table: g_sgate[r][n] = sigmoid( x[n] . gate_w[r] ).
// ---------------------------------------------------------------------------
__global__ void gate_kernel(const float* __restrict__ x,
                            const float* __restrict__ gw) {
    __shared__ float sx[8][132];
    __shared__ float sg[16][132];
    const int tid = threadIdx.x;
    const int nb = blockIdx.x * 8;
#pragma unroll
    for (int i = 0; i < 4; i++) {
        int l = tid + i * 128;
        int r = l >> 5, c = l & 31;
        *(float4*)&sg[r][c * 4] = __ldg((const float4*)gw + r * 32 + c);
    }
#pragma unroll
    for (int i = 0; i < 2; i++) {
        int l = tid + i * 128;
        int n = l >> 5, c = l & 31;
        float4 v = make_float4(0.f, 0.f, 0.f, 0.f);
        if (nb + n < NN) v = __ldg((const float4*)x + (size_t)(nb + n) * 32 + c);
        *(float4*)&sx[n][c * 4] = v;
    }
    __syncthreads();
    const int node = tid >> 4, rel = tid & 15;
    float d = 0.f;
#pragma unroll
    for (int k = 0; k < 32; k++) {
        float4 a = *(float4*)&sx[node][k * 4];
        float4 g = *(float4*)&sg[rel][k * 4];
        d += a.x * g.x + a.y * g.y + a.z * g.z + a.w * g.w;
    }
    if (nb + node < NN)
        g_sgate[(size_t)rel * NN + nb + node] = 1.f / (1.f + __expf(-d));
}

// ---------------------------------------------------------------------------
// Shared GEMM machinery: 128x128x128 tf32 tile, cp.async 3-buffer pipeline.
// ---------------------------------------------------------------------------
#define XSTR 36
#define WSTR 136
#define XS (128 * XSTR)
#define WS (32 * WSTR)
#define NSTG 3
#define GEMM_SMEM (NSTG * (XS + WS) * 4)    // 107,520 B -> 2 CTAs = 215 KB/SM

#define GEMM_MAINLOOP(GA_EXPR)                                                    \
    float* sX = sm;                                                               \
    float* sW = sm + NSTG * XS;                                                   \
    int ga[4];                                                                    \
    _Pragma("unroll")                                                             \
    for (int i = 0; i < 4; i++) {                                                 \
        int xr = (tid >> 3) + i * 32;                                             \
        ga[i] = (GA_EXPR);                                                        \
    }                                                                             \
    const int xc4 = tid & 7;                                                      \
    float acc[2][8][4];                                                           \
    _Pragma("unroll")                                                             \
    for (int mt = 0; mt < 2; mt++)                                                \
        _Pragma("unroll")                                                         \
        for (int nt = 0; nt < 8; nt++)                                            \
            _Pragma("unroll")                                                     \
            for (int q = 0; q < 4; q++) acc[mt][nt][q] = 0.f;                     \
    auto issue = [&](int s, int buf) {                                            \
        _Pragma("unroll")                                                         \
        for (int i = 0; i < 4; i++) {                                             \
            const char* srcp = (const char*)g_xt + (size_t)ga[i] * 512            \
                               + s * 128 + xc4 * 16;                              \
            uint32_t dstp = sptr(sX + buf * XS + ((tid >> 3) + i * 32) * XSTR     \
                                 + xc4 * 4);                                      \
            asm volatile("cp.async.cg.shared.global [%0], [%1], 16;"              \
                         :: "r"(dstp), "l"(srcp) : "memory");                     \
        }                                                                         \
        _Pragma("unroll")                                                         \
        for (int i = 0; i < 4; i++) {                                             \
            int linear = tid + i * 256;                                           \
            int wk = linear >> 5, wc4 = linear & 31;                              \
            const float4* srcp = (const float4*)Wp + (size_t)(32 * s + wk) * 32   \
                                 + wc4;                                           \
            uint32_t dstp = sptr(sW + buf * WS + wk * WSTR + wc4 * 4);            \
            asm volatile("cp.async.cg.shared.global [%0], [%1], 16;"              \
                         :: "r"(dstp), "l"(srcp) : "memory");                     \
        }                                                                         \
    };                                                                            \
    issue(0, 0);                                                                  \
    asm volatile("cp.async.commit_group;" ::: "memory");                          \
    issue(1, 1);                                                                  \
    asm volatile("cp.async.commit_group;" ::: "memory");                          \
    const int warp = tid >> 5, lane = tid & 31;                                   \
    const int g = lane >> 2, t = lane & 3;                                        \
    const int mbase = (warp >> 1) * 32;                                           \
    const int nbase = (warp & 1) * 64;                                            \
    _Pragma("unroll")                                                             \
    for (int s = 0; s < 4; s++) {                                                 \
        if (s < 3) asm volatile("cp.async.wait_group 1;" ::: "memory");           \
        else       asm volatile("cp.async.wait_group 0;" ::: "memory");           \
        __syncthreads();                                                          \
        if (s + 2 < 4) {                                                          \
            issue(s + 2, (s + 2) % 3);                                            \
            asm volatile("cp.async.commit_group;" ::: "memory");                  \
        }                                                                         \
        const uint32_t* uX = (const uint32_t*)(sX + (s % 3) * XS);                \
        const uint32_t* uW = (const uint32_t*)(sW + (s % 3) * WS);                \
        _Pragma("unroll")                                                         \
        for (int kk = 0; kk < 4; kk++) {                                          \
            const int k0 = kk * 8;                                                \
            uint32_t a[2][4];                                                     \
            _Pragma("unroll")                                                     \
            for (int mt = 0; mt < 2; mt++) {                                      \
                int base = (mbase + mt * 16 + g) * XSTR + k0 + t;                 \
                a[mt][0] = uX[base];                                              \
                a[mt][1] = uX[base + 8 * XSTR];                                   \
                a[mt][2] = uX[base + 4];                                          \
                a[mt][3] = uX[base + 8 * XSTR + 4];                               \
            }                                                                     \
            _Pragma("unroll")                                                     \
            for (int nt = 0; nt < 8; nt++) {                                      \
                int col = nbase + nt * 8 + g;                                     \
                uint32_t b0 = uW[(k0 + t) * WSTR + col];                          \
                uint32_t b1 = uW[(k0 + t + 4) * WSTR + col];                      \
                _Pragma("unroll")                                                 \
                for (int mt = 0; mt < 2; mt++) {                                  \
                    asm volatile(                                                 \
                        "mma.sync.aligned.m16n8k8.row.col.f32.tf32.tf32.f32 "     \
                        "{%0,%1,%2,%3}, {%4,%5,%6,%7}, {%8,%9}, {%0,%1,%2,%3};\n" \
                        : "+f"(acc[mt][nt][0]), "+f"(acc[mt][nt][1]),             \
                          "+f"(acc[mt][nt][2]), "+f"(acc[mt][nt][3])              \
                        : "r"(a[mt][0]), "r"(a[mt][1]), "r"(a[mt][2]),            \
                          "r"(a[mt][3]), "r"(b0), "r"(b1));                       \
                }                                                                 \
            }                                                                     \
        }                                                                         \
    }

// Self-loop GEMM: y = X @ loop_w + bias  (initializes y; must run first).
__global__ void __launch_bounds__(256, 2)
gemm_loop_kernel(const float* __restrict__ bias, float* __restrict__ y) {
    extern __shared__ float sm[];
    const int tid = threadIdx.x;
    const int rowbase = blockIdx.x * 128;
    const float* Wp = g_wt + (size_t)NR * DD * DD;

    GEMM_MAINLOOP(rowbase + xr)

#pragma unroll
    for (int mt = 0; mt < 2; mt++) {
        int rA = rowbase + mbase + mt * 16 + g;
#pragma unroll
        for (int nt = 0; nt < 8; nt++) {
            int col = nbase + nt * 8 + 2 * t;
            float ba = __ldg(bias + col), bb = __ldg(bias + col + 1);
            if (rA < NN)
                *(float2*)(y + (size_t)rA * DD + col) =
                    make_float2(acc[mt][nt][0] + ba, acc[mt][nt][1] + bb);
            if (rA + 8 < NN)
                *(float2*)(y + (size_t)(rA + 8) * DD + col) =
                    make_float2(acc[mt][nt][2] + ba, acc[mt][nt][3] + bb);
        }
    }
}

// Data GEMM + fused edge scatter: compute 128 compacted rows of X@W[r], then
// for each incident edge reduce weight*row straight into y (no g_hall pass).
__global__ void __launch_bounds__(256, 2)
gemm_data_kernel(const int* __restrict__ dst, const float* __restrict__ norm,
                 float* __restrict__ y) {
    extern __shared__ float sm[];
    const int tid = threadIdx.x;
    const int j = blockIdx.x;
    if (j >= g_nblk) return;
    int r = NR - 1;
#pragma unroll
    for (int q = NR - 1; q > 0; q--)
        if (j < g_pblk[q]) r = q - 1;
    const int rowbase = j * 128;
    const float* Wp = g_wt + (size_t)r * DD * DD;

    GEMM_MAINLOOP(__ldg(&g_glist[rowbase + xr]))

    // ---- Fused scatter epilogue ----
    __syncthreads();                       // all warps done reading smem buffers
    float* st = sm;                        // 128 x 132 tile (67.6 KB)
    float* rg = sm + 128 * 132;            // 128 row gates
#pragma unroll
    for (int mt = 0; mt < 2; mt++) {
        int rloc = mbase + mt * 16 + g;
#pragma unroll
        for (int nt = 0; nt < 8; nt++) {
            int col = nbase + nt * 8 + 2 * t;
            *(float2*)&st[rloc * 132 + col] =
                make_float2(acc[mt][nt][0], acc[mt][nt][1]);
            *(float2*)&st[(rloc + 8) * 132 + col] =
                make_float2(acc[mt][nt][2], acc[mt][nt][3]);
        }
    }
    if (tid < 128) {
        int s_node = __ldg(&g_glist[rowbase + tid]);
        rg[tid] = __ldg(&g_sgate[(size_t)r * NN + s_node]);
    }
    __syncthreads();

    const int ebeg = __ldg(&g_erow[rowbase]);
    const int eend = __ldg(&g_erow[rowbase + 128]);
    for (int i = ebeg + warp; i < eend; i += 8) {
        int e = __ldg(&g_elist[i]);
        int local = __ldg(&g_cidx[e]) - rowbase;
        int dn = __ldg(dst + e);
        float wgt = __ldg(norm + e) * rg[local];
        float4 v = *(float4*)&st[local * 132 + lane * 4];
        float* yp = y + (size_t)dn * DD + lane * 4;
        asm volatile("red.global.add.v4.f32 [%0], {%1,%2,%3,%4};"
                     :: "l"(yp), "f"(v.x * wgt), "f"(v.y * wgt),
                        "f"(v.z * wgt), "f"(v.w * wgt)
                     : "memory");
    }
}

// ---------------------------------------------------------------------------
extern "C" void kernel_launch(void* const* d_in, const int* in_sizes, int n_in,
                              void* d_out, int out_size) {
    const float* h    = (const float*)d_in[0];
    const float* norm = (const float*)d_in[1];
    const float* w0   = (const float*)d_in[2];
    const float* b0   = (const float*)d_in[3];
    const float* lw0  = (const float*)d_in[4];
    const float* gw0  = (const float*)d_in[5];
    const float* w1   = (const float*)d_in[6];
    const float* b1   = (const float*)d_in[7];
    const float* lw1  = (const float*)d_in[8];
    const float* gw1  = (const float*)d_in[9];
    const int*   src  = (const int*)d_in[10];
    const int*   dst  = (const int*)d_in[11];
    const int*   rel  = (const int*)d_in[12];
    float* out = (float*)d_out;

    cudaFuncSetAttribute(gemm_loop_kernel,
                         cudaFuncAttributeMaxDynamicSharedMemorySize, GEMM_SMEM);
    cudaFuncSetAttribute(gemm_data_kernel,
                         cudaFuncAttributeMaxDynamicSharedMemorySize, GEMM_SMEM);

    float* h1 = nullptr;
    cudaGetSymbolAddress((void**)&h1, g_h1);
    float* xt = nullptr;
    cudaGetSymbolAddress((void**)&xt, g_xt);
    int* scanp = nullptr;
    cudaGetSymbolAddress((void**)&scanp, g_scan);
    int* flagp = nullptr;
    cudaGetSymbolAddress((void**)&flagp, g_flag);
    int* ecntp = nullptr;
    cudaGetSymbolAddress((void**)&ecntp, g_ecnt);
    int* erowp = nullptr;
    cudaGetSymbolAddress((void**)&erowp, g_erow);

    const int NBF = (NFLAG + 1023) / 1024;           // 782
    const int NBE = (NPADMAX + 1023) / 1024;         // 783
    const int data_grid = NPADMAX / 128;             // 6256 worst case
    const int xcvt_grid = NP * 32 / 256;
    const int wcvt_grid = ((NR + 1) * DD * DD / 4 + 255) / 256;
    const int gate_grid = (NN + 7) / 8;

    // ---- Compaction + CSR prep (shared by both layers)
    zero_kernel<<<NPADMAX / 256, 256>>>();
    mark_kernel<<<NE / 256, 256>>>(src, rel);
    scan1_kernel<<<NBF, 256>>>(flagp, scanp, NFLAG);
    scan2_kernel<<<1, 1024>>>(NBF);
    scan3_kernel<<<(NFLAG + 255) / 256, 256>>>(scanp, NFLAG, -1);
    meta_kernel<<<1, 32>>>();
    build_kernel<<<(NFLAG + 255) / 256, 256>>>();
    cidx_kernel<<<NE / 256, 256>>>(src, rel);
    scan1_kernel<<<NBE, 256>>>(ecntp, erowp, NPADMAX);
    scan2_kernel<<<1, 1024>>>(NBE);
    scan3_kernel<<<(NPADMAX + 255) / 256, 256>>>(erowp, NPADMAX, NE);
    scatter_kernel<<<NE / 256, 256>>>();

    // ---- Layer 0
    xcvt_kernel<<<xcvt_grid, 256>>>(h, 0);
    wcvt_kernel<<<wcvt_grid, 256>>>(w0, lw0);
    gate_kernel<<<gate_grid, 128>>>(xt, gw0);
    gemm_loop_kernel<<<NBLK, 256, GEMM_SMEM>>>(b0, h1);
    gemm_data_kernel<<<data_grid, 256, GEMM_SMEM>>>(dst, norm, h1);

    // ---- Layer 1 (relu fused into xcvt)
    xcvt_kernel<<<xcvt_grid, 256>>>(h1, 1);
    wcvt_kernel<<<wcvt_grid, 256>>>(w1, lw1);
    gate_kernel<<<gate_grid, 128>>>(xt, gw1);
    gemm_loop_kernel<<<NBLK, 256, GEMM_SMEM>>>(b1, out);
    gemm_data_kernel<<<data_grid, 256, GEMM_SMEM>>>(dst, norm, out);
}

// round 11
// speedup vs baseline: 1.7907x; 1.0163x over previous
#include <cuda_runtime.h>
#include <cstdint>

#define NN 50000
#define NE 800000
#define NR 16
#define DD 128
#define NP 50048                 // NN padded to 128 (391 blocks)
#define NBLK 391
#define NFLAG (NR * NN)          // 800000 (r,s) pairs
#define NPADMAX (NR * NP)        // 800768 max padded compact rows

// Scratch (device globals; no dynamic allocation allowed).
__device__ float g_sgate[(size_t)NR * NN];         // 3.2 MB gate table
__device__ float g_h1[(size_t)NN * DD];            // 25.6 MB layer-0 output (pre-relu)
__device__ float g_xt[(size_t)NP * DD];            // 25.6 MB tf32-rounded X (zero-padded)
__device__ float g_wt[(size_t)(NR + 1) * DD * DD]; // 1.1 MB tf32-rounded W[0..15], loop_w
// Compaction + CSR scratch
__device__ int g_flag[NFLAG];
__device__ int g_scan[NFLAG];
__device__ int g_bsum[1024];
__device__ int g_glist[NPADMAX];
__device__ int g_cidx[NE];
__device__ int g_ecnt[NPADMAX];
__device__ int g_efill[NPADMAX];
__device__ int g_erow[NPADMAX + 1];
__device__ int g_elist[NE];      // edge ids sorted by compact row
__device__ int g_spack[NE];      // (dst << 8) | local_row, in elist order
__device__ float g_sw[NE];       // per-layer edge weight (norm * gate), elist order
__device__ int g_relstart[NR];
__device__ int g_padoff[NR + 1];
__device__ int g_pblk[NR + 1];
__device__ int g_nblk;

__device__ __forceinline__ uint32_t f2tf32(float f) {
    uint32_t u;
    asm("cvt.rna.tf32.f32 %0, %1;" : "=r"(u) : "f"(f));
    return u;
}
__device__ __forceinline__ uint32_t sptr(const void* p) {
    return (uint32_t)__cvta_generic_to_shared(p);
}

// ---------------------------------------------------------------------------
// Compaction + CSR prep (once per call)
// ---------------------------------------------------------------------------
__global__ void zero_kernel() {
    int i = blockIdx.x * 256 + threadIdx.x;          // grid covers NPADMAX exactly
    g_glist[i] = 0;
    g_ecnt[i] = 0;
    g_efill[i] = 0;
    if (i < NFLAG) g_flag[i] = 0;
}
__global__ void mark_kernel(const int* __restrict__ src, const int* __restrict__ rel) {
    int e = blockIdx.x * 256 + threadIdx.x;
    g_flag[__ldg(rel + e) * NN + __ldg(src + e)] = 1;
}
// Block-local exclusive scan (1024 elems/block of 256 threads) + block sums.
__global__ void scan1_kernel(const int* __restrict__ in, int* __restrict__ out, int n) {
    __shared__ int sd[256];
    const int tid = threadIdx.x;
    int base = blockIdx.x * 1024 + tid * 4;
    int f[4], s = 0;
#pragma unroll
    for (int j = 0; j < 4; j++) {
        f[j] = (base + j < n) ? in[base + j] : 0;
        s += f[j];
    }
    sd[tid] = s;
    __syncthreads();
#pragma unroll
    for (int off = 1; off < 256; off <<= 1) {
        int v = (tid >= off) ? sd[tid - off] : 0;
        __syncthreads();
        sd[tid] += v;
        __syncthreads();
    }
    int run = sd[tid] - s;                           // block-local exclusive
#pragma unroll
    for (int j = 0; j < 4; j++) {
        if (base + j < n) out[base + j] = run;
        run += f[j];
    }
    if (tid == 255) g_bsum[blockIdx.x] = sd[255];
}
__global__ void scan2_kernel(int nblocks) {          // one block, 1024 threads
    __shared__ int sd[1024];
    const int tid = threadIdx.x;
    int v0 = (tid < nblocks) ? g_bsum[tid] : 0;
    sd[tid] = v0;
    __syncthreads();
#pragma unroll
    for (int off = 1; off < 1024; off <<= 1) {
        int v = (tid >= off) ? sd[tid - off] : 0;
        __syncthreads();
        sd[tid] += v;
        __syncthreads();
    }
    if (tid < nblocks) g_bsum[tid] = sd[tid] - v0;   // exclusive
}
__global__ void scan3_kernel(int* __restrict__ out, int n, int tail) {
    int i = blockIdx.x * 256 + threadIdx.x;
    if (i < n) out[i] += g_bsum[i >> 10];
    if (i == 0 && tail >= 0) out[n] = tail;
}
__global__ void meta_kernel() {
    if (threadIdx.x != 0) return;
    int total = g_scan[NFLAG - 1] + g_flag[NFLAG - 1];
    int pad = 0;
    for (int r = 0; r < NR; r++) {
        int st = g_scan[r * NN];
        int nx = (r < NR - 1) ? g_scan[(r + 1) * NN] : total;
        g_relstart[r] = st;
        g_padoff[r] = pad;
        g_pblk[r] = pad >> 7;
        pad += ((nx - st + 127) & ~127);
    }
    g_padoff[NR] = pad;
    g_pblk[NR] = pad >> 7;
    g_nblk = pad >> 7;
}
__global__ void build_kernel() {
    int p = blockIdx.x * 256 + threadIdx.x;          // grid covers NFLAG
    if (p >= NFLAG || !g_flag[p]) return;
    int r = p / NN, s = p - r * NN;
    g_glist[g_padoff[r] + g_scan[p] - g_relstart[r]] = s;
}
__global__ void cidx_kernel(const int* __restrict__ src, const int* __restrict__ rel) {
    int e = blockIdx.x * 256 + threadIdx.x;
    int r = __ldg(rel + e), s = __ldg(src + e);
    int c = g_padoff[r] + g_scan[r * NN + s] - g_relstart[r];
    g_cidx[e] = c;
    atomicAdd(&g_ecnt[c], 1);
}
__global__ void scatter_kernel(const int* __restrict__ dst) {
    int e = blockIdx.x * 256 + threadIdx.x;          // grid covers NE
    int c = g_cidx[e];
    int pos = g_erow[c] + atomicAdd(&g_efill[c], 1);
    g_elist[pos] = e;
    g_spack[pos] = (__ldg(dst + e) << 8) | (c & 127);
}
// Per-layer edge weights in elist order: g_sw[i] = norm[e] * gate(rel[e], src[e]).
__global__ void ew_kernel(const int* __restrict__ src, const int* __restrict__ rel,
                          const float* __restrict__ norm) {
    int i = blockIdx.x * 256 + threadIdx.x;          // grid covers NE
    int e = __ldg(&g_elist[i]);
    int r = __ldg(rel + e), s = __ldg(src + e);
    g_sw[i] = __ldg(norm + e) * __ldg(&g_sgate[(size_t)r * NN + s]);
}

// ---------------------------------------------------------------------------
// X pre-pass: xt = tf32_rna( relu?(x) ), zero-padded to NP rows.
// ---------------------------------------------------------------------------
__global__ void xcvt_kernel(const float* __restrict__ x, int relu) {
    int i = blockIdx.x * 256 + threadIdx.x;          // float4 index, grid covers NP*32
    int m = i >> 5, c = i & 31;
    float4 v = make_float4(0.f, 0.f, 0.f, 0.f);
    if (m < NN) v = __ldg((const float4*)x + (size_t)m * 32 + c);
    if (relu) {
        v.x = fmaxf(v.x, 0.f); v.y = fmaxf(v.y, 0.f);
        v.z = fmaxf(v.z, 0.f); v.w = fmaxf(v.w, 0.f);
    }
    uint4 o;
    o.x = f2tf32(v.x); o.y = f2tf32(v.y); o.z = f2tf32(v.z); o.w = f2tf32(v.w);
    ((uint4*)g_xt)[i] = o;
}

// W pre-pass: g_wt[0..15] = tf32(W[r]), g_wt[16] = tf32(loop_w).
__global__ void wcvt_kernel(const float* __restrict__ Wr,
                            const float* __restrict__ loopw) {
    size_t i = (size_t)blockIdx.x * 256 + threadIdx.x;  // float4 index
    const size_t wlim = (size_t)NR * DD * DD / 4;
    float4 v = (i < wlim) ? __ldg((const float4*)Wr + i)
                          : __ldg((const float4*)loopw + (i - wlim));
    uint4 o;
    o.x = f2tf32(v.x); o.y = f2tf32(v.y); o.z = f2tf32(v.z); o.w = f2tf32(v.w);
    ((uint4*)g_wt)[i] = o;
}

// ---------------------------------------------------------------------------
// Gate table: g_sgate[r][n] = sigmoid( x[n] . gate_w[r] ).
// ---------------------------------------------------------------------------
__global__ void gate_kernel(const float* __restrict__ x,
                            const float* __restrict__ gw) {
    __shared__ float sx[8][132];
    __shared__ float sg[16][132];
    const int tid = threadIdx.x;
    const int nb = blockIdx.x * 8;
#pragma unroll
    for (int i = 0; i < 4; i++) {
        int l = tid + i * 128;
        int r = l >> 5, c = l & 31;
        *(float4*)&sg[r][c * 4] = __ldg((const float4*)gw + r * 32 + c);
    }
#pragma unroll
    for (int i = 0; i < 2; i++) {
        int l = tid + i * 128;
        int n = l >> 5, c = l & 31;
        float4 v = make_float4(0.f, 0.f, 0.f, 0.f);
        if (nb + n < NN) v = __ldg((const float4*)x + (size_t)(nb + n) * 32 + c);
        *(float4*)&sx[n][c * 4] = v;
    }
    __syncthreads();
    const int node = tid >> 4, rel = tid & 15;
    float d = 0.f;
#pragma unroll
    for (int k = 0; k < 32; k++) {
        float4 a = *(float4*)&sx[node][k * 4];
        float4 g = *(float4*)&sg[rel][k * 4];
        d += a.x * g.x + a.y * g.y + a.z * g.z + a.w * g.w;
    }
    if (nb + node < NN)
        g_sgate[(size_t)rel * NN + nb + node] = 1.f / (1.f + __expf(-d));
}

// ---------------------------------------------------------------------------
// Shared GEMM machinery: 128x128x128 tf32 tile, cp.async 3-buffer pipeline.
// ---------------------------------------------------------------------------
#define XSTR 36
#define WSTR 136
#define XS (128 * XSTR)
#define WS (32 * WSTR)
#define NSTG 3
#define GEMM_SMEM (NSTG * (XS + WS) * 4)    // 107,520 B -> 2 CTAs = 215 KB/SM

#define GEMM_MAINLOOP(GA_EXPR)                                                    \
    float* sX = sm;                                                               \
    float* sW = sm + NSTG * XS;                                                   \
    int ga[4];                                                                    \
    _Pragma("unroll")                                                             \
    for (int i = 0; i < 4; i++) {                                                 \
        int xr = (tid >> 3) + i * 32;                                             \
        ga[i] = (GA_EXPR);                                                        \
    }                                                                             \
    const int xc4 = tid & 7;                                                      \
    float acc[2][8][4];                                                           \
    _Pragma("unroll")                                                             \
    for (int mt = 0; mt < 2; mt++)                                                \
        _Pragma("unroll")                                                         \
        for (int nt = 0; nt < 8; nt++)                                            \
            _Pragma("unroll")                                                     \
            for (int q = 0; q < 4; q++) acc[mt][nt][q] = 0.f;                     \
    auto issue = [&](int s, int buf) {                                            \
        _Pragma("unroll")                                                         \
        for (int i = 0; i < 4; i++) {                                             \
            const char* srcp = (const char*)g_xt + (size_t)ga[i] * 512            \
                               + s * 128 + xc4 * 16;                              \
            uint32_t dstp = sptr(sX + buf * XS + ((tid >> 3) + i * 32) * XSTR     \
                                 + xc4 * 4);                                      \
            asm volatile("cp.async.cg.shared.global [%0], [%1], 16;"              \
                         :: "r"(dstp), "l"(srcp) : "memory");                     \
        }                                                                         \
        _Pragma("unroll")                                                         \
        for (int i = 0; i < 4; i++) {                                             \
            int linear = tid + i * 256;                                           \
            int wk = linear >> 5, wc4 = linear & 31;                              \
            const float4* srcp = (const float4*)Wp + (size_t)(32 * s + wk) * 32   \
                                 + wc4;                                           \
            uint32_t dstp = sptr(sW + buf * WS + wk * WSTR + wc4 * 4);            \
            asm volatile("cp.async.cg.shared.global [%0], [%1], 16;"              \
                         :: "r"(dstp), "l"(srcp) : "memory");                     \
        }                                                                         \
    };                                                                            \
    issue(0, 0);                                                                  \
    asm volatile("cp.async.commit_group;" ::: "memory");                          \
    issue(1, 1);                                                                  \
    asm volatile("cp.async.commit_group;" ::: "memory");                          \
    const int warp = tid >> 5, lane = tid & 31;                                   \
    const int g = lane >> 2, t = lane & 3;                                        \
    const int mbase = (warp >> 1) * 32;                                           \
    const int nbase = (warp & 1) * 64;                                            \
    _Pragma("unroll")                                                             \
    for (int s = 0; s < 4; s++) {                                                 \
        if (s < 3) asm volatile("cp.async.wait_group 1;" ::: "memory");           \
        else       asm volatile("cp.async.wait_group 0;" ::: "memory");           \
        __syncthreads();                                                          \
        if (s + 2 < 4) {                                                          \
            issue(s + 2, (s + 2) % 3);                                            \
            asm volatile("cp.async.commit_group;" ::: "memory");                  \
        }                                                                         \
        const uint32_t* uX = (const uint32_t*)(sX + (s % 3) * XS);                \
        const uint32_t* uW = (const uint32_t*)(sW + (s % 3) * WS);                \
        _Pragma("unroll")                                                         \
        for (int kk = 0; kk < 4; kk++) {                                          \
            const int k0 = kk * 8;                                                \
            uint32_t a[2][4];                                                     \
            _Pragma("unroll")                                                     \
            for (int mt = 0; mt < 2; mt++) {                                      \
                int base = (mbase + mt * 16 + g) * XSTR + k0 + t;                 \
                a[mt][0] = uX[base];                                              \
                a[mt][1] = uX[base + 8 * XSTR];                                   \
                a[mt][2] = uX[base + 4];                                          \
                a[mt][3] = uX[base + 8 * XSTR + 4];                               \
            }                                                                     \
            _Pragma("unroll")                                                     \
            for (int nt = 0; nt < 8; nt++) {                                      \
                int col = nbase + nt * 8 + g;                                     \
                uint32_t b0 = uW[(k0 + t) * WSTR + col];                          \
                uint32_t b1 = uW[(k0 + t + 4) * WSTR + col];                      \
                _Pragma("unroll")                                                 \
                for (int mt = 0; mt < 2; mt++) {                                  \
                    asm volatile(                                                 \
                        "mma.sync.aligned.m16n8k8.row.col.f32.tf32.tf32.f32 "     \
                        "{%0,%1,%2,%3}, {%4,%5,%6,%7}, {%8,%9}, {%0,%1,%2,%3};\n" \
                        : "+f"(acc[mt][nt][0]), "+f"(acc[mt][nt][1]),             \
                          "+f"(acc[mt][nt][2]), "+f"(acc[mt][nt][3])              \
                        : "r"(a[mt][0]), "r"(a[mt][1]), "r"(a[mt][2]),            \
                          "r"(a[mt][3]), "r"(b0), "r"(b1));                       \
                }                                                                 \
            }                                                                     \
        }                                                                         \
    }

// Self-loop GEMM: y = X @ loop_w + bias  (initializes y; must run first).
__global__ void __launch_bounds__(256, 2)
gemm_loop_kernel(const float* __restrict__ bias, float* __restrict__ y) {
    extern __shared__ float sm[];
    const int tid = threadIdx.x;
    const int rowbase = blockIdx.x * 128;
    const float* Wp = g_wt + (size_t)NR * DD * DD;

    GEMM_MAINLOOP(rowbase + xr)

#pragma unroll
    for (int mt = 0; mt < 2; mt++) {
        int rA = rowbase + mbase + mt * 16 + g;
#pragma unroll
        for (int nt = 0; nt < 8; nt++) {
            int col = nbase + nt * 8 + 2 * t;
            float ba = __ldg(bias + col), bb = __ldg(bias + col + 1);
            if (rA < NN)
                *(float2*)(y + (size_t)rA * DD + col) =
                    make_float2(acc[mt][nt][0] + ba, acc[mt][nt][1] + bb);
            if (rA + 8 < NN)
                *(float2*)(y + (size_t)(rA + 8) * DD + col) =
                    make_float2(acc[mt][nt][2] + ba, acc[mt][nt][3] + bb);
        }
    }
}

// Data GEMM + fused edge scatter: compute 128 compacted rows of X@W[r], then
// for each incident edge reduce weight*row straight into y.
// Scatter reads only g_spack/g_sw (prebuilt, elist order): 2 broadcast loads +
// 1 smem float4 + 1 red.v4 per edge, unrolled x4 for MLP.
__global__ void __launch_bounds__(256, 2)
gemm_data_kernel(float* __restrict__ y) {
    extern __shared__ float sm[];
    const int tid = threadIdx.x;
    const int j = blockIdx.x;
    if (j >= g_nblk) return;
    int r = NR - 1;
#pragma unroll
    for (int q = NR - 1; q > 0; q--)
        if (j < g_pblk[q]) r = q - 1;
    const int rowbase = j * 128;
    const float* Wp = g_wt + (size_t)r * DD * DD;

    GEMM_MAINLOOP(__ldg(&g_glist[rowbase + xr]))

    // ---- Fused scatter epilogue ----
    __syncthreads();                       // all warps done reading smem buffers
    float* st = sm;                        // 128 x 132 tile (67.6 KB)
#pragma unroll
    for (int mt = 0; mt < 2; mt++) {
        int rloc = mbase + mt * 16 + g;
#pragma unroll
        for (int nt = 0; nt < 8; nt++) {
            int col = nbase + nt * 8 + 2 * t;
            *(float2*)&st[rloc * 132 + col] =
                make_float2(acc[mt][nt][0], acc[mt][nt][1]);
            *(float2*)&st[(rloc + 8) * 132 + col] =
                make_float2(acc[mt][nt][2], acc[mt][nt][3]);
        }
    }
    __syncthreads();

    const int ebeg = __ldg(&g_erow[rowbase]);
    const int eend = __ldg(&g_erow[rowbase + 128]);
    int i = ebeg + warp;
    // Unrolled x4 (stride 8 warps): batch independent loads, then 4 reductions.
    for (; i + 24 < eend; i += 32) {
        int pk[4];
        float wg[4];
#pragma unroll
        for (int u = 0; u < 4; u++) {
            pk[u] = __ldg(&g_spack[i + u * 8]);
            wg[u] = __ldg(&g_sw[i + u * 8]);
        }
#pragma unroll
        for (int u = 0; u < 4; u++) {
            float4 v = *(float4*)&st[(pk[u] & 127) * 132 + lane * 4];
            float* yp = y + (size_t)(pk[u] >> 8) * DD + lane * 4;
            asm volatile("red.global.add.v4.f32 [%0], {%1,%2,%3,%4};"
                         :: "l"(yp), "f"(v.x * wg[u]), "f"(v.y * wg[u]),
                            "f"(v.z * wg[u]), "f"(v.w * wg[u])
                         : "memory");
        }
    }
    for (; i < eend; i += 8) {
        int pk = __ldg(&g_spack[i]);
        float wg = __ldg(&g_sw[i]);
        float4 v = *(float4*)&st[(pk & 127) * 132 + lane * 4];
        float* yp = y + (size_t)(pk >> 8) * DD + lane * 4;
        asm volatile("red.global.add.v4.f32 [%0], {%1,%2,%3,%4};"
                     :: "l"(yp), "f"(v.x * wg), "f"(v.y * wg),
                        "f"(v.z * wg), "f"(v.w * wg)
                     : "memory");
    }
}

// ---------------------------------------------------------------------------
extern "C" void kernel_launch(void* const* d_in, const int* in_sizes, int n_in,
                              void* d_out, int out_size) {
    const float* h    = (const float*)d_in[0];
    const float* norm = (const float*)d_in[1];
    const float* w0   = (const float*)d_in[2];
    const float* b0   = (const float*)d_in[3];
    const float* lw0  = (const float*)d_in[4];
    const float* gw0  = (const float*)d_in[5];
    const float* w1   = (const float*)d_in[6];
    const float* b1   = (const float*)d_in[7];
    const float* lw1  = (const float*)d_in[8];
    const float* gw1  = (const float*)d_in[9];
    const int*   src  = (const int*)d_in[10];
    const int*   dst  = (const int*)d_in[11];
    const int*   rel  = (const int*)d_in[12];
    float* out = (float*)d_out;

    cudaFuncSetAttribute(gemm_loop_kernel,
                         cudaFuncAttributeMaxDynamicSharedMemorySize, GEMM_SMEM);
    cudaFuncSetAttribute(gemm_data_kernel,
                         cudaFuncAttributeMaxDynamicSharedMemorySize, GEMM_SMEM);

    float* h1 = nullptr;
    cudaGetSymbolAddress((void**)&h1, g_h1);
    float* xt = nullptr;
    cudaGetSymbolAddress((void**)&xt, g_xt);
    int* scanp = nullptr;
    cudaGetSymbolAddress((void**)&scanp, g_scan);
    int* flagp = nullptr;
    cudaGetSymbolAddress((void**)&flagp, g_flag);
    int* ecntp = nullptr;
    cudaGetSymbolAddress((void**)&ecntp, g_ecnt);
    int* erowp = nullptr;
    cudaGetSymbolAddress((void**)&erowp, g_erow);

    const int NBF = (NFLAG + 1023) / 1024;           // 782
    const int NBE = (NPADMAX + 1023) / 1024;         // 783
    const int data_grid = NPADMAX / 128;             // 6256 worst case
    const int xcvt_grid = NP * 32 / 256;
    const int wcvt_grid = ((NR + 1) * DD * DD / 4 + 255) / 256;
    const int gate_grid = (NN + 7) / 8;

    // ---- Compaction + CSR prep (shared by both layers)
    zero_kernel<<<NPADMAX / 256, 256>>>();
    mark_kernel<<<NE / 256, 256>>>(src, rel);
    scan1_kernel<<<NBF, 256>>>(flagp, scanp, NFLAG);
    scan2_kernel<<<1, 1024>>>(NBF);
    scan3_kernel<<<(NFLAG + 255) / 256, 256>>>(scanp, NFLAG, -1);
    meta_kernel<<<1, 32>>>();
    build_kernel<<<(NFLAG + 255) / 256, 256>>>();
    cidx_kernel<<<NE / 256, 256>>>(src, rel);
    scan1_kernel<<<NBE, 256>>>(ecntp, erowp, NPADMAX);
    scan2_kernel<<<1, 1024>>>(NBE);
    scan3_kernel<<<(NPADMAX + 255) / 256, 256>>>(erowp, NPADMAX, NE);
    scatter_kernel<<<NE / 256, 256>>>(dst);

    // ---- Layer 0
    xcvt_kernel<<<xcvt_grid, 256>>>(h, 0);
    wcvt_kernel<<<wcvt_grid, 256>>>(w0, lw0);
    gate_kernel<<<gate_grid, 128>>>(xt, gw0);
    ew_kernel<<<NE / 256, 256>>>(src, rel, norm);
    gemm_loop_kernel<<<NBLK, 256, GEMM_SMEM>>>(b0, h1);
    gemm_data_kernel<<<data_grid, 256, GEMM_SMEM>>>(h1);

    // ---- Layer 1 (relu fused into xcvt)
    xcvt_kernel<<<xcvt_grid, 256>>>(h1, 1);
    wcvt_kernel<<<wcvt_grid, 256>>>(w1, lw1);
    gate_kernel<<<gate_grid, 128>>>(xt, gw1);
    ew_kernel<<<NE / 256, 256>>>(src, rel, norm);
    gemm_loop_kernel<<<NBLK, 256, GEMM_SMEM>>>(b1, out);
    gemm_data_kernel<<<data_grid, 256, GEMM_SMEM>>>(out);
}

// round 12
// speedup vs baseline: 1.8350x; 1.0248x over previous
#include <cuda_runtime.h>
#include <cstdint>

#define NN 50000
#define NE 800000
#define NR 16
#define DD 128
#define NP 50048                 // NN padded to 128 (391 blocks)
#define NBLK 391
#define NFLAG (NR * NN)          // 800000 (r,s) pairs
#define NPADMAX (NR * NP)        // 800768 max padded compact rows

// Scratch (device globals; no dynamic allocation allowed).
__device__ float g_sgate[(size_t)NR * NN];         // 3.2 MB gate table
__device__ float g_h1[(size_t)NN * DD];            // 25.6 MB layer-0 output (pre-relu)
__device__ float g_xt[(size_t)NP * DD];            // 25.6 MB tf32-rounded X (zero-padded)
__device__ float g_wt[(size_t)(NR + 1) * DD * DD]; // 1.1 MB tf32-rounded W^T (n-major)
// Compaction + CSR scratch
__device__ int g_flag[NFLAG];
__device__ int g_scan[NFLAG];
__device__ int g_bsum[1024];
__device__ int g_glist[NPADMAX];
__device__ int g_cidx[NE];
__device__ int g_ecnt[NPADMAX];
__device__ int g_efill[NPADMAX];
__device__ int g_erow[NPADMAX + 1];
__device__ int g_elist[NE];      // edge ids sorted by compact row
__device__ int g_spack[NE];      // (dst << 8) | local_row, in elist order
__device__ float g_sw[NE];       // per-layer edge weight (norm * gate), elist order
__device__ int g_relstart[NR];
__device__ int g_padoff[NR + 1];
__device__ int g_pblk[NR + 1];
__device__ int g_nblk;

__device__ __forceinline__ uint32_t f2tf32(float f) {
    uint32_t u;
    asm("cvt.rna.tf32.f32 %0, %1;" : "=r"(u) : "f"(f));
    return u;
}
__device__ __forceinline__ uint32_t sptr(const void* p) {
    return (uint32_t)__cvta_generic_to_shared(p);
}
#define LDSM4(r0, r1, r2, r3, addr)                                          \
    asm volatile("ldmatrix.sync.aligned.m8n8.x4.shared.b16 {%0,%1,%2,%3}, [%4];" \
                 : "=r"(r0), "=r"(r1), "=r"(r2), "=r"(r3) : "r"(addr))

// ---------------------------------------------------------------------------
// Compaction + CSR prep (once per call)
// ---------------------------------------------------------------------------
__global__ void zero_kernel() {
    int i = blockIdx.x * 256 + threadIdx.x;          // grid covers NPADMAX exactly
    g_glist[i] = 0;
    g_ecnt[i] = 0;
    g_efill[i] = 0;
    if (i < NFLAG) g_flag[i] = 0;
}
__global__ void mark_kernel(const int* __restrict__ src, const int* __restrict__ rel) {
    int e = blockIdx.x * 256 + threadIdx.x;
    g_flag[__ldg(rel + e) * NN + __ldg(src + e)] = 1;
}
// Block-local exclusive scan (1024 elems/block of 256 threads) + block sums.
__global__ void scan1_kernel(const int* __restrict__ in, int* __restrict__ out, int n) {
    __shared__ int sd[256];
    const int tid = threadIdx.x;
    int base = blockIdx.x * 1024 + tid * 4;
    int f[4], s = 0;
#pragma unroll
    for (int j = 0; j < 4; j++) {
        f[j] = (base + j < n) ? in[base + j] : 0;
        s += f[j];
    }
    sd[tid] = s;
    __syncthreads();
#pragma unroll
    for (int off = 1; off < 256; off <<= 1) {
        int v = (tid >= off) ? sd[tid - off] : 0;
        __syncthreads();
        sd[tid] += v;
        __syncthreads();
    }
    int run = sd[tid] - s;                           // block-local exclusive
#pragma unroll
    for (int j = 0; j < 4; j++) {
        if (base + j < n) out[base + j] = run;
        run += f[j];
    }
    if (tid == 255) g_bsum[blockIdx.x] = sd[255];
}
__global__ void scan2_kernel(int nblocks) {          // one block, 1024 threads
    __shared__ int sd[1024];
    const int tid = threadIdx.x;
    int v0 = (tid < nblocks) ? g_bsum[tid] : 0;
    sd[tid] = v0;
    __syncthreads();
#pragma unroll
    for (int off = 1; off < 1024; off <<= 1) {
        int v = (tid >= off) ? sd[tid - off] : 0;
        __syncthreads();
        sd[tid] += v;
        __syncthreads();
    }
    if (tid < nblocks) g_bsum[tid] = sd[tid] - v0;   // exclusive
}
__global__ void scan3_kernel(int* __restrict__ out, int n, int tail) {
    int i = blockIdx.x * 256 + threadIdx.x;
    if (i < n) out[i] += g_bsum[i >> 10];
    if (i == 0 && tail >= 0) out[n] = tail;
}
__global__ void meta_kernel() {
    if (threadIdx.x != 0) return;
    int total = g_scan[NFLAG - 1] + g_flag[NFLAG - 1];
    int pad = 0;
    for (int r = 0; r < NR; r++) {
        int st = g_scan[r * NN];
        int nx = (r < NR - 1) ? g_scan[(r + 1) * NN] : total;
        g_relstart[r] = st;
        g_padoff[r] = pad;
        g_pblk[r] = pad >> 7;
        pad += ((nx - st + 127) & ~127);
    }
    g_padoff[NR] = pad;
    g_pblk[NR] = pad >> 7;
    g_nblk = pad >> 7;
}
__global__ void build_kernel() {
    int p = blockIdx.x * 256 + threadIdx.x;          // grid covers NFLAG
    if (p >= NFLAG || !g_flag[p]) return;
    int r = p / NN, s = p - r * NN;
    g_glist[g_padoff[r] + g_scan[p] - g_relstart[r]] = s;
}
__global__ void cidx_kernel(const int* __restrict__ src, const int* __restrict__ rel) {
    int e = blockIdx.x * 256 + threadIdx.x;
    int r = __ldg(rel + e), s = __ldg(src + e);
    int c = g_padoff[r] + g_scan[r * NN + s] - g_relstart[r];
    g_cidx[e] = c;
    atomicAdd(&g_ecnt[c], 1);
}
__global__ void scatter_kernel(const int* __restrict__ dst) {
    int e = blockIdx.x * 256 + threadIdx.x;          // grid covers NE
    int c = g_cidx[e];
    int pos = g_erow[c] + atomicAdd(&g_efill[c], 1);
    g_elist[pos] = e;
    g_spack[pos] = (__ldg(dst + e) << 8) | (c & 127);
}
// Per-layer edge weights in elist order: g_sw[i] = norm[e] * gate(rel[e], src[e]).
__global__ void ew_kernel(const int* __restrict__ src, const int* __restrict__ rel,
                          const float* __restrict__ norm) {
    int i = blockIdx.x * 256 + threadIdx.x;          // grid covers NE
    int e = __ldg(&g_elist[i]);
    int r = __ldg(rel + e), s = __ldg(src + e);
    g_sw[i] = __ldg(norm + e) * __ldg(&g_sgate[(size_t)r * NN + s]);
}

// ---------------------------------------------------------------------------
// X pre-pass: xt = tf32_rna( relu?(x) ), zero-padded to NP rows.
// ---------------------------------------------------------------------------
__global__ void xcvt_kernel(const float* __restrict__ x, int relu) {
    int i = blockIdx.x * 256 + threadIdx.x;          // float4 index, grid covers NP*32
    int m = i >> 5, c = i & 31;
    float4 v = make_float4(0.f, 0.f, 0.f, 0.f);
    if (m < NN) v = __ldg((const float4*)x + (size_t)m * 32 + c);
    if (relu) {
        v.x = fmaxf(v.x, 0.f); v.y = fmaxf(v.y, 0.f);
        v.z = fmaxf(v.z, 0.f); v.w = fmaxf(v.w, 0.f);
    }
    uint4 o;
    o.x = f2tf32(v.x); o.y = f2tf32(v.y); o.z = f2tf32(v.z); o.w = f2tf32(v.w);
    ((uint4*)g_xt)[i] = o;
}

// W pre-pass (TRANSPOSED): g_wt[r][n][k] = tf32( W[r][k][n] ); r=16 -> loop_w.
// n-major rows enable ldmatrix B-fragment loads in the GEMM.
__global__ void wcvt_kernel(const float* __restrict__ Wr,
                            const float* __restrict__ loopw) {
    int i = blockIdx.x * 256 + threadIdx.x;          // float4 idx, grid = 17*4096/256
    int r = i >> 12, rem = i & 4095;
    int n = rem >> 5, kq = rem & 31, k = kq * 4;
    const float* src = (r < NR) ? (Wr + (size_t)r * DD * DD) : loopw;
    uint4 o;
    o.x = f2tf32(__ldg(src + (size_t)(k + 0) * DD + n));
    o.y = f2tf32(__ldg(src + (size_t)(k + 1) * DD + n));
    o.z = f2tf32(__ldg(src + (size_t)(k + 2) * DD + n));
    o.w = f2tf32(__ldg(src + (size_t)(k + 3) * DD + n));
    ((uint4*)g_wt)[i] = o;
}

// ---------------------------------------------------------------------------
// Gate table: g_sgate[r][n] = sigmoid( x[n] . gate_w[r] ).
// ---------------------------------------------------------------------------
__global__ void gate_kernel(const float* __restrict__ x,
                            const float* __restrict__ gw) {
    __shared__ float sx[8][132];
    __shared__ float sg[16][132];
    const int tid = threadIdx.x;
    const int nb = blockIdx.x * 8;
#pragma unroll
    for (int i = 0; i < 4; i++) {
        int l = tid + i * 128;
        int r = l >> 5, c = l & 31;
        *(float4*)&sg[r][c * 4] = __ldg((const float4*)gw + r * 32 + c);
    }
#pragma unroll
    for (int i = 0; i < 2; i++) {
        int l = tid + i * 128;
        int n = l >> 5, c = l & 31;
        float4 v = make_float4(0.f, 0.f, 0.f, 0.f);
        if (nb + n < NN) v = __ldg((const float4*)x + (size_t)(nb + n) * 32 + c);
        *(float4*)&sx[n][c * 4] = v;
    }
    __syncthreads();
    const int node = tid >> 4, rel = tid & 15;
    float d = 0.f;
#pragma unroll
    for (int k = 0; k < 32; k++) {
        float4 a = *(float4*)&sx[node][k * 4];
        float4 g = *(float4*)&sg[rel][k * 4];
        d += a.x * g.x + a.y * g.y + a.z * g.z + a.w * g.w;
    }
    if (nb + node < NN)
        g_sgate[(size_t)rel * NN + nb + node] = 1.f / (1.f + __expf(-d));
}

// ---------------------------------------------------------------------------
// Shared GEMM machinery: 128x128x128 tf32 tile, cp.async 3-buffer pipeline,
// ldmatrix.x4 fragment loads (A m-major, B n-major; both stride 36 floats ->
// 8-row ldmatrix phases advance 4 banks/row: conflict-free).
// ---------------------------------------------------------------------------
#define XSTR 36
#define XS (128 * XSTR)          // 4608 floats per stage (A)
#define WS (128 * XSTR)          // 4608 floats per stage (B, n-major)
#define NSTG 3
#define GEMM_SMEM (NSTG * (XS + WS) * 4)    // 110,592 B -> 2 CTAs = 221 KB/SM

#define GEMM_MAINLOOP(GA_EXPR)                                                    \
    float* sX = sm;                                                               \
    float* sW = sm + NSTG * XS;                                                   \
    int ga[4];                                                                    \
    _Pragma("unroll")                                                             \
    for (int i = 0; i < 4; i++) {                                                 \
        int xr = (tid >> 3) + i * 32;                                             \
        ga[i] = (GA_EXPR);                                                        \
    }                                                                             \
    const int xc4 = tid & 7;                                                      \
    float acc[2][8][4];                                                           \
    _Pragma("unroll")                                                             \
    for (int mt = 0; mt < 2; mt++)                                                \
        _Pragma("unroll")                                                         \
        for (int nt = 0; nt < 8; nt++)                                            \
            _Pragma("unroll")                                                     \
            for (int q = 0; q < 4; q++) acc[mt][nt][q] = 0.f;                     \
    auto issue = [&](int s, int buf) {                                            \
        _Pragma("unroll")                                                         \
        for (int i = 0; i < 4; i++) {                                             \
            const char* srcp = (const char*)g_xt + (size_t)ga[i] * 512            \
                               + s * 128 + xc4 * 16;                              \
            uint32_t dstp = sptr(sX + buf * XS + ((tid >> 3) + i * 32) * XSTR     \
                                 + xc4 * 4);                                      \
            asm volatile("cp.async.cg.shared.global [%0], [%1], 16;"              \
                         :: "r"(dstp), "l"(srcp) : "memory");                     \
        }                                                                         \
        _Pragma("unroll")                                                         \
        for (int i = 0; i < 4; i++) {                                             \
            int wrow = (tid >> 3) + i * 32;                                       \
            const float4* srcp = (const float4*)Wp + (size_t)wrow * 32            \
                                 + s * 8 + xc4;                                   \
            uint32_t dstp = sptr(sW + buf * WS + wrow * XSTR + xc4 * 4);          \
            asm volatile("cp.async.cg.shared.global [%0], [%1], 16;"              \
                         :: "r"(dstp), "l"(srcp) : "memory");                     \
        }                                                                         \
    };                                                                            \
    issue(0, 0);                                                                  \
    asm volatile("cp.async.commit_group;" ::: "memory");                          \
    issue(1, 1);                                                                  \
    asm volatile("cp.async.commit_group;" ::: "memory");                          \
    const int warp = tid >> 5, lane = tid & 31;                                   \
    const int g = lane >> 2, t = lane & 3;                                        \
    const int mbase = (warp >> 1) * 32;                                           \
    const int nbase = (warp & 1) * 64;                                            \
    /* ldmatrix per-lane source rows: tile = lane>>3, tile row = lane&7 */        \
    const int aRow = mbase + (lane & 7) + ((lane >> 3) & 1) * 8;                  \
    const int aK   = (lane >> 4) * 4;                                             \
    const int bRow = nbase + (lane & 7) + ((lane >> 4) & 1) * 8;                  \
    const int bK   = ((lane >> 3) & 1) * 4;                                       \
    _Pragma("unroll")                                                             \
    for (int s = 0; s < 4; s++) {                                                 \
        if (s < 3) asm volatile("cp.async.wait_group 1;" ::: "memory");           \
        else       asm volatile("cp.async.wait_group 0;" ::: "memory");           \
        __syncthreads();                                                          \
        if (s + 2 < 4) {                                                          \
            issue(s + 2, (s + 2) % 3);                                            \
            asm volatile("cp.async.commit_group;" ::: "memory");                  \
        }                                                                         \
        const uint32_t sxb = sptr(sX + (s % 3) * XS);                             \
        const uint32_t swb = sptr(sW + (s % 3) * WS);                             \
        _Pragma("unroll")                                                         \
        for (int kk = 0; kk < 4; kk++) {                                          \
            const int k0 = kk * 8;                                                \
            uint32_t a[2][4];                                                     \
            _Pragma("unroll")                                                     \
            for (int mt = 0; mt < 2; mt++) {                                      \
                uint32_t ad = sxb + ((aRow + mt * 16) * XSTR + k0 + aK) * 4;      \
                LDSM4(a[mt][0], a[mt][1], a[mt][2], a[mt][3], ad);                \
            }                                                                     \
            _Pragma("unroll")                                                     \
            for (int half = 0; half < 2; half++) {                                \
                uint32_t b[4][2];                                                 \
                _Pragma("unroll")                                                 \
                for (int pp = 0; pp < 2; pp++) {                                  \
                    int p = half * 2 + pp;                                        \
                    uint32_t bd = swb + ((bRow + p * 16) * XSTR + k0 + bK) * 4;   \
                    LDSM4(b[pp * 2][0], b[pp * 2][1],                             \
                          b[pp * 2 + 1][0], b[pp * 2 + 1][1], bd);                \
                }                                                                 \
                _Pragma("unroll")                                                 \
                for (int ntl = 0; ntl < 4; ntl++) {                               \
                    int nt = half * 4 + ntl;                                      \
                    _Pragma("unroll")                                             \
                    for (int mt = 0; mt < 2; mt++) {                              \
                        asm volatile(                                             \
                            "mma.sync.aligned.m16n8k8.row.col.f32.tf32.tf32.f32 " \
                            "{%0,%1,%2,%3}, {%4,%5,%6,%7}, {%8,%9}, "             \
                            "{%0,%1,%2,%3};\n"                                    \
                            : "+f"(acc[mt][nt][0]), "+f"(acc[mt][nt][1]),         \
                              "+f"(acc[mt][nt][2]), "+f"(acc[mt][nt][3])          \
                            : "r"(a[mt][0]), "r"(a[mt][1]), "r"(a[mt][2]),        \
                              "r"(a[mt][3]), "r"(b[ntl][0]), "r"(b[ntl][1]));     \
                    }                                                             \
                }                                                                 \
            }                                                                     \
        }                                                                         \
    }

// Self-loop GEMM: y = X @ loop_w + bias  (initializes y; must run first).
__global__ void __launch_bounds__(256, 2)
gemm_loop_kernel(const float* __restrict__ bias, float* __restrict__ y) {
    extern __shared__ float sm[];
    const int tid = threadIdx.x;
    const int rowbase = blockIdx.x * 128;
    const float* Wp = g_wt + (size_t)NR * DD * DD;

    GEMM_MAINLOOP(rowbase + xr)

#pragma unroll
    for (int mt = 0; mt < 2; mt++) {
        int rA = rowbase + mbase + mt * 16 + g;
#pragma unroll
        for (int nt = 0; nt < 8; nt++) {
            int col = nbase + nt * 8 + 2 * t;
            float ba = __ldg(bias + col), bb = __ldg(bias + col + 1);
            if (rA < NN)
                *(float2*)(y + (size_t)rA * DD + col) =
                    make_float2(acc[mt][nt][0] + ba, acc[mt][nt][1] + bb);
            if (rA + 8 < NN)
                *(float2*)(y + (size_t)(rA + 8) * DD + col) =
                    make_float2(acc[mt][nt][2] + ba, acc[mt][nt][3] + bb);
        }
    }
}

// Data GEMM + fused edge scatter: compute 128 compacted rows of X@W[r], then
// for each incident edge reduce weight*row straight into y.
__global__ void __launch_bounds__(256, 2)
gemm_data_kernel(float* __restrict__ y) {
    extern __shared__ float sm[];
    const int tid = threadIdx.x;
    const int j = blockIdx.x;
    if (j >= g_nblk) return;
    int r = NR - 1;
#pragma unroll
    for (int q = NR - 1; q > 0; q--)
        if (j < g_pblk[q]) r = q - 1;
    const int rowbase = j * 128;
    const float* Wp = g_wt + (size_t)r * DD * DD;

    GEMM_MAINLOOP(__ldg(&g_glist[rowbase + xr]))

    // ---- Fused scatter epilogue ----
    __syncthreads();                       // all warps done reading smem buffers
    float* st = sm;                        // 128 x 132 tile (67.6 KB)
#pragma unroll
    for (int mt = 0; mt < 2; mt++) {
        int rloc = mbase + mt * 16 + g;
#pragma unroll
        for (int nt = 0; nt < 8; nt++) {
            int col = nbase + nt * 8 + 2 * t;
            *(float2*)&st[rloc * 132 + col] =
                make_float2(acc[mt][nt][0], acc[mt][nt][1]);
            *(float2*)&st[(rloc + 8) * 132 + col] =
                make_float2(acc[mt][nt][2], acc[mt][nt][3]);
        }
    }
    __syncthreads();

    const int ebeg = __ldg(&g_erow[rowbase]);
    const int eend = __ldg(&g_erow[rowbase + 128]);
    int i = ebeg + warp;
    // Unrolled x4 (stride 8 warps): batch independent loads, then 4 reductions.
    for (; i + 24 < eend; i += 32) {
        int pk[4];
        float wg[4];
#pragma unroll
        for (int u = 0; u < 4; u++) {
            pk[u] = __ldg(&g_spack[i + u * 8]);
            wg[u] = __ldg(&g_sw[i + u * 8]);
        }
#pragma unroll
        for (int u = 0; u < 4; u++) {
            float4 v = *(float4*)&st[(pk[u] & 127) * 132 + lane * 4];
            float* yp = y + (size_t)(pk[u] >> 8) * DD + lane * 4;
            asm volatile("red.global.add.v4.f32 [%0], {%1,%2,%3,%4};"
                         :: "l"(yp), "f"(v.x * wg[u]), "f"(v.y * wg[u]),
                            "f"(v.z * wg[u]), "f"(v.w * wg[u])
                         : "memory");
        }
    }
    for (; i < eend; i += 8) {
        int pk = __ldg(&g_spack[i]);
        float wg = __ldg(&g_sw[i]);
        float4 v = *(float4*)&st[(pk & 127) * 132 + lane * 4];
        float* yp = y + (size_t)(pk >> 8) * DD + lane * 4;
        asm volatile("red.global.add.v4.f32 [%0], {%1,%2,%3,%4};"
                     :: "l"(yp), "f"(v.x * wg), "f"(v.y * wg),
                        "f"(v.z * wg), "f"(v.w * wg)
                     : "memory");
    }
}

// ---------------------------------------------------------------------------
extern "C" void kernel_launch(void* const* d_in, const int* in_sizes, int n_in,
                              void* d_out, int out_size) {
    const float* h    = (const float*)d_in[0];
    const float* norm = (const float*)d_in[1];
    const float* w0   = (const float*)d_in[2];
    const float* b0   = (const float*)d_in[3];
    const float* lw0  = (const float*)d_in[4];
    const float* gw0  = (const float*)d_in[5];
    const float* w1   = (const float*)d_in[6];
    const float* b1   = (const float*)d_in[7];
    const float* lw1  = (const float*)d_in[8];
    const float* gw1  = (const float*)d_in[9];
    const int*   src  = (const int*)d_in[10];
    const int*   dst  = (const int*)d_in[11];
    const int*   rel  = (const int*)d_in[12];
    float* out = (float*)d_out;

    cudaFuncSetAttribute(gemm_loop_kernel,
                         cudaFuncAttributeMaxDynamicSharedMemorySize, GEMM_SMEM);
    cudaFuncSetAttribute(gemm_data_kernel,
                         cudaFuncAttributeMaxDynamicSharedMemorySize, GEMM_SMEM);

    float* h1 = nullptr;
    cudaGetSymbolAddress((void**)&h1, g_h1);
    float* xt = nullptr;
    cudaGetSymbolAddress((void**)&xt, g_xt);
    int* scanp = nullptr;
    cudaGetSymbolAddress((void**)&scanp, g_scan);
    int* flagp = nullptr;
    cudaGetSymbolAddress((void**)&flagp, g_flag);
    int* ecntp = nullptr;
    cudaGetSymbolAddress((void**)&ecntp, g_ecnt);
    int* erowp = nullptr;
    cudaGetSymbolAddress((void**)&erowp, g_erow);

    const int NBF = (NFLAG + 1023) / 1024;           // 782
    const int NBE = (NPADMAX + 1023) / 1024;         // 783
    const int data_grid = NPADMAX / 128;             // 6256 worst case
    const int xcvt_grid = NP * 32 / 256;
    const int wcvt_grid = (NR + 1) * 128 * 32 / 256; // 272 (exact)
    const int gate_grid = (NN + 7) / 8;

    // ---- Compaction + CSR prep (shared by both layers)
    zero_kernel<<<NPADMAX / 256, 256>>>();
    mark_kernel<<<NE / 256, 256>>>(src, rel);
    scan1_kernel<<<NBF, 256>>>(flagp, scanp, NFLAG);
    scan2_kernel<<<1, 1024>>>(NBF);
    scan3_kernel<<<(NFLAG + 255) / 256, 256>>>(scanp, NFLAG, -1);
    meta_kernel<<<1, 32>>>();
    build_kernel<<<(NFLAG + 255) / 256, 256>>>();
    cidx_kernel<<<NE / 256, 256>>>(src, rel);
    scan1_kernel<<<NBE, 256>>>(ecntp, erowp, NPADMAX);
    scan2_kernel<<<1, 1024>>>(NBE);
    scan3_kernel<<<(NPADMAX + 255) / 256, 256>>>(erowp, NPADMAX, NE);
    scatter_kernel<<<NE / 256, 256>>>(dst);

    // ---- Layer 0
    xcvt_kernel<<<xcvt_grid, 256>>>(h, 0);
    wcvt_kernel<<<wcvt_grid, 256>>>(w0, lw0);
    gate_kernel<<<gate_grid, 128>>>(xt, gw0);
    ew_kernel<<<NE / 256, 256>>>(src, rel, norm);
    gemm_loop_kernel<<<NBLK, 256, GEMM_SMEM>>>(b0, h1);
    gemm_data_kernel<<<data_grid, 256, GEMM_SMEM>>>(h1);

    // ---- Layer 1 (relu fused into xcvt)
    xcvt_kernel<<<xcvt_grid, 256>>>(h1, 1);
    wcvt_kernel<<<wcvt_grid, 256>>>(w1, lw1);
    gate_kernel<<<gate_grid, 128>>>(xt, gw1);
    ew_kernel<<<NE / 256, 256>>>(src, rel, norm);
    gemm_loop_kernel<<<NBLK, 256, GEMM_SMEM>>>(b1, out);
    gemm_data_kernel<<<data_grid, 256, GEMM_SMEM>>>(out);
}

// round 13
// speedup vs baseline: 1.8720x; 1.0202x over previous
#include <cuda_runtime.h>
#include <cstdint>

#define NN 50000
#define NE 800000
#define NR 16
#define DD 128
#define NP 50048                 // NN padded to 128 (391 blocks)
#define NBLK 391
#define NFLAG (NR * NN)          // 800000 (r,s) pairs ( == NE )
#define NPADMAX (NR * NP)        // 800768 max padded compact rows

// Scratch (device globals; no dynamic allocation allowed).
__device__ float g_sgate[(size_t)NR * NN];         // 3.2 MB gate table
__device__ float g_h1[(size_t)NN * DD];            // 25.6 MB layer-0 output (pre-relu)
__device__ float g_xt[(size_t)NP * DD];            // 25.6 MB tf32-rounded X (zero-padded)
__device__ float g_wt[(size_t)(NR + 1) * DD * DD]; // 1.1 MB tf32-rounded W^T (n-major)
// Compaction + CSR scratch
__device__ int g_flag[NFLAG];
__device__ int g_scan[NFLAG];
__device__ int g_bsum[1024];
__device__ int g_glist[NPADMAX];
__device__ int g_cidx[NE];
__device__ int g_ecnt[NPADMAX];
__device__ int g_efill[NPADMAX];
__device__ int g_erow[NPADMAX + 1];
__device__ int g_spack[NE];      // (dst << 8) | local_row, row-sorted order
__device__ float g_snorm[NE];    // norm[e], row-sorted order (layer-invariant)
__device__ int g_relstart[NR];
__device__ int g_padoff[NR + 1];
__device__ int g_pblk[NR + 1];
__device__ int g_nblk;

__device__ __forceinline__ uint32_t f2tf32(float f) {
    uint32_t u;
    asm("cvt.rna.tf32.f32 %0, %1;" : "=r"(u) : "f"(f));
    return u;
}
__device__ __forceinline__ uint32_t sptr(const void* p) {
    return (uint32_t)__cvta_generic_to_shared(p);
}
#define LDSM4(r0, r1, r2, r3, addr)                                          \
    asm volatile("ldmatrix.sync.aligned.m8n8.x4.shared.b16 {%0,%1,%2,%3}, [%4];" \
                 : "=r"(r0), "=r"(r1), "=r"(r2), "=r"(r3) : "r"(addr))

// ---------------------------------------------------------------------------
// Compaction + CSR prep (once per call)
// ---------------------------------------------------------------------------
__global__ void zero_kernel() {
    int i = blockIdx.x * 256 + threadIdx.x;          // grid covers NPADMAX exactly
    g_glist[i] = 0;
    g_ecnt[i] = 0;
    g_efill[i] = 0;
    if (i < NFLAG) g_flag[i] = 0;
}
__global__ void mark_kernel(const int* __restrict__ src, const int* __restrict__ rel) {
    int e = blockIdx.x * 256 + threadIdx.x;
    g_flag[__ldg(rel + e) * NN + __ldg(src + e)] = 1;
}
// Block-local exclusive scan (1024 elems/block of 256 threads) + block sums.
__global__ void scan1_kernel(const int* __restrict__ in, int* __restrict__ out, int n) {
    __shared__ int sd[256];
    const int tid = threadIdx.x;
    int base = blockIdx.x * 1024 + tid * 4;
    int f[4], s = 0;
#pragma unroll
    for (int j = 0; j < 4; j++) {
        f[j] = (base + j < n) ? in[base + j] : 0;
        s += f[j];
    }
    sd[tid] = s;
    __syncthreads();
#pragma unroll
    for (int off = 1; off < 256; off <<= 1) {
        int v = (tid >= off) ? sd[tid - off] : 0;
        __syncthreads();
        sd[tid] += v;
        __syncthreads();
    }
    int run = sd[tid] - s;                           // block-local exclusive
#pragma unroll
    for (int j = 0; j < 4; j++) {
        if (base + j < n) out[base + j] = run;
        run += f[j];
    }
    if (tid == 255) g_bsum[blockIdx.x] = sd[255];
}
__global__ void scan2_kernel(int nblocks) {          // one block, 1024 threads
    __shared__ int sd[1024];
    const int tid = threadIdx.x;
    int v0 = (tid < nblocks) ? g_bsum[tid] : 0;
    sd[tid] = v0;
    __syncthreads();
#pragma unroll
    for (int off = 1; off < 1024; off <<= 1) {
        int v = (tid >= off) ? sd[tid - off] : 0;
        __syncthreads();
        sd[tid] += v;
        __syncthreads();
    }
    if (tid < nblocks) g_bsum[tid] = sd[tid] - v0;   // exclusive
}
__global__ void scan3_kernel(int* __restrict__ out, int n, int tail) {
    int i = blockIdx.x * 256 + threadIdx.x;
    if (i < n) out[i] += g_bsum[i >> 10];
    if (i == 0 && tail >= 0) out[n] = tail;
}
__global__ void meta_kernel() {
    if (threadIdx.x != 0) return;
    int total = g_scan[NFLAG - 1] + g_flag[NFLAG - 1];
    int pad = 0;
    for (int r = 0; r < NR; r++) {
        int st = g_scan[r * NN];
        int nx = (r < NR - 1) ? g_scan[(r + 1) * NN] : total;
        g_relstart[r] = st;
        g_padoff[r] = pad;
        g_pblk[r] = pad >> 7;
        pad += ((nx - st + 127) & ~127);
    }
    g_padoff[NR] = pad;
    g_pblk[NR] = pad >> 7;
    g_nblk = pad >> 7;
}
// Merged build (pair domain) + cidx (edge domain): NFLAG == NE == 800000.
__global__ void buildcidx_kernel(const int* __restrict__ src,
                                 const int* __restrict__ rel) {
    int i = blockIdx.x * 256 + threadIdx.x;          // grid covers NE exactly
    // build: scatter node id for used pair i
    if (g_flag[i]) {
        int pr = i / NN, ps = i - pr * NN;
        g_glist[g_padoff[pr] + g_scan[i] - g_relstart[pr]] = ps;
    }
    // cidx: compact row index for edge i + per-row histogram
    int r = __ldg(rel + i), s = __ldg(src + i);
    int c = g_padoff[r] + g_scan[r * NN + s] - g_relstart[r];
    g_cidx[i] = c;
    atomicAdd(&g_ecnt[c], 1);
}
__global__ void scatter_kernel(const int* __restrict__ dst,
                               const float* __restrict__ norm) {
    int e = blockIdx.x * 256 + threadIdx.x;          // grid covers NE
    int c = g_cidx[e];
    int pos = g_erow[c] + atomicAdd(&g_efill[c], 1);
    g_spack[pos] = (__ldg(dst + e) << 8) | (c & 127);
    g_snorm[pos] = __ldg(norm + e);
}

// ---------------------------------------------------------------------------
// Merged X pass: one read of x produces BOTH the tf32-rounded (relu'd) xt
// AND the 16-relation gate table. 128 threads = 8 nodes.
// ---------------------------------------------------------------------------
__global__ void gatex_kernel(const float* __restrict__ x,
                             const float* __restrict__ gw, int relu) {
    __shared__ float sx[8][132];
    __shared__ float sg[16][132];
    const int tid = threadIdx.x;
    const int nb = blockIdx.x * 8;                   // grid = NP/8 (covers padding)
#pragma unroll
    for (int i = 0; i < 4; i++) {
        int l = tid + i * 128;
        int r = l >> 5, c = l & 31;
        *(float4*)&sg[r][c * 4] = __ldg((const float4*)gw + r * 32 + c);
    }
#pragma unroll
    for (int i = 0; i < 2; i++) {
        int l = tid + i * 128;
        int n = l >> 5, c = l & 31;
        float4 v = make_float4(0.f, 0.f, 0.f, 0.f);
        if (nb + n < NN) v = __ldg((const float4*)x + (size_t)(nb + n) * 32 + c);
        if (relu) {
            v.x = fmaxf(v.x, 0.f); v.y = fmaxf(v.y, 0.f);
            v.z = fmaxf(v.z, 0.f); v.w = fmaxf(v.w, 0.f);
        }
        *(float4*)&sx[n][c * 4] = v;
    }
    __syncthreads();
    // xt store (tf32-rounded), covers padded rows with zeros
#pragma unroll
    for (int i = 0; i < 2; i++) {
        int l = tid + i * 128;
        int n = l >> 5, c = l & 31;
        float4 v = *(float4*)&sx[n][c * 4];
        uint4 o;
        o.x = f2tf32(v.x); o.y = f2tf32(v.y); o.z = f2tf32(v.z); o.w = f2tf32(v.w);
        ((uint4*)g_xt)[(size_t)(nb + n) * 32 + c] = o;
    }
    // gate dot products
    const int node = tid >> 4, rel = tid & 15;
    float d = 0.f;
#pragma unroll
    for (int k = 0; k < 32; k++) {
        float4 a = *(float4*)&sx[node][k * 4];
        float4 g = *(float4*)&sg[rel][k * 4];
        d += a.x * g.x + a.y * g.y + a.z * g.z + a.w * g.w;
    }
    if (nb + node < NN)
        g_sgate[(size_t)rel * NN + nb + node] = 1.f / (1.f + __expf(-d));
}

// W pre-pass (TRANSPOSED): g_wt[r][n][k] = tf32( W[r][k][n] ); r=16 -> loop_w.
__global__ void wcvt_kernel(const float* __restrict__ Wr,
                            const float* __restrict__ loopw) {
    int i = blockIdx.x * 256 + threadIdx.x;          // float4 idx, grid = 17*4096/256
    int r = i >> 12, rem = i & 4095;
    int n = rem >> 5, kq = rem & 31, k = kq * 4;
    const float* src = (r < NR) ? (Wr + (size_t)r * DD * DD) : loopw;
    uint4 o;
    o.x = f2tf32(__ldg(src + (size_t)(k + 0) * DD + n));
    o.y = f2tf32(__ldg(src + (size_t)(k + 1) * DD + n));
    o.z = f2tf32(__ldg(src + (size_t)(k + 2) * DD + n));
    o.w = f2tf32(__ldg(src + (size_t)(k + 3) * DD + n));
    ((uint4*)g_wt)[i] = o;
}

// ---------------------------------------------------------------------------
// Unified GEMM: 128x128x128 tf32 tile, cp.async 3-buffer pipeline, ldmatrix
// fragment loads. Block j < NBLK: self-loop tile (y += X@loop_w + bias via
// red.add; y pre-zeroed). Block j >= NBLK: data tile + fused edge scatter.
// ---------------------------------------------------------------------------
#define XSTR 36
#define XS (128 * XSTR)
#define WS (128 * XSTR)
#define NSTG 3
#define GEMM_SMEM (NSTG * (XS + WS) * 4)    // 110,592 B -> 2 CTAs = 221 KB/SM

__global__ void __launch_bounds__(256, 2)
gemm_all_kernel(const float* __restrict__ bias, float* __restrict__ y) {
    extern __shared__ float sm[];
    float* sX = sm;
    float* sW = sm + NSTG * XS;
    const int tid = threadIdx.x;
    const int j = blockIdx.x;
    const bool is_loop = j < NBLK;
    int r, rowbase;
    if (is_loop) {
        r = NR;
        rowbase = j * 128;
    } else {
        int jj = j - NBLK;
        if (jj >= g_nblk) return;
        r = NR - 1;
#pragma unroll
        for (int q = NR - 1; q > 0; q--)
            if (jj < g_pblk[q]) r = q - 1;
        rowbase = jj * 128;
    }
    const float* Wp = g_wt + (size_t)r * DD * DD;

    int ga[4];
#pragma unroll
    for (int i = 0; i < 4; i++) {
        int xr = (tid >> 3) + i * 32;
        ga[i] = is_loop ? (rowbase + xr) : __ldg(&g_glist[rowbase + xr]);
    }
    const int xc4 = tid & 7;
    float acc[2][8][4];
#pragma unroll
    for (int mt = 0; mt < 2; mt++)
#pragma unroll
        for (int nt = 0; nt < 8; nt++)
#pragma unroll
            for (int q = 0; q < 4; q++) acc[mt][nt][q] = 0.f;

    auto issue = [&](int s, int buf) {
#pragma unroll
        for (int i = 0; i < 4; i++) {
            const char* srcp = (const char*)g_xt + (size_t)ga[i] * 512 + s * 128 + xc4 * 16;
            uint32_t dstp = sptr(sX + buf * XS + ((tid >> 3) + i * 32) * XSTR + xc4 * 4);
            asm volatile("cp.async.cg.shared.global [%0], [%1], 16;"
                         :: "r"(dstp), "l"(srcp) : "memory");
        }
#pragma unroll
        for (int i = 0; i < 4; i++) {
            int wrow = (tid >> 3) + i * 32;
            const float4* srcp = (const float4*)Wp + (size_t)wrow * 32 + s * 8 + xc4;
            uint32_t dstp = sptr(sW + buf * WS + wrow * XSTR + xc4 * 4);
            asm volatile("cp.async.cg.shared.global [%0], [%1], 16;"
                         :: "r"(dstp), "l"(srcp) : "memory");
        }
    };
    issue(0, 0);
    asm volatile("cp.async.commit_group;" ::: "memory");
    issue(1, 1);
    asm volatile("cp.async.commit_group;" ::: "memory");

    const int warp = tid >> 5, lane = tid & 31;
    const int g = lane >> 2, t = lane & 3;
    const int mbase = (warp >> 1) * 32;
    const int nbase = (warp & 1) * 64;
    const int aRow = mbase + (lane & 7) + ((lane >> 3) & 1) * 8;
    const int aK   = (lane >> 4) * 4;
    const int bRow = nbase + (lane & 7) + ((lane >> 4) & 1) * 8;
    const int bK   = ((lane >> 3) & 1) * 4;

#pragma unroll
    for (int s = 0; s < 4; s++) {
        if (s < 3) asm volatile("cp.async.wait_group 1;" ::: "memory");
        else       asm volatile("cp.async.wait_group 0;" ::: "memory");
        __syncthreads();
        if (s + 2 < 4) {
            issue(s + 2, (s + 2) % 3);
            asm volatile("cp.async.commit_group;" ::: "memory");
        }
        const uint32_t sxb = sptr(sX + (s % 3) * XS);
        const uint32_t swb = sptr(sW + (s % 3) * WS);
#pragma unroll
        for (int kk = 0; kk < 4; kk++) {
            const int k0 = kk * 8;
            uint32_t a[2][4];
#pragma unroll
            for (int mt = 0; mt < 2; mt++) {
                uint32_t ad = sxb + ((aRow + mt * 16) * XSTR + k0 + aK) * 4;
                LDSM4(a[mt][0], a[mt][1], a[mt][2], a[mt][3], ad);
            }
#pragma unroll
            for (int half = 0; half < 2; half++) {
                uint32_t b[4][2];
#pragma unroll
                for (int pp = 0; pp < 2; pp++) {
                    int p = half * 2 + pp;
                    uint32_t bd = swb + ((bRow + p * 16) * XSTR + k0 + bK) * 4;
                    LDSM4(b[pp * 2][0], b[pp * 2][1],
                          b[pp * 2 + 1][0], b[pp * 2 + 1][1], bd);
                }
#pragma unroll
                for (int ntl = 0; ntl < 4; ntl++) {
                    int nt = half * 4 + ntl;
#pragma unroll
                    for (int mt = 0; mt < 2; mt++) {
                        asm volatile(
                            "mma.sync.aligned.m16n8k8.row.col.f32.tf32.tf32.f32 "
                            "{%0,%1,%2,%3}, {%4,%5,%6,%7}, {%8,%9}, {%0,%1,%2,%3};\n"
                            : "+f"(acc[mt][nt][0]), "+f"(acc[mt][nt][1]),
                              "+f"(acc[mt][nt][2]), "+f"(acc[mt][nt][3])
                            : "r"(a[mt][0]), "r"(a[mt][1]), "r"(a[mt][2]),
                              "r"(a[mt][3]), "r"(b[ntl][0]), "r"(b[ntl][1]));
                    }
                }
            }
        }
    }

    if (is_loop) {
        // y += X@loop_w + bias (y pre-zeroed; atomics so ordering vs scatter is free)
#pragma unroll
        for (int mt = 0; mt < 2; mt++) {
            int rA = rowbase + mbase + mt * 16 + g;
#pragma unroll
            for (int nt = 0; nt < 8; nt++) {
                int col = nbase + nt * 8 + 2 * t;
                float ba = __ldg(bias + col), bb = __ldg(bias + col + 1);
                if (rA < NN)
                    asm volatile("red.global.add.v2.f32 [%0], {%1,%2};"
                                 :: "l"(y + (size_t)rA * DD + col),
                                    "f"(acc[mt][nt][0] + ba), "f"(acc[mt][nt][1] + bb)
                                 : "memory");
                if (rA + 8 < NN)
                    asm volatile("red.global.add.v2.f32 [%0], {%1,%2};"
                                 :: "l"(y + (size_t)(rA + 8) * DD + col),
                                    "f"(acc[mt][nt][2] + ba), "f"(acc[mt][nt][3] + bb)
                                 : "memory");
            }
        }
        return;
    }

    // ---- Fused scatter epilogue (data tiles) ----
    __syncthreads();                       // all warps done reading smem buffers
    float* st = sm;                        // 128 x 132 tile (67.6 KB)
    float* rg = sm + 128 * 132;            // 128 per-row gates
#pragma unroll
    for (int mt = 0; mt < 2; mt++) {
        int rloc = mbase + mt * 16 + g;
#pragma unroll
        for (int nt = 0; nt < 8; nt++) {
            int col = nbase + nt * 8 + 2 * t;
            *(float2*)&st[rloc * 132 + col] =
                make_float2(acc[mt][nt][0], acc[mt][nt][1]);
            *(float2*)&st[(rloc + 8) * 132 + col] =
                make_float2(acc[mt][nt][2], acc[mt][nt][3]);
        }
    }
    if (tid < 128)
        rg[tid] = __ldg(&g_sgate[(size_t)r * NN + __ldg(&g_glist[rowbase + tid])]);
    __syncthreads();

    const int ebeg = __ldg(&g_erow[rowbase]);
    const int eend = __ldg(&g_erow[rowbase + 128]);
    int i = ebeg + warp;
    for (; i + 24 < eend; i += 32) {
        int pk[4];
        float sn[4];
#pragma unroll
        for (int u = 0; u < 4; u++) {
            pk[u] = __ldg(&g_spack[i + u * 8]);
            sn[u] = __ldg(&g_snorm[i + u * 8]);
        }
#pragma unroll
        for (int u = 0; u < 4; u++) {
            float wg = sn[u] * rg[pk[u] & 127];
            float4 v = *(float4*)&st[(pk[u] & 127) * 132 + lane * 4];
            float* yp = y + (size_t)(pk[u] >> 8) * DD + lane * 4;
            asm volatile("red.global.add.v4.f32 [%0], {%1,%2,%3,%4};"
                         :: "l"(yp), "f"(v.x * wg), "f"(v.y * wg),
                            "f"(v.z * wg), "f"(v.w * wg)
                         : "memory");
        }
    }
    for (; i < eend; i += 8) {
        int pk = __ldg(&g_spack[i]);
        float wg = __ldg(&g_snorm[i]) * rg[pk & 127];
        float4 v = *(float4*)&st[(pk & 127) * 132 + lane * 4];
        float* yp = y + (size_t)(pk >> 8) * DD + lane * 4;
        asm volatile("red.global.add.v4.f32 [%0], {%1,%2,%3,%4};"
                     :: "l"(yp), "f"(v.x * wg), "f"(v.y * wg),
                        "f"(v.z * wg), "f"(v.w * wg)
                     : "memory");
    }
}

// ---------------------------------------------------------------------------
extern "C" void kernel_launch(void* const* d_in, const int* in_sizes, int n_in,
                              void* d_out, int out_size) {
    const float* h    = (const float*)d_in[0];
    const float* norm = (const float*)d_in[1];
    const float* w0   = (const float*)d_in[2];
    const float* b0   = (const float*)d_in[3];
    const float* lw0  = (const float*)d_in[4];
    const float* gw0  = (const float*)d_in[5];
    const float* w1   = (const float*)d_in[6];
    const float* b1   = (const float*)d_in[7];
    const float* lw1  = (const float*)d_in[8];
    const float* gw1  = (const float*)d_in[9];
    const int*   src  = (const int*)d_in[10];
    const int*   dst  = (const int*)d_in[11];
    const int*   rel  = (const int*)d_in[12];
    float* out = (float*)d_out;

    cudaFuncSetAttribute(gemm_all_kernel,
                         cudaFuncAttributeMaxDynamicSharedMemorySize, GEMM_SMEM);

    float* h1 = nullptr;
    cudaGetSymbolAddress((void**)&h1, g_h1);
    int* scanp = nullptr;
    cudaGetSymbolAddress((void**)&scanp, g_scan);
    int* flagp = nullptr;
    cudaGetSymbolAddress((void**)&flagp, g_flag);
    int* ecntp = nullptr;
    cudaGetSymbolAddress((void**)&ecntp, g_ecnt);
    int* erowp = nullptr;
    cudaGetSymbolAddress((void**)&erowp, g_erow);

    const int NBF = (NFLAG + 1023) / 1024;           // 782
    const int NBE = (NPADMAX + 1023) / 1024;         // 783
    const int all_grid = NBLK + NPADMAX / 128;       // 6647 worst case
    const int gatex_grid = NP / 8;                   // 6256 (covers padding)
    const int wcvt_grid = (NR + 1) * 128 * 32 / 256; // 272 (exact)

    // ---- Compaction + CSR prep (shared by both layers)
    zero_kernel<<<NPADMAX / 256, 256>>>();
    mark_kernel<<<NE / 256, 256>>>(src, rel);
    scan1_kernel<<<NBF, 256>>>(flagp, scanp, NFLAG);
    scan2_kernel<<<1, 1024>>>(NBF);
    scan3_kernel<<<(NFLAG + 255) / 256, 256>>>(scanp, NFLAG, -1);
    meta_kernel<<<1, 32>>>();
    buildcidx_kernel<<<NE / 256, 256>>>(src, rel);
    scan1_kernel<<<NBE, 256>>>(ecntp, erowp, NPADMAX);
    scan2_kernel<<<1, 1024>>>(NBE);
    scan3_kernel<<<(NPADMAX + 255) / 256, 256>>>(erowp, NPADMAX, NE);
    scatter_kernel<<<NE / 256, 256>>>(dst, norm);

    // ---- Layer 0
    cudaMemsetAsync(h1, 0, (size_t)NN * DD * sizeof(float));
    gatex_kernel<<<gatex_grid, 128>>>(h, gw0, 0);
    wcvt_kernel<<<wcvt_grid, 256>>>(w0, lw0);
    gemm_all_kernel<<<all_grid, 256, GEMM_SMEM>>>(b0, h1);

    // ---- Layer 1 (relu fused into gatex)
    cudaMemsetAsync(out, 0, (size_t)NN * DD * sizeof(float));
    gatex_kernel<<<gatex_grid, 128>>>(h1, gw1, 1);
    wcvt_kernel<<<wcvt_grid, 256>>>(w1, lw1);
    gemm_all_kernel<<<all_grid, 256, GEMM_SMEM>>>(b1, out);
}

// round 14
// speedup vs baseline: 2.1859x; 1.1677x over previous
#include <cuda_runtime.h>
#include <cuda_fp16.h>
#include <cstdint>

#define NN 50000
#define NE 800000
#define NR 16
#define DD 128
#define NP 50048                 // NN padded to 128 (391 blocks)
#define NBLK 391
#define NFLAG (NR * NN)          // 800000 (r,s) pairs ( == NE )
#define NPADMAX (NR * NP)        // 800768 max padded compact rows

// Scratch (device globals; no dynamic allocation allowed).
__device__ float g_sgate[(size_t)NR * NN];         // 3.2 MB gate table
__device__ float g_h1[(size_t)NN * DD];            // 25.6 MB layer-0 output (pre-relu)
__device__ __half g_xh[(size_t)NP * DD];           // 12.8 MB fp16 X (zero-padded)
__device__ __half g_wh[(size_t)(NR + 1) * DD * DD];// 0.55 MB fp16 W^T (n-major)
// Compaction + CSR scratch
__device__ int g_flag[NFLAG];
__device__ int g_scan[NFLAG];
__device__ int g_bsum[1024];
__device__ int g_glist[NPADMAX];
__device__ int g_cidx[NE];
__device__ int g_ecnt[NPADMAX];
__device__ int g_efill[NPADMAX];
__device__ int g_erow[NPADMAX + 1];
__device__ int g_spack[NE];      // (dst << 8) | local_row, row-sorted order
__device__ float g_snorm[NE];    // norm[e], row-sorted order (layer-invariant)
__device__ int g_relstart[NR];
__device__ int g_padoff[NR + 1];
__device__ int g_pblk[NR + 1];
__device__ int g_nblk;

__device__ __forceinline__ uint32_t sptr(const void* p) {
    return (uint32_t)__cvta_generic_to_shared(p);
}
#define LDSM4(r0, r1, r2, r3, addr)                                          \
    asm volatile("ldmatrix.sync.aligned.m8n8.x4.shared.b16 {%0,%1,%2,%3}, [%4];" \
                 : "=r"(r0), "=r"(r1), "=r"(r2), "=r"(r3) : "r"(addr))

// ---------------------------------------------------------------------------
// Compaction + CSR prep (once per call) — unchanged from R12
// ---------------------------------------------------------------------------
__global__ void zero_kernel() {
    int i = blockIdx.x * 256 + threadIdx.x;
    g_glist[i] = 0;
    g_ecnt[i] = 0;
    g_efill[i] = 0;
    if (i < NFLAG) g_flag[i] = 0;
}
__global__ void mark_kernel(const int* __restrict__ src, const int* __restrict__ rel) {
    int e = blockIdx.x * 256 + threadIdx.x;
    g_flag[__ldg(rel + e) * NN + __ldg(src + e)] = 1;
}
__global__ void scan1_kernel(const int* __restrict__ in, int* __restrict__ out, int n) {
    __shared__ int sd[256];
    const int tid = threadIdx.x;
    int base = blockIdx.x * 1024 + tid * 4;
    int f[4], s = 0;
#pragma unroll
    for (int j = 0; j < 4; j++) {
        f[j] = (base + j < n) ? in[base + j] : 0;
        s += f[j];
    }
    sd[tid] = s;
    __syncthreads();
#pragma unroll
    for (int off = 1; off < 256; off <<= 1) {
        int v = (tid >= off) ? sd[tid - off] : 0;
        __syncthreads();
        sd[tid] += v;
        __syncthreads();
    }
    int run = sd[tid] - s;
#pragma unroll
    for (int j = 0; j < 4; j++) {
        if (base + j < n) out[base + j] = run;
        run += f[j];
    }
    if (tid == 255) g_bsum[blockIdx.x] = sd[255];
}
__global__ void scan2_kernel(int nblocks) {
    __shared__ int sd[1024];
    const int tid = threadIdx.x;
    int v0 = (tid < nblocks) ? g_bsum[tid] : 0;
    sd[tid] = v0;
    __syncthreads();
#pragma unroll
    for (int off = 1; off < 1024; off <<= 1) {
        int v = (tid >= off) ? sd[tid - off] : 0;
        __syncthreads();
        sd[tid] += v;
        __syncthreads();
    }
    if (tid < nblocks) g_bsum[tid] = sd[tid] - v0;
}
__global__ void scan3_kernel(int* __restrict__ out, int n, int tail) {
    int i = blockIdx.x * 256 + threadIdx.x;
    if (i < n) out[i] += g_bsum[i >> 10];
    if (i == 0 && tail >= 0) out[n] = tail;
}
__global__ void meta_kernel() {
    if (threadIdx.x != 0) return;
    int total = g_scan[NFLAG - 1] + g_flag[NFLAG - 1];
    int pad = 0;
    for (int r = 0; r < NR; r++) {
        int st = g_scan[r * NN];
        int nx = (r < NR - 1) ? g_scan[(r + 1) * NN] : total;
        g_relstart[r] = st;
        g_padoff[r] = pad;
        g_pblk[r] = pad >> 7;
        pad += ((nx - st + 127) & ~127);
    }
    g_padoff[NR] = pad;
    g_pblk[NR] = pad >> 7;
    g_nblk = pad >> 7;
}
__global__ void buildcidx_kernel(const int* __restrict__ src,
                                 const int* __restrict__ rel) {
    int i = blockIdx.x * 256 + threadIdx.x;
    if (g_flag[i]) {
        int pr = i / NN, ps = i - pr * NN;
        g_glist[g_padoff[pr] + g_scan[i] - g_relstart[pr]] = ps;
    }
    int r = __ldg(rel + i), s = __ldg(src + i);
    int c = g_padoff[r] + g_scan[r * NN + s] - g_relstart[r];
    g_cidx[i] = c;
    atomicAdd(&g_ecnt[c], 1);
}
__global__ void scatter_kernel(const int* __restrict__ dst,
                               const float* __restrict__ norm) {
    int e = blockIdx.x * 256 + threadIdx.x;
    int c = g_cidx[e];
    int pos = g_erow[c] + atomicAdd(&g_efill[c], 1);
    g_spack[pos] = (__ldg(dst + e) << 8) | (c & 127);
    g_snorm[pos] = __ldg(norm + e);
}

// ---------------------------------------------------------------------------
// Merged X pass: one read of x produces the fp16 (relu'd) xh AND the gate
// table. 128 threads = 8 nodes.
// ---------------------------------------------------------------------------
__global__ void gatex_kernel(const float* __restrict__ x,
                             const float* __restrict__ gw, int relu) {
    __shared__ float sx[8][132];
    __shared__ float sg[16][132];
    const int tid = threadIdx.x;
    const int nb = blockIdx.x * 8;                   // grid = NP/8 (covers padding)
#pragma unroll
    for (int i = 0; i < 4; i++) {
        int l = tid + i * 128;
        int r = l >> 5, c = l & 31;
        *(float4*)&sg[r][c * 4] = __ldg((const float4*)gw + r * 32 + c);
    }
#pragma unroll
    for (int i = 0; i < 2; i++) {
        int l = tid + i * 128;
        int n = l >> 5, c = l & 31;
        float4 v = make_float4(0.f, 0.f, 0.f, 0.f);
        if (nb + n < NN) v = __ldg((const float4*)x + (size_t)(nb + n) * 32 + c);
        if (relu) {
            v.x = fmaxf(v.x, 0.f); v.y = fmaxf(v.y, 0.f);
            v.z = fmaxf(v.z, 0.f); v.w = fmaxf(v.w, 0.f);
        }
        *(float4*)&sx[n][c * 4] = v;
    }
    __syncthreads();
    // xh store (fp16 rn), covers padded rows with zeros
#pragma unroll
    for (int i = 0; i < 2; i++) {
        int l = tid + i * 128;
        int n = l >> 5, c = l & 31;
        float4 v = *(float4*)&sx[n][c * 4];
        __half2 h01 = __floats2half2_rn(v.x, v.y);
        __half2 h23 = __floats2half2_rn(v.z, v.w);
        uint2 o;
        o.x = *(uint32_t*)&h01;
        o.y = *(uint32_t*)&h23;
        ((uint2*)g_xh)[(size_t)(nb + n) * 32 + c] = o;
    }
    // gate dot products (fp32, unchanged numerics)
    const int node = tid >> 4, rel = tid & 15;
    float d = 0.f;
#pragma unroll
    for (int k = 0; k < 32; k++) {
        float4 a = *(float4*)&sx[node][k * 4];
        float4 g = *(float4*)&sg[rel][k * 4];
        d += a.x * g.x + a.y * g.y + a.z * g.z + a.w * g.w;
    }
    if (nb + node < NN)
        g_sgate[(size_t)rel * NN + nb + node] = 1.f / (1.f + __expf(-d));
}

// W pre-pass (TRANSPOSED, fp16): g_wh[r][n][k] = fp16( W[r][k][n] ); r=16 -> loop_w.
__global__ void wcvt_kernel(const float* __restrict__ Wr,
                            const float* __restrict__ loopw) {
    int i = blockIdx.x * 256 + threadIdx.x;          // grid = 17*4096/256 = 272
    int r = i >> 12, rem = i & 4095;
    int n = rem >> 5, kq = rem & 31, k = kq * 4;
    const float* src = (r < NR) ? (Wr + (size_t)r * DD * DD) : loopw;
    float v0 = __ldg(src + (size_t)(k + 0) * DD + n);
    float v1 = __ldg(src + (size_t)(k + 1) * DD + n);
    float v2 = __ldg(src + (size_t)(k + 2) * DD + n);
    float v3 = __ldg(src + (size_t)(k + 3) * DD + n);
    __half2 h01 = __floats2half2_rn(v0, v1);
    __half2 h23 = __floats2half2_rn(v2, v3);
    uint2 o;
    o.x = *(uint32_t*)&h01;
    o.y = *(uint32_t*)&h23;
    ((uint2*)g_wh)[(size_t)r * 4096 + n * 32 + kq] = o;
}

// ---------------------------------------------------------------------------
// Unified GEMM: 128x128x128 fp16 tile (fp32 accum), cp.async 3-buffer
// pipeline (4 stages of k32), ldmatrix fragments, mma.m16n8k16.
// Block j < NBLK: self-loop tile (y += X@loop_w + bias). Else: data tile +
// fused edge scatter. Smem stride 40 halves (80 B): ldmatrix conflict-free.
// ---------------------------------------------------------------------------
#define HSTR 40
#define HS (128 * HSTR)          // 5120 halves per stage buffer
#define NSTG 3
#define GEMM_SMEM 68096          // max(3*2*HS*2 = 61440, 128*132*4 + 512)

__global__ void __launch_bounds__(256, 2)
gemm_all_kernel(const float* __restrict__ bias, float* __restrict__ y) {
    extern __shared__ float sm[];
    __half* sA = (__half*)sm;
    __half* sB = sA + NSTG * HS;
    const int tid = threadIdx.x;
    const int j = blockIdx.x;
    const bool is_loop = j < NBLK;
    int r, rowbase;
    if (is_loop) {
        r = NR;
        rowbase = j * 128;
    } else {
        int jj = j - NBLK;
        if (jj >= g_nblk) return;
        r = NR - 1;
#pragma unroll
        for (int q = NR - 1; q > 0; q--)
            if (jj < g_pblk[q]) r = q - 1;
        rowbase = jj * 128;
    }
    const __half* Wp = g_wh + (size_t)r * DD * DD;

    int ga[2];
#pragma unroll
    for (int i = 0; i < 2; i++) {
        int xr = (tid >> 2) + i * 64;
        ga[i] = is_loop ? (rowbase + xr) : __ldg(&g_glist[rowbase + xr]);
    }
    const int c4 = tid & 3;
    float acc[2][8][4];
#pragma unroll
    for (int mt = 0; mt < 2; mt++)
#pragma unroll
        for (int nt = 0; nt < 8; nt++)
#pragma unroll
            for (int q = 0; q < 4; q++) acc[mt][nt][q] = 0.f;

    auto issue = [&](int s, int buf) {
#pragma unroll
        for (int i = 0; i < 2; i++) {
            const char* srcp = (const char*)g_xh + (size_t)ga[i] * 256 + s * 64 + c4 * 16;
            uint32_t dstp = sptr(sA + buf * HS + ((tid >> 2) + i * 64) * HSTR + c4 * 8);
            asm volatile("cp.async.cg.shared.global [%0], [%1], 16;"
                         :: "r"(dstp), "l"(srcp) : "memory");
        }
#pragma unroll
        for (int i = 0; i < 2; i++) {
            int wrow = (tid >> 2) + i * 64;
            const char* srcp = (const char*)Wp + (size_t)wrow * 256 + s * 64 + c4 * 16;
            uint32_t dstp = sptr(sB + buf * HS + wrow * HSTR + c4 * 8);
            asm volatile("cp.async.cg.shared.global [%0], [%1], 16;"
                         :: "r"(dstp), "l"(srcp) : "memory");
        }
    };
    issue(0, 0);
    asm volatile("cp.async.commit_group;" ::: "memory");
    issue(1, 1);
    asm volatile("cp.async.commit_group;" ::: "memory");

    const int warp = tid >> 5, lane = tid & 31;
    const int g = lane >> 2, t = lane & 3;
    const int mbase = (warp >> 1) * 32;
    const int nbase = (warp & 1) * 64;
    // ldmatrix lane->address components (see fragment mapping notes)
    const int aRow = mbase + (lane & 15);
    const int aK   = (lane >> 4) * 8;
    const int bRow = nbase + (lane & 7) + (lane >> 4) * 8;
    const int bK   = ((lane >> 3) & 1) * 8;

#pragma unroll
    for (int s = 0; s < 4; s++) {
        if (s < 3) asm volatile("cp.async.wait_group 1;" ::: "memory");
        else       asm volatile("cp.async.wait_group 0;" ::: "memory");
        __syncthreads();
        if (s + 2 < 4) {
            issue(s + 2, (s + 2) % 3);
            asm volatile("cp.async.commit_group;" ::: "memory");
        }
        const uint32_t sxb = sptr(sA + (s % 3) * HS);
        const uint32_t swb = sptr(sB + (s % 3) * HS);
#pragma unroll
        for (int kk = 0; kk < 2; kk++) {
            const int k0 = kk * 16;
            uint32_t a[2][4];
#pragma unroll
            for (int mt = 0; mt < 2; mt++) {
                uint32_t ad = sxb + ((aRow + mt * 16) * HSTR + k0 + aK) * 2;
                LDSM4(a[mt][0], a[mt][1], a[mt][2], a[mt][3], ad);
            }
#pragma unroll
            for (int p = 0; p < 4; p++) {            // n-tile pairs (2p, 2p+1)
                uint32_t b0a, b1a, b0b, b1b;
                uint32_t bd = swb + ((bRow + p * 16) * HSTR + k0 + bK) * 2;
                LDSM4(b0a, b1a, b0b, b1b, bd);
#pragma unroll
                for (int mt = 0; mt < 2; mt++) {
                    asm volatile(
                        "mma.sync.aligned.m16n8k16.row.col.f32.f16.f16.f32 "
                        "{%0,%1,%2,%3}, {%4,%5,%6,%7}, {%8,%9}, {%0,%1,%2,%3};\n"
                        : "+f"(acc[mt][2 * p][0]), "+f"(acc[mt][2 * p][1]),
                          "+f"(acc[mt][2 * p][2]), "+f"(acc[mt][2 * p][3])
                        : "r"(a[mt][0]), "r"(a[mt][1]), "r"(a[mt][2]),
                          "r"(a[mt][3]), "r"(b0a), "r"(b1a));
                    asm volatile(
                        "mma.sync.aligned.m16n8k16.row.col.f32.f16.f16.f32 "
                        "{%0,%1,%2,%3}, {%4,%5,%6,%7}, {%8,%9}, {%0,%1,%2,%3};\n"
                        : "+f"(acc[mt][2 * p + 1][0]), "+f"(acc[mt][2 * p + 1][1]),
                          "+f"(acc[mt][2 * p + 1][2]), "+f"(acc[mt][2 * p + 1][3])
                        : "r"(a[mt][0]), "r"(a[mt][1]), "r"(a[mt][2]),
                          "r"(a[mt][3]), "r"(b0b), "r"(b1b));
                }
            }
        }
    }

    if (is_loop) {
        // y += X@loop_w + bias (y pre-zeroed; atomics so ordering is free)
#pragma unroll
        for (int mt = 0; mt < 2; mt++) {
            int rA = rowbase + mbase + mt * 16 + g;
#pragma unroll
            for (int nt = 0; nt < 8; nt++) {
                int col = nbase + nt * 8 + 2 * t;
                float ba = __ldg(bias + col), bb = __ldg(bias + col + 1);
                if (rA < NN)
                    asm volatile("red.global.add.v2.f32 [%0], {%1,%2};"
                                 :: "l"(y + (size_t)rA * DD + col),
                                    "f"(acc[mt][nt][0] + ba), "f"(acc[mt][nt][1] + bb)
                                 : "memory");
                if (rA + 8 < NN)
                    asm volatile("red.global.add.v2.f32 [%0], {%1,%2};"
                                 :: "l"(y + (size_t)(rA + 8) * DD + col),
                                    "f"(acc[mt][nt][2] + ba), "f"(acc[mt][nt][3] + bb)
                                 : "memory");
            }
        }
        return;
    }

    // ---- Fused scatter epilogue (data tiles) ----
    __syncthreads();                       // all warps done reading smem buffers
    float* st = sm;                        // 128 x 132 fp32 tile (67.6 KB)
    float* rg = sm + 128 * 132;            // 128 per-row gates
#pragma unroll
    for (int mt = 0; mt < 2; mt++) {
        int rloc = mbase + mt * 16 + g;
#pragma unroll
        for (int nt = 0; nt < 8; nt++) {
            int col = nbase + nt * 8 + 2 * t;
            *(float2*)&st[rloc * 132 + col] =
                make_float2(acc[mt][nt][0], acc[mt][nt][1]);
            *(float2*)&st[(rloc + 8) * 132 + col] =
                make_float2(acc[mt][nt][2], acc[mt][nt][3]);
        }
    }
    if (tid < 128)
        rg[tid] = __ldg(&g_sgate[(size_t)r * NN + __ldg(&g_glist[rowbase + tid])]);
    __syncthreads();

    const int ebeg = __ldg(&g_erow[rowbase]);
    const int eend = __ldg(&g_erow[rowbase + 128]);
    int i = ebeg + warp;
    for (; i + 24 < eend; i += 32) {
        int pk[4];
        float sn[4];
#pragma unroll
        for (int u = 0; u < 4; u++) {
            pk[u] = __ldg(&g_spack[i + u * 8]);
            sn[u] = __ldg(&g_snorm[i + u * 8]);
        }
#pragma unroll
        for (int u = 0; u < 4; u++) {
            float wg = sn[u] * rg[pk[u] & 127];
            float4 v = *(float4*)&st[(pk[u] & 127) * 132 + lane * 4];
            float* yp = y + (size_t)(pk[u] >> 8) * DD + lane * 4;
            asm volatile("red.global.add.v4.f32 [%0], {%1,%2,%3,%4};"
                         :: "l"(yp), "f"(v.x * wg), "f"(v.y * wg),
                            "f"(v.z * wg), "f"(v.w * wg)
                         : "memory");
        }
    }
    for (; i < eend; i += 8) {
        int pk = __ldg(&g_spack[i]);
        float wg = __ldg(&g_snorm[i]) * rg[pk & 127];
        float4 v = *(float4*)&st[(pk & 127) * 132 + lane * 4];
        float* yp = y + (size_t)(pk >> 8) * DD + lane * 4;
        asm volatile("red.global.add.v4.f32 [%0], {%1,%2,%3,%4};"
                     :: "l"(yp), "f"(v.x * wg), "f"(v.y * wg),
                        "f"(v.z * wg), "f"(v.w * wg)
                     : "memory");
    }
}

// ---------------------------------------------------------------------------
extern "C" void kernel_launch(void* const* d_in, const int* in_sizes, int n_in,
                              void* d_out, int out_size) {
    const float* h    = (const float*)d_in[0];
    const float* norm = (const float*)d_in[1];
    const float* w0   = (const float*)d_in[2];
    const float* b0   = (const float*)d_in[3];
    const float* lw0  = (const float*)d_in[4];
    const float* gw0  = (const float*)d_in[5];
    const float* w1   = (const float*)d_in[6];
    const float* b1   = (const float*)d_in[7];
    const float* lw1  = (const float*)d_in[8];
    const float* gw1  = (const float*)d_in[9];
    const int*   src  = (const int*)d_in[10];
    const int*   dst  = (const int*)d_in[11];
    const int*   rel  = (const int*)d_in[12];
    float* out = (float*)d_out;

    cudaFuncSetAttribute(gemm_all_kernel,
                         cudaFuncAttributeMaxDynamicSharedMemorySize, GEMM_SMEM);

    float* h1 = nullptr;
    cudaGetSymbolAddress((void**)&h1, g_h1);
    int* scanp = nullptr;
    cudaGetSymbolAddress((void**)&scanp, g_scan);
    int* flagp = nullptr;
    cudaGetSymbolAddress((void**)&flagp, g_flag);
    int* ecntp = nullptr;
    cudaGetSymbolAddress((void**)&ecntp, g_ecnt);
    int* erowp = nullptr;
    cudaGetSymbolAddress((void**)&erowp, g_erow);

    const int NBF = (NFLAG + 1023) / 1024;           // 782
    const int NBE = (NPADMAX + 1023) / 1024;         // 783
    const int all_grid = NBLK + NPADMAX / 128;       // 6647 worst case
    const int gatex_grid = NP / 8;                   // 6256 (covers padding)
    const int wcvt_grid = (NR + 1) * 128 * 32 / 256; // 272 (exact)

    // ---- Compaction + CSR prep (shared by both layers)
    zero_kernel<<<NPADMAX / 256, 256>>>();
    mark_kernel<<<NE / 256, 256>>>(src, rel);
    scan1_kernel<<<NBF, 256>>>(flagp, scanp, NFLAG);
    scan2_kernel<<<1, 1024>>>(NBF);
    scan3_kernel<<<(NFLAG + 255) / 256, 256>>>(scanp, NFLAG, -1);
    meta_kernel<<<1, 32>>>();
    buildcidx_kernel<<<NE / 256, 256>>>(src, rel);
    scan1_kernel<<<NBE, 256>>>(ecntp, erowp, NPADMAX);
    scan2_kernel<<<1, 1024>>>(NBE);
    scan3_kernel<<<(NPADMAX + 255) / 256, 256>>>(erowp, NPADMAX, NE);
    scatter_kernel<<<NE / 256, 256>>>(dst, norm);

    // ---- Layer 0
    cudaMemsetAsync(h1, 0, (size_t)NN * DD * sizeof(float));
    gatex_kernel<<<gatex_grid, 128>>>(h, gw0, 0);
    wcvt_kernel<<<wcvt_grid, 256>>>(w0, lw0);
    gemm_all_kernel<<<all_grid, 256, GEMM_SMEM>>>(b0, h1);

    // ---- Layer 1 (relu fused into gatex)
    cudaMemsetAsync(out, 0, (size_t)NN * DD * sizeof(float));
    gatex_kernel<<<gatex_grid, 128>>>(h1, gw1, 1);
    wcvt_kernel<<<wcvt_grid, 256>>>(w1, lw1);
    gemm_all_kernel<<<all_grid, 256, GEMM_SMEM>>>(b1, out);
}

// round 15
// speedup vs baseline: 2.1981x; 1.0056x over previous
#include <cuda_runtime.h>
#include <cuda_fp16.h>
#include <cstdint>

#define NN 50000
#define NE 800000
#define NR 16
#define DD 128
#define NP 50048                 // NN padded to 128 (391 blocks)
#define NBLK 391
#define NFLAG (NR * NN)          // 800000 (r,s) pairs ( == NE )
#define NPADMAX (NR * NP)        // 800768 max padded compact rows

// Scratch (device globals; no dynamic allocation allowed).
__device__ float g_sgate[(size_t)NR * NN];         // 3.2 MB gate table
__device__ float g_h1[(size_t)NN * DD];            // 25.6 MB layer-0 output (pre-relu)
__device__ __half g_xh[(size_t)NP * DD];           // 12.8 MB fp16 X (zero-padded)
__device__ __half g_wh[(size_t)(NR + 1) * DD * DD];// 0.55 MB fp16 W^T (n-major)
// Compaction + CSR scratch
__device__ int g_flag[NFLAG];
__device__ int g_scan[NFLAG];
__device__ int g_bsum[1024];
__device__ int g_glist[NPADMAX];
__device__ int g_cidx[NE];
__device__ int g_ecnt[NPADMAX];
__device__ int g_efill[NPADMAX];
__device__ int g_erow[NPADMAX + 1];
__device__ int g_spack[NE];      // (dst << 8) | local_row, row-sorted order
__device__ float g_snorm[NE];    // norm[e], row-sorted order (layer-invariant)
__device__ int g_relstart[NR];
__device__ int g_padoff[NR + 1];
__device__ int g_pblk[NR + 1];
__device__ int g_nblk;

__device__ __forceinline__ uint32_t sptr(const void* p) {
    return (uint32_t)__cvta_generic_to_shared(p);
}
#define LDSM4(r0, r1, r2, r3, addr)                                          \
    asm volatile("ldmatrix.sync.aligned.m8n8.x4.shared.b16 {%0,%1,%2,%3}, [%4];" \
                 : "=r"(r0), "=r"(r1), "=r"(r2), "=r"(r3) : "r"(addr))

// ---------------------------------------------------------------------------
// Compaction + CSR prep (once per call) — unchanged from R12
// ---------------------------------------------------------------------------
__global__ void zero_kernel() {
    int i = blockIdx.x * 256 + threadIdx.x;
    g_glist[i] = 0;
    g_ecnt[i] = 0;
    g_efill[i] = 0;
    if (i < NFLAG) g_flag[i] = 0;
}
__global__ void mark_kernel(const int* __restrict__ src, const int* __restrict__ rel) {
    int e = blockIdx.x * 256 + threadIdx.x;
    g_flag[__ldg(rel + e) * NN + __ldg(src + e)] = 1;
}
__global__ void scan1_kernel(const int* __restrict__ in, int* __restrict__ out, int n) {
    __shared__ int sd[256];
    const int tid = threadIdx.x;
    int base = blockIdx.x * 1024 + tid * 4;
    int f[4], s = 0;
#pragma unroll
    for (int j = 0; j < 4; j++) {
        f[j] = (base + j < n) ? in[base + j] : 0;
        s += f[j];
    }
    sd[tid] = s;
    __syncthreads();
#pragma unroll
    for (int off = 1; off < 256; off <<= 1) {
        int v = (tid >= off) ? sd[tid - off] : 0;
        __syncthreads();
        sd[tid] += v;
        __syncthreads();
    }
    int run = sd[tid] - s;
#pragma unroll
    for (int j = 0; j < 4; j++) {
        if (base + j < n) out[base + j] = run;
        run += f[j];
    }
    if (tid == 255) g_bsum[blockIdx.x] = sd[255];
}
__global__ void scan2_kernel(int nblocks) {
    __shared__ int sd[1024];
    const int tid = threadIdx.x;
    int v0 = (tid < nblocks) ? g_bsum[tid] : 0;
    sd[tid] = v0;
    __syncthreads();
#pragma unroll
    for (int off = 1; off < 1024; off <<= 1) {
        int v = (tid >= off) ? sd[tid - off] : 0;
        __syncthreads();
        sd[tid] += v;
        __syncthreads();
    }
    if (tid < nblocks) g_bsum[tid] = sd[tid] - v0;
}
__global__ void scan3_kernel(int* __restrict__ out, int n, int tail) {
    int i = blockIdx.x * 256 + threadIdx.x;
    if (i < n) out[i] += g_bsum[i >> 10];
    if (i == 0 && tail >= 0) out[n] = tail;
}
__global__ void meta_kernel() {
    if (threadIdx.x != 0) return;
    int total = g_scan[NFLAG - 1] + g_flag[NFLAG - 1];
    int pad = 0;
    for (int r = 0; r < NR; r++) {
        int st = g_scan[r * NN];
        int nx = (r < NR - 1) ? g_scan[(r + 1) * NN] : total;
        g_relstart[r] = st;
        g_padoff[r] = pad;
        g_pblk[r] = pad >> 7;
        pad += ((nx - st + 127) & ~127);
    }
    g_padoff[NR] = pad;
    g_pblk[NR] = pad >> 7;
    g_nblk = pad >> 7;
}
__global__ void buildcidx_kernel(const int* __restrict__ src,
                                 const int* __restrict__ rel) {
    int i = blockIdx.x * 256 + threadIdx.x;
    if (g_flag[i]) {
        int pr = i / NN, ps = i - pr * NN;
        g_glist[g_padoff[pr] + g_scan[i] - g_relstart[pr]] = ps;
    }
    int r = __ldg(rel + i), s = __ldg(src + i);
    int c = g_padoff[r] + g_scan[r * NN + s] - g_relstart[r];
    g_cidx[i] = c;
    atomicAdd(&g_ecnt[c], 1);
}
__global__ void scatter_kernel(const int* __restrict__ dst,
                               const float* __restrict__ norm) {
    int e = blockIdx.x * 256 + threadIdx.x;
    int c = g_cidx[e];
    int pos = g_erow[c] + atomicAdd(&g_efill[c], 1);
    g_spack[pos] = (__ldg(dst + e) << 8) | (c & 127);
    g_snorm[pos] = __ldg(norm + e);
}

// ---------------------------------------------------------------------------
// Merged X pass: one read of x produces the fp16 (relu'd) xh AND the gate
// table. 128 threads = 8 nodes.
// ---------------------------------------------------------------------------
__global__ void gatex_kernel(const float* __restrict__ x,
                             const float* __restrict__ gw, int relu) {
    __shared__ float sx[8][132];
    __shared__ float sg[16][132];
    const int tid = threadIdx.x;
    const int nb = blockIdx.x * 8;                   // grid = NP/8 (covers padding)
#pragma unroll
    for (int i = 0; i < 4; i++) {
        int l = tid + i * 128;
        int r = l >> 5, c = l & 31;
        *(float4*)&sg[r][c * 4] = __ldg((const float4*)gw + r * 32 + c);
    }
#pragma unroll
    for (int i = 0; i < 2; i++) {
        int l = tid + i * 128;
        int n = l >> 5, c = l & 31;
        float4 v = make_float4(0.f, 0.f, 0.f, 0.f);
        if (nb + n < NN) v = __ldg((const float4*)x + (size_t)(nb + n) * 32 + c);
        if (relu) {
            v.x = fmaxf(v.x, 0.f); v.y = fmaxf(v.y, 0.f);
            v.z = fmaxf(v.z, 0.f); v.w = fmaxf(v.w, 0.f);
        }
        *(float4*)&sx[n][c * 4] = v;
    }
    __syncthreads();
    // xh store (fp16 rn), covers padded rows with zeros
#pragma unroll
    for (int i = 0; i < 2; i++) {
        int l = tid + i * 128;
        int n = l >> 5, c = l & 31;
        float4 v = *(float4*)&sx[n][c * 4];
        __half2 h01 = __floats2half2_rn(v.x, v.y);
        __half2 h23 = __floats2half2_rn(v.z, v.w);
        uint2 o;
        o.x = *(uint32_t*)&h01;
        o.y = *(uint32_t*)&h23;
        ((uint2*)g_xh)[(size_t)(nb + n) * 32 + c] = o;
    }
    // gate dot products (fp32, unchanged numerics)
    const int node = tid >> 4, rel = tid & 15;
    float d = 0.f;
#pragma unroll
    for (int k = 0; k < 32; k++) {
        float4 a = *(float4*)&sx[node][k * 4];
        float4 g = *(float4*)&sg[rel][k * 4];
        d += a.x * g.x + a.y * g.y + a.z * g.z + a.w * g.w;
    }
    if (nb + node < NN)
        g_sgate[(size_t)rel * NN + nb + node] = 1.f / (1.f + __expf(-d));
}

// W pre-pass (TRANSPOSED, fp16): g_wh[r][n][k] = fp16( W[r][k][n] ); r=16 -> loop_w.
__global__ void wcvt_kernel(const float* __restrict__ Wr,
                            const float* __restrict__ loopw) {
    int i = blockIdx.x * 256 + threadIdx.x;          // grid = 17*4096/256 = 272
    int r = i >> 12, rem = i & 4095;
    int n = rem >> 5, kq = rem & 31, k = kq * 4;
    const float* src = (r < NR) ? (Wr + (size_t)r * DD * DD) : loopw;
    float v0 = __ldg(src + (size_t)(k + 0) * DD + n);
    float v1 = __ldg(src + (size_t)(k + 1) * DD + n);
    float v2 = __ldg(src + (size_t)(k + 2) * DD + n);
    float v3 = __ldg(src + (size_t)(k + 3) * DD + n);
    __half2 h01 = __floats2half2_rn(v0, v1);
    __half2 h23 = __floats2half2_rn(v2, v3);
    uint2 o;
    o.x = *(uint32_t*)&h01;
    o.y = *(uint32_t*)&h23;
    ((uint2*)g_wh)[(size_t)r * 4096 + n * 32 + kq] = o;
}

// ---------------------------------------------------------------------------
// Unified GEMM: 128x128x128 fp16 tile (fp32 accum), cp.async 3-buffer
// pipeline (4 stages of k32), ldmatrix fragments, mma.m16n8k16.
// Block j < NBLK: self-loop tile (y += X@loop_w + bias). Else: data tile +
// fused edge scatter. Smem stride 40 halves (80 B): ldmatrix conflict-free.
// ---------------------------------------------------------------------------
#define HSTR 40
#define HS (128 * HSTR)          // 5120 halves per stage buffer
#define NSTG 3
#define GEMM_SMEM 68096          // max(3*2*HS*2 = 61440, 128*132*4 + 512)

__global__ void __launch_bounds__(256, 2)
gemm_all_kernel(const float* __restrict__ bias, float* __restrict__ y) {
    extern __shared__ float sm[];
    __half* sA = (__half*)sm;
    __half* sB = sA + NSTG * HS;
    const int tid = threadIdx.x;
    const int j = blockIdx.x;
    const bool is_loop = j < NBLK;
    int r, rowbase;
    if (is_loop) {
        r = NR;
        rowbase = j * 128;
    } else {
        int jj = j - NBLK;
        if (jj >= g_nblk) return;
        r = NR - 1;
#pragma unroll
        for (int q = NR - 1; q > 0; q--)
            if (jj < g_pblk[q]) r = q - 1;
        rowbase = jj * 128;
    }
    const __half* Wp = g_wh + (size_t)r * DD * DD;

    int ga[2];
#pragma unroll
    for (int i = 0; i < 2; i++) {
        int xr = (tid >> 2) + i * 64;
        ga[i] = is_loop ? (rowbase + xr) : __ldg(&g_glist[rowbase + xr]);
    }
    const int c4 = tid & 3;
    float acc[2][8][4];
#pragma unroll
    for (int mt = 0; mt < 2; mt++)
#pragma unroll
        for (int nt = 0; nt < 8; nt++)
#pragma unroll
            for (int q = 0; q < 4; q++) acc[mt][nt][q] = 0.f;

    auto issue = [&](int s, int buf) {
#pragma unroll
        for (int i = 0; i < 2; i++) {
            const char* srcp = (const char*)g_xh + (size_t)ga[i] * 256 + s * 64 + c4 * 16;
            uint32_t dstp = sptr(sA + buf * HS + ((tid >> 2) + i * 64) * HSTR + c4 * 8);
            asm volatile("cp.async.cg.shared.global [%0], [%1], 16;"
                         :: "r"(dstp), "l"(srcp) : "memory");
        }
#pragma unroll
        for (int i = 0; i < 2; i++) {
            int wrow = (tid >> 2) + i * 64;
            const char* srcp = (const char*)Wp + (size_t)wrow * 256 + s * 64 + c4 * 16;
            uint32_t dstp = sptr(sB + buf * HS + wrow * HSTR + c4 * 8);
            asm volatile("cp.async.cg.shared.global [%0], [%1], 16;"
                         :: "r"(dstp), "l"(srcp) : "memory");
        }
    };
    issue(0, 0);
    asm volatile("cp.async.commit_group;" ::: "memory");
    issue(1, 1);
    asm volatile("cp.async.commit_group;" ::: "memory");

    const int warp = tid >> 5, lane = tid & 31;
    const int g = lane >> 2, t = lane & 3;
    const int mbase = (warp >> 1) * 32;
    const int nbase = (warp & 1) * 64;
    // ldmatrix lane->address components (see fragment mapping notes)
    const int aRow = mbase + (lane & 15);
    const int aK   = (lane >> 4) * 8;
    const int bRow = nbase + (lane & 7) + (lane >> 4) * 8;
    const int bK   = ((lane >> 3) & 1) * 8;

#pragma unroll
    for (int s = 0; s < 4; s++) {
        if (s < 3) asm volatile("cp.async.wait_group 1;" ::: "memory");
        else       asm volatile("cp.async.wait_group 0;" ::: "memory");
        __syncthreads();
        if (s + 2 < 4) {
            issue(s + 2, (s + 2) % 3);
            asm volatile("cp.async.commit_group;" ::: "memory");
        }
        const uint32_t sxb = sptr(sA + (s % 3) * HS);
        const uint32_t swb = sptr(sB + (s % 3) * HS);
#pragma unroll
        for (int kk = 0; kk < 2; kk++) {
            const int k0 = kk * 16;
            uint32_t a[2][4];
#pragma unroll
            for (int mt = 0; mt < 2; mt++) {
                uint32_t ad = sxb + ((aRow + mt * 16) * HSTR + k0 + aK) * 2;
                LDSM4(a[mt][0], a[mt][1], a[mt][2], a[mt][3], ad);
            }
#pragma unroll
            for (int p = 0; p < 4; p++) {            // n-tile pairs (2p, 2p+1)
                uint32_t b0a, b1a, b0b, b1b;
                uint32_t bd = swb + ((bRow + p * 16) * HSTR + k0 + bK) * 2;
                LDSM4(b0a, b1a, b0b, b1b, bd);
#pragma unroll
                for (int mt = 0; mt < 2; mt++) {
                    asm volatile(
                        "mma.sync.aligned.m16n8k16.row.col.f32.f16.f16.f32 "
                        "{%0,%1,%2,%3}, {%4,%5,%6,%7}, {%8,%9}, {%0,%1,%2,%3};\n"
                        : "+f"(acc[mt][2 * p][0]), "+f"(acc[mt][2 * p][1]),
                          "+f"(acc[mt][2 * p][2]), "+f"(acc[mt][2 * p][3])
                        : "r"(a[mt][0]), "r"(a[mt][1]), "r"(a[mt][2]),
                          "r"(a[mt][3]), "r"(b0a), "r"(b1a));
                    asm volatile(
                        "mma.sync.aligned.m16n8k16.row.col.f32.f16.f16.f32 "
                        "{%0,%1,%2,%3}, {%4,%5,%6,%7}, {%8,%9}, {%0,%1,%2,%3};\n"
                        : "+f"(acc[mt][2 * p + 1][0]), "+f"(acc[mt][2 * p + 1][1]),
                          "+f"(acc[mt][2 * p + 1][2]), "+f"(acc[mt][2 * p + 1][3])
                        : "r"(a[mt][0]), "r"(a[mt][1]), "r"(a[mt][2]),
                          "r"(a[mt][3]), "r"(b0b), "r"(b1b));
                }
            }
        }
    }

    if (is_loop) {
        // y += X@loop_w + bias (y pre-zeroed; atomics so ordering is free)
#pragma unroll
        for (int mt = 0; mt < 2; mt++) {
            int rA = rowbase + mbase + mt * 16 + g;
#pragma unroll
            for (int nt = 0; nt < 8; nt++) {
                int col = nbase + nt * 8 + 2 * t;
                float ba = __ldg(bias + col), bb = __ldg(bias + col + 1);
                if (rA < NN)
                    asm volatile("red.global.add.v2.f32 [%0], {%1,%2};"
                                 :: "l"(y + (size_t)rA * DD + col),
                                    "f"(acc[mt][nt][0] + ba), "f"(acc[mt][nt][1] + bb)
                                 : "memory");
                if (rA + 8 < NN)
                    asm volatile("red.global.add.v2.f32 [%0], {%1,%2};"
                                 :: "l"(y + (size_t)(rA + 8) * DD + col),
                                    "f"(acc[mt][nt][2] + ba), "f"(acc[mt][nt][3] + bb)
                                 : "memory");
            }
        }
        return;
    }

    // ---- Fused scatter epilogue (data tiles) ----
    __syncthreads();                       // all warps done reading smem buffers
    float* st = sm;                        // 128 x 132 fp32 tile (67.6 KB)
    float* rg = sm + 128 * 132;            // 128 per-row gates
#pragma unroll
    for (int mt = 0; mt < 2; mt++) {
        int rloc = mbase + mt * 16 + g;
#pragma unroll
        for (int nt = 0; nt < 8; nt++) {
            int col = nbase + nt * 8 + 2 * t;
            *(float2*)&st[rloc * 132 + col] =
                make_float2(acc[mt][nt][0], acc[mt][nt][1]);
            *(float2*)&st[(rloc + 8) * 132 + col] =
                make_float2(acc[mt][nt][2], acc[mt][nt][3]);
        }
    }
    if (tid < 128)
        rg[tid] = __ldg(&g_sgate[(size_t)r * NN + __ldg(&g_glist[rowbase + tid])]);
    __syncthreads();

    const int ebeg = __ldg(&g_erow[rowbase]);
    const int eend = __ldg(&g_erow[rowbase + 128]);
    int i = ebeg + warp;
    for (; i + 24 < eend; i += 32) {
        int pk[4];
        float sn[4];
#pragma unroll
        for (int u = 0; u < 4; u++) {
            pk[u] = __ldg(&g_spack[i + u * 8]);
            sn[u] = __ldg(&g_snorm[i + u * 8]);
        }
#pragma unroll
        for (int u = 0; u < 4; u++) {
            float wg = sn[u] * rg[pk[u] & 127];
            float4 v = *(float4*)&st[(pk[u] & 127) * 132 + lane * 4];
            float* yp = y + (size_t)(pk[u] >> 8) * DD + lane * 4;
            asm volatile("red.global.add.v4.f32 [%0], {%1,%2,%3,%4};"
                         :: "l"(yp), "f"(v.x * wg), "f"(v.y * wg),
                            "f"(v.z * wg), "f"(v.w * wg)
                         : "memory");
        }
    }
    for (; i < eend; i += 8) {
        int pk = __ldg(&g_spack[i]);
        float wg = __ldg(&g_snorm[i]) * rg[pk & 127];
        float4 v = *(float4*)&st[(pk & 127) * 132 + lane * 4];
        float* yp = y + (size_t)(pk >> 8) * DD + lane * 4;
        asm volatile("red.global.add.v4.f32 [%0], {%1,%2,%3,%4};"
                     :: "l"(yp), "f"(v.x * wg), "f"(v.y * wg),
                        "f"(v.z * wg), "f"(v.w * wg)
                     : "memory");
    }
}

// ---------------------------------------------------------------------------
extern "C" void kernel_launch(void* const* d_in, const int* in_sizes, int n_in,
                              void* d_out, int out_size) {
    const float* h    = (const float*)d_in[0];
    const float* norm = (const float*)d_in[1];
    const float* w0   = (const float*)d_in[2];
    const float* b0   = (const float*)d_in[3];
    const float* lw0  = (const float*)d_in[4];
    const float* gw0  = (const float*)d_in[5];
    const float* w1   = (const float*)d_in[6];
    const float* b1   = (const float*)d_in[7];
    const float* lw1  = (const float*)d_in[8];
    const float* gw1  = (const float*)d_in[9];
    const int*   src  = (const int*)d_in[10];
    const int*   dst  = (const int*)d_in[11];
    const int*   rel  = (const int*)d_in[12];
    float* out = (float*)d_out;

    cudaFuncSetAttribute(gemm_all_kernel,
                         cudaFuncAttributeMaxDynamicSharedMemorySize, GEMM_SMEM);

    float* h1 = nullptr;
    cudaGetSymbolAddress((void**)&h1, g_h1);
    int* scanp = nullptr;
    cudaGetSymbolAddress((void**)&scanp, g_scan);
    int* flagp = nullptr;
    cudaGetSymbolAddress((void**)&flagp, g_flag);
    int* ecntp = nullptr;
    cudaGetSymbolAddress((void**)&ecntp, g_ecnt);
    int* erowp = nullptr;
    cudaGetSymbolAddress((void**)&erowp, g_erow);

    const int NBF = (NFLAG + 1023) / 1024;           // 782
    const int NBE = (NPADMAX + 1023) / 1024;         // 783
    const int all_grid = NBLK + NPADMAX / 128;       // 6647 worst case
    const int gatex_grid = NP / 8;                   // 6256 (covers padding)
    const int wcvt_grid = (NR + 1) * 128 * 32 / 256; // 272 (exact)

    // ---- Compaction + CSR prep (shared by both layers)
    zero_kernel<<<NPADMAX / 256, 256>>>();
    mark_kernel<<<NE / 256, 256>>>(src, rel);
    scan1_kernel<<<NBF, 256>>>(flagp, scanp, NFLAG);
    scan2_kernel<<<1, 1024>>>(NBF);
    scan3_kernel<<<(NFLAG + 255) / 256, 256>>>(scanp, NFLAG, -1);
    meta_kernel<<<1, 32>>>();
    buildcidx_kernel<<<NE / 256, 256>>>(src, rel);
    scan1_kernel<<<NBE, 256>>>(ecntp, erowp, NPADMAX);
    scan2_kernel<<<1, 1024>>>(NBE);
    scan3_kernel<<<(NPADMAX + 255) / 256, 256>>>(erowp, NPADMAX, NE);
    scatter_kernel<<<NE / 256, 256>>>(dst, norm);

    // ---- Layer 0
    cudaMemsetAsync(h1, 0, (size_t)NN * DD * sizeof(float));
    gatex_kernel<<<gatex_grid, 128>>>(h, gw0, 0);
    wcvt_kernel<<<wcvt_grid, 256>>>(w0, lw0);
    gemm_all_kernel<<<all_grid, 256, GEMM_SMEM>>>(b0, h1);

    // ---- Layer 1 (relu fused into gatex)
    cudaMemsetAsync(out, 0, (size_t)NN * DD * sizeof(float));
    gatex_kernel<<<gatex_grid, 128>>>(h1, gw1, 1);
    wcvt_kernel<<<wcvt_grid, 256>>>(w1, lw1);
    gemm_all_kernel<<<all_grid, 256, GEMM_SMEM>>>(b1, out);
}